// round 2
// baseline (speedup 1.0000x reference)
#include <cuda_runtime.h>

#define VOX (48*48*48)
typedef unsigned long long u64;

// Intermediate h = silu(conv1(features)): [voxel][64]
__device__ float g_h[VOX * 64];

__device__ __forceinline__ void fma2(u64& acc, u64 a, u64 b) {
    asm("fma.rn.f32x2 %0, %1, %2, %0;" : "+l"(acc) : "l"(a), "l"(b));
}

// ---------------------------------------------------------------------------
// Kernel 1: h = silu(conv3x3x3(features, w1, b1)), replicate pad, f32x2 FMA.
// grid (24,48): block covers rows (h0, h0+1) at depth d. 256 threads:
//   op = tid&31 (output channel pair 2op,2op+1), wg = (tid>>5)&3 (12 voxels),
//   hr = tid>>7 (which of the 2 h rows).
// smem per 4-ci chunk:
//   sWp [4ci][9r][3kw][64o]        : weight, o-pairs adjacent (LDS.64)
//   sFd [4ci][3kd][4hh][52 dup f2] : features duplicated {f,f} (LDS.64 bcast)
// ---------------------------------------------------------------------------
extern "C" __global__ void __launch_bounds__(256, 3) k_conv1(
    const float* __restrict__ feat, const float* __restrict__ w1,
    const float* __restrict__ b1)
{
    extern __shared__ float sm1[];
    float* sWp = sm1;           // 6912 floats
    float* sFd = sm1 + 6912;    // 4992 floats

    const int tid = threadIdx.x;
    const int op = tid & 31;
    const int wg = (tid >> 5) & 3;
    const int hr = tid >> 7;
    const int w0 = wg * 12;
    const int h0 = blockIdx.x * 2;
    const int d  = blockIdx.y;
    const int h  = h0 + hr;

    u64 acc[12];
    {
        u64 bias = *(const u64*)&b1[2 * op];
#pragma unroll
        for (int j = 0; j < 12; j++) acc[j] = bias;
    }

#pragma unroll 1
    for (int ci0 = 0; ci0 < 32; ci0 += 4) {
        // stage weights: layout ((ci*9+r)*3+kw)*64 + o ; src w1[o][ci][tap]
        for (int t = tid; t < 6912; t += 256) {
            int o = t & 63, q = t >> 6;
            int kw = q % 3, r = (q / 3) % 9, ci = q / 27;
            sWp[t] = w1[(o * 32 + ci0 + ci) * 27 + r * 3 + kw];
        }
        // stage features duplicated: ((ci*3+kd)*4+hh) row of 52 f32x2 pairs,
        // pair i holds value at w = i-1 (clamped)
        for (int t = tid; t < 2496; t += 256) {
            int i = t % 52, rr = t / 52;
            int hh = rr & 3, kd = (rr >> 2) % 3, ci = rr / 12;
            float v = 0.0f;
            if (i < 50) {
                int zw = min(max(i - 1, 0), 47);
                int zz = min(max(d - 1 + kd, 0), 47);
                int yy = min(max(h0 - 1 + hh, 0), 47);
                v = feat[(ci0 + ci) * VOX + (zz * 48 + yy) * 48 + zw];
            }
            ((float2*)sFd)[rr * 52 + i] = make_float2(v, v);
        }
        __syncthreads();

#pragma unroll 1
        for (int ci = 0; ci < 4; ci++) {
#pragma unroll
            for (int kd = 0; kd < 3; kd++) {
#pragma unroll
                for (int kh = 0; kh < 3; kh++) {
                    const u64* Dp = (const u64*)&sFd[((ci * 3 + kd) * 4 + hr + kh) * 104] + w0;
                    u64 Dv[14];
#pragma unroll
                    for (int t = 0; t < 14; t++) Dv[t] = Dp[t];
                    const float* Wb = &sWp[((ci * 9 + kd * 3 + kh) * 3) * 64 + 2 * op];
#pragma unroll
                    for (int kw = 0; kw < 3; kw++) {
                        u64 wv = *(const u64*)(Wb + kw * 64);
#pragma unroll
                        for (int j = 0; j < 12; j++)
                            fma2(acc[j], wv, Dv[j + kw]);
                    }
                }
            }
        }
        __syncthreads();
    }

    // SiLU + store pairs: g_h[voxel][2op..2op+1]
    long base = ((long)((d * 48 + h) * 48 + w0)) * 64 + 2 * op;
#pragma unroll
    for (int j = 0; j < 12; j++) {
        float2 v = *(float2*)&acc[j];
        v.x = v.x / (1.0f + __expf(-v.x));
        v.y = v.y / (1.0f + __expf(-v.y));
        *(float2*)&g_h[base + (long)j * 64] = v;
    }
}

// ---------------------------------------------------------------------------
// Kernel 2 (per (d,h) row of 48 voxels):
//   A: m = w2 @ h + b2 (f32x2 GEMM, 6v x 8mc tiles)  -> sMraw
//   B: softmax per 27-group -> sMd duplicated/transposed [v][n][g]{m,m}
//   C: apply to x taps staged channel-transposed in sX
// smem (190 KB, disjoint regions; sHd/sW2 alias sMd which is written later):
//   sMd  [0,20928)   : v*436 + n*16 + 2g
//   sMr  [20928,..)  : v*218 + mc            (10464)
//   sX   [31392,..)  : (rr*50+wp)*36 + c     (16200)   rr=dz*3+dy, wp<->w=wp-1
// ---------------------------------------------------------------------------
extern "C" __global__ void __launch_bounds__(256, 1) k_mask_apply(
    const float* __restrict__ x, const float* __restrict__ w2,
    const float* __restrict__ b2, float* __restrict__ out)
{
    extern __shared__ float sm2[];
    float* sMd = sm2;           // 20928
    float* sMr = sm2 + 20928;   // 10464
    float* sX  = sm2 + 31392;   // 16200
    float* sHd = sm2;           // alias: 6336  (v*132 + 2k, dup h)
    float* sW2 = sm2 + 6336;    // alias: 13824 (k*216 + mc)

    const int tid = threadIdx.x;
    const int hB = blockIdx.x, d = blockIdx.y;

    // ---- stage sHd (dup), sW2 (transposed), sX (channel-transposed) ----
    {
        long rowb = (long)((d * 48 + hB) * 48) * 64;
        for (int t = tid; t < 3072; t += 256) {
            int k = t & 63, v = t >> 6;
            float hv = g_h[rowb + t];
            ((float2*)sHd)[v * 66 + k] = make_float2(hv, hv);
        }
        for (int t = tid; t < 13824; t += 256) {
            int mc = t >> 6, k = t & 63;
            sW2[k * 216 + mc] = w2[t];
        }
        for (int t = tid; t < 14400; t += 256) {
            int wp = t % 50, q = t / 50;
            int c = q & 31, rr = q >> 5;
            int zz = min(max(d - 1 + rr / 3, 0), 47);
            int yy = min(max(hB - 1 + rr % 3, 0), 47);
            int zw = min(max(wp - 1, 0), 47);
            sX[(rr * 50 + wp) * 36 + c] = x[(long)c * VOX + (zz * 48 + yy) * 48 + zw];
        }
    }
    __syncthreads();

    // ---- A: 1x1 conv GEMM, f32x2 over mc pairs ----
    if (tid < 216) {
        const int v0 = (tid & 7) * 6;
        const int mc0 = (tid >> 3) * 8;
        u64 acc[6][4];
        {
            u64 bb[4];
#pragma unroll
            for (int jp = 0; jp < 4; jp++) bb[jp] = *(const u64*)&b2[mc0 + 2 * jp];
#pragma unroll
            for (int i = 0; i < 6; i++)
#pragma unroll
                for (int jp = 0; jp < 4; jp++) acc[i][jp] = bb[jp];
        }
#pragma unroll 4
        for (int k = 0; k < 64; k++) {
            u64 hd[6];
#pragma unroll
            for (int i = 0; i < 6; i++)
                hd[i] = *(const u64*)&sHd[(v0 + i) * 132 + 2 * k];
            const float* wb = &sW2[k * 216 + mc0];
            ulonglong2 wA = *(const ulonglong2*)wb;
            ulonglong2 wB = *(const ulonglong2*)(wb + 4);
            u64 wv[4] = {wA.x, wA.y, wB.x, wB.y};
#pragma unroll
            for (int i = 0; i < 6; i++)
#pragma unroll
                for (int jp = 0; jp < 4; jp++)
                    fma2(acc[i][jp], hd[i], wv[jp]);
        }
#pragma unroll
        for (int i = 0; i < 6; i++)
#pragma unroll
            for (int jp = 0; jp < 4; jp++)
                *(float2*)&sMr[(v0 + i) * 218 + mc0 + 2 * jp] = *(float2*)&acc[i][jp];
    }
    __syncthreads();

    // ---- B: softmax over each 27-group, write duplicated/transposed ----
    for (int s = tid; s < 384; s += 256) {
        int v = s >> 3, g = s & 7;
        const float* p = &sMr[v * 218 + g * 27];
        float mx = p[0];
#pragma unroll
        for (int n = 1; n < 27; n++) mx = fmaxf(mx, p[n]);
        float e[27], ssum = 0.0f;
#pragma unroll
        for (int n = 0; n < 27; n++) { e[n] = __expf(p[n] - mx); ssum += e[n]; }
        float inv = 1.0f / ssum;
        float* q = &sMd[v * 436 + 2 * g];
#pragma unroll
        for (int n = 0; n < 27; n++) {
            float m = e[n] * inv;
            *(float2*)&q[n * 16] = make_float2(m, m);
        }
    }
    __syncthreads();

    // ---- C: apply. slot = (v, channel group of 4). f32x2 over channel pairs.
    for (int p = tid; p < 384; p += 256) {
        int v = p % 48, cg = p / 48;
        int c0 = cg * 4;
        u64 acc[8][2];
#pragma unroll
        for (int g = 0; g < 8; g++) { acc[g][0] = 0ull; acc[g][1] = 0ull; }
        const float* mB = &sMd[v * 436];

#pragma unroll
        for (int rr = 0; rr < 9; rr++) {
#pragma unroll
            for (int dx = 0; dx < 3; dx++) {
                int n = rr * 3 + dx;
                ulonglong2 T = *(const ulonglong2*)&sX[(rr * 50 + v + dx) * 36 + c0];
                ulonglong2 M0 = *(const ulonglong2*)&mB[n * 16];
                ulonglong2 M1 = *(const ulonglong2*)&mB[n * 16 + 4];
                ulonglong2 M2 = *(const ulonglong2*)&mB[n * 16 + 8];
                ulonglong2 M3 = *(const ulonglong2*)&mB[n * 16 + 12];
                fma2(acc[0][0], M0.x, T.x); fma2(acc[0][1], M0.x, T.y);
                fma2(acc[1][0], M0.y, T.x); fma2(acc[1][1], M0.y, T.y);
                fma2(acc[2][0], M1.x, T.x); fma2(acc[2][1], M1.x, T.y);
                fma2(acc[3][0], M1.y, T.x); fma2(acc[3][1], M1.y, T.y);
                fma2(acc[4][0], M2.x, T.x); fma2(acc[4][1], M2.x, T.y);
                fma2(acc[5][0], M2.y, T.x); fma2(acc[5][1], M2.y, T.y);
                fma2(acc[6][0], M3.x, T.x); fma2(acc[6][1], M3.x, T.y);
                fma2(acc[7][0], M3.y, T.x); fma2(acc[7][1], M3.y, T.y);
            }
        }

        // out[c][2d+i][2h+j][2v+k]: k-pairs packed into float2 (coalesced over v)
#pragma unroll
        for (int i = 0; i < 2; i++)
#pragma unroll
            for (int j = 0; j < 2; j++) {
                int g0 = i * 4 + j * 2;
#pragma unroll
                for (int jp = 0; jp < 2; jp++) {
                    float2 a0 = *(float2*)&acc[g0][jp];       // k=0, ch (c0+2jp, +1)
                    float2 a1 = *(float2*)&acc[g0 + 1][jp];   // k=1
                    int c = c0 + 2 * jp;
                    long ob = (((long)c * 96 + 2 * d + i) * 96 + 2 * hB + j) * 96 + 2 * v;
                    *(float2*)&out[ob] = make_float2(a0.x, a1.x);
                    *(float2*)&out[ob + 884736] = make_float2(a0.y, a1.y);
                }
            }
    }
}

// ---------------------------------------------------------------------------
extern "C" void kernel_launch(void* const* d_in, const int* in_sizes, int n_in,
                              void* d_out, int out_size)
{
    const float* x    = (const float*)d_in[0];
    const float* feat = (const float*)d_in[1];
    const float* w1   = (const float*)d_in[2];
    const float* b1   = (const float*)d_in[3];
    const float* w2   = (const float*)d_in[4];
    const float* b2   = (const float*)d_in[5];
    float* out = (float*)d_out;

    const int smem1 = (6912 + 4992) * 4;                    // 47616 B
    const int smem2 = (20928 + 10464 + 16200) * 4;          // 190368 B
    cudaFuncSetAttribute(k_conv1, cudaFuncAttributeMaxDynamicSharedMemorySize, smem1);
    cudaFuncSetAttribute(k_mask_apply, cudaFuncAttributeMaxDynamicSharedMemorySize, smem2);

    k_conv1<<<dim3(24, 48), 256, smem1>>>(feat, w1, b1);
    k_mask_apply<<<dim3(48, 48), 256, smem2>>>(x, w2, b2, out);
}

// round 3
// speedup vs baseline: 1.7413x; 1.7413x over previous
#include <cuda_runtime.h>

#define VOX (48*48*48)
typedef unsigned long long u64;

// Device globals: intermediate h, pre-transposed weights.
__device__ float g_h[VOX * 64];        // [voxel][64]
__device__ float g_w1s[55296];         // [(ci*27+tap)*64 + o]
__device__ float g_w2t[13824];         // [k*216 + mc]

__device__ __forceinline__ void fma2(u64& acc, u64 a, u64 b) {
    asm("fma.rn.f32x2 %0, %1, %2, %0;" : "+l"(acc) : "l"(a), "l"(b));
}
__device__ __forceinline__ u64 dup2(float v) {
    u64 r; asm("mov.b64 %0, {%1, %1};" : "=l"(r) : "f"(v)); return r;
}

// ---------------------------------------------------------------------------
// Prep: transpose w1 -> g_w1s, w2 -> g_w2t (runs every launch, deterministic)
// ---------------------------------------------------------------------------
extern "C" __global__ void k_prep(const float* __restrict__ w1,
                                  const float* __restrict__ w2)
{
    int id = blockIdx.x * 256 + threadIdx.x;
    if (id < 13824) {
        int k = id / 216, mc = id % 216;
        g_w2t[id] = w2[mc * 64 + k];
    } else if (id < 13824 + 55296) {
        int q = id - 13824;
        int o = q & 63, r = q >> 6;
        int tap = r % 27, ci = r / 27;
        g_w1s[q] = w1[o * 864 + ci * 27 + tap];
    }
}

// ---------------------------------------------------------------------------
// Kernel 1: h = silu(conv3x3x3(features)), replicate pad, f32x2, 4ch x 12vox.
// grid (12,48): block = 4 h-rows at depth d. 256 threads:
//   op4 = tid&15 : channel pairs (2*op4, 2*op4+1) and (2*op4+32, 2*op4+33)
//   wg  = (tid>>4)&3 : 12-voxel w group
//   hr  = tid>>6 : h row within block
// smem per 4-ci chunk:
//   sWp [4ci][27tap][64o]          (contiguous copy of g_w1s slice)
//   sFd [4ci][3kd][6hh][52 dup f2] (features duplicated {f,f})
// ---------------------------------------------------------------------------
extern "C" __global__ void __launch_bounds__(256, 2) k_conv1(
    const float* __restrict__ feat, const float* __restrict__ b1)
{
    extern __shared__ float sm1[];
    float* sWp = sm1;           // 6912 floats
    float* sFd = sm1 + 6912;    // 7488 floats (3744 f32x2)

    const int tid = threadIdx.x;
    const int op4 = tid & 15;
    const int wg  = (tid >> 4) & 3;
    const int hr  = tid >> 6;
    const int w0  = wg * 12;
    const int h0  = blockIdx.x * 4;
    const int d   = blockIdx.y;
    const int h   = h0 + hr;

    u64 acc[2][12];
    {
        u64 bias0 = *(const u64*)&b1[2 * op4];
        u64 bias1 = *(const u64*)&b1[2 * op4 + 32];
#pragma unroll
        for (int j = 0; j < 12; j++) { acc[0][j] = bias0; acc[1][j] = bias1; }
    }

#pragma unroll 1
    for (int ci0 = 0; ci0 < 32; ci0 += 4) {
        // weights: contiguous float4 copy of g_w1s chunk
        {
            const float4* src = (const float4*)(g_w1s + ci0 * 1728);
            float4* dst = (float4*)sWp;
            for (int t = tid; t < 1728; t += 256) dst[t] = src[t];
        }
        // features duplicated: ((ci*3+kd)*6+hh) rows of 52 f32x2, entry i = w(i-1)
        for (int t = tid; t < 3744; t += 256) {
            int i  = t % 52, rr = t / 52;
            int hh = rr % 6, kd = (rr / 6) % 3, ci = rr / 18;
            float v = 0.0f;
            if (i < 50) {
                int zw = min(max(i - 1, 0), 47);
                int zz = min(max(d - 1 + kd, 0), 47);
                int yy = min(max(h0 - 1 + hh, 0), 47);
                v = feat[(ci0 + ci) * VOX + (zz * 48 + yy) * 48 + zw];
            }
            ((float2*)sFd)[t] = make_float2(v, v);
        }
        __syncthreads();

#pragma unroll 1
        for (int ci = 0; ci < 4; ci++) {
#pragma unroll
            for (int kd = 0; kd < 3; kd++) {
#pragma unroll
                for (int kh = 0; kh < 3; kh++) {
                    const u64* Dp = (const u64*)sFd + ((ci * 3 + kd) * 6 + hr + kh) * 52 + w0;
                    u64 Dv[14];
#pragma unroll
                    for (int t = 0; t < 14; t++) Dv[t] = Dp[t];
                    const float* Wb = &sWp[(ci * 27 + kd * 9 + kh * 3) * 64];
#pragma unroll
                    for (int kw = 0; kw < 3; kw++) {
                        u64 wv0 = *(const u64*)(Wb + kw * 64 + 2 * op4);
                        u64 wv1 = *(const u64*)(Wb + kw * 64 + 2 * op4 + 32);
#pragma unroll
                        for (int j = 0; j < 12; j++) {
                            fma2(acc[0][j], wv0, Dv[j + kw]);
                            fma2(acc[1][j], wv1, Dv[j + kw]);
                        }
                    }
                }
            }
        }
        __syncthreads();
    }

    // SiLU + store pairs
    long vb = (long)((d * 48 + h) * 48 + w0) * 64;
#pragma unroll
    for (int j = 0; j < 12; j++) {
#pragma unroll
        for (int half = 0; half < 2; half++) {
            float2 v = *(float2*)&acc[half][j];
            v.x = v.x / (1.0f + __expf(-v.x));
            v.y = v.y / (1.0f + __expf(-v.y));
            *(float2*)&g_h[vb + (long)j * 64 + 2 * op4 + half * 32] = v;
        }
    }
}

// ---------------------------------------------------------------------------
// Kernel 2 (per (d,h) row of 48 voxels):
//   A: masks = w2 @ h + b2 via f32x2 GEMM (w2t from global, dup-h in smem),
//      written directly TRANSPOSED: sMt[v*218 + n*8 + g]
//   B: softmax per (v,g) over n, in place
//   C: apply: f32x2 over g-pairs; acc pair {g,g+1} == output {k=0,k=1} float2
// smem: sMt 48*218 = 10464 ; sHd 48*130 = 6240  -> 66816 B
// ---------------------------------------------------------------------------
extern "C" __global__ void __launch_bounds__(256, 2) k_mask_apply(
    const float* __restrict__ x, const float* __restrict__ b2,
    float* __restrict__ out)
{
    extern __shared__ float sm2[];
    float* sMt = sm2;            // 10464
    float* sHd = sm2 + 10464;    // 6240 (v*130 + 2k, duplicated h)

    const int tid = threadIdx.x;
    const int hB = blockIdx.x, d = blockIdx.y;

    // stage dup h
    {
        long rowb = (long)((d * 48 + hB) * 48) * 64;
        for (int t = tid; t < 3072; t += 256) {
            int k = t & 63, v = t >> 6;
            float hv = g_h[rowb + t];
            *(float2*)&sHd[v * 130 + 2 * k] = make_float2(hv, hv);
        }
    }
    __syncthreads();

    // ---- A: 1x1 conv GEMM, 6v x 8mc tiles, f32x2 over mc pairs ----
    if (tid < 216) {
        const int v0  = (tid & 7) * 6;
        const int mc0 = (tid >> 3) * 8;
        u64 acc[6][4];
        {
            u64 bb[4];
#pragma unroll
            for (int jp = 0; jp < 4; jp++) bb[jp] = *(const u64*)&b2[mc0 + 2 * jp];
#pragma unroll
            for (int i = 0; i < 6; i++)
#pragma unroll
                for (int jp = 0; jp < 4; jp++) acc[i][jp] = bb[jp];
        }
#pragma unroll 4
        for (int k = 0; k < 64; k++) {
            u64 hd[6];
#pragma unroll
            for (int i = 0; i < 6; i++)
                hd[i] = *(const u64*)&sHd[(v0 + i) * 130 + 2 * k];
            const float* wr = g_w2t + k * 216 + mc0;
            float4 wA = *(const float4*)wr;
            float4 wB = *(const float4*)(wr + 4);
            u64 wv[4] = { *(u64*)&wA.x, *(u64*)&wA.z, *(u64*)&wB.x, *(u64*)&wB.z };
#pragma unroll
            for (int i = 0; i < 6; i++)
#pragma unroll
                for (int jp = 0; jp < 4; jp++)
                    fma2(acc[i][jp], hd[i], wv[jp]);
        }
        // scatter-store transposed: mc = g*27+n -> sMt[v*218 + n*8 + g]
#pragma unroll
        for (int i = 0; i < 6; i++) {
            float* row = &sMt[(v0 + i) * 218];
#pragma unroll
            for (int jp = 0; jp < 4; jp++) {
                float2 val = *(float2*)&acc[i][jp];
                int mcA = mc0 + 2 * jp, mcB = mcA + 1;
                row[(mcA % 27) * 8 + mcA / 27] = val.x;
                row[(mcB % 27) * 8 + mcB / 27] = val.y;
            }
        }
    }
    __syncthreads();

    // ---- B: softmax over n for each (v,g), strided 8, in place ----
    for (int s = tid; s < 384; s += 256) {
        int v = s >> 3, g = s & 7;
        float* p = &sMt[v * 218 + g];
        float mx = p[0];
#pragma unroll
        for (int n = 1; n < 27; n++) mx = fmaxf(mx, p[n * 8]);
        float e[27], ssum = 0.0f;
#pragma unroll
        for (int n = 0; n < 27; n++) { e[n] = __expf(p[n * 8] - mx); ssum += e[n]; }
        float inv = 1.0f / ssum;
#pragma unroll
        for (int n = 0; n < 27; n++) p[n * 8] = e[n] * inv;
    }
    __syncthreads();

    // ---- C: apply. slot = (v, cp) -> channels cp, cp+16. f32x2 over g-pairs.
    int zd[3], zh[3];
#pragma unroll
    for (int t = 0; t < 3; t++) {
        zd[t] = min(max(d + t - 1, 0), 47);
        zh[t] = min(max(hB + t - 1, 0), 47);
    }

    for (int p = tid; p < 768; p += 256) {
        int v = p % 48, cp = p / 48;
        int zw[3];
        zw[0] = max(v - 1, 0); zw[1] = v; zw[2] = min(v + 1, 47);

        float t0[27], t1[27];
#pragma unroll
        for (int dz = 0; dz < 3; dz++)
#pragma unroll
            for (int dy = 0; dy < 3; dy++)
#pragma unroll
                for (int dx = 0; dx < 3; dx++) {
                    long idx = ((long)zd[dz] * 48 + zh[dy]) * 48 + zw[dx];
                    int n = dz * 9 + dy * 3 + dx;
                    t0[n] = x[(long)cp * VOX + idx];
                    t1[n] = x[(long)(cp + 16) * VOX + idx];
                }

        u64 a0[4], a1[4];   // pairs {g0,g1},{g2,g3},{g4,g5},{g6,g7}
#pragma unroll
        for (int q = 0; q < 4; q++) { a0[q] = 0ull; a1[q] = 0ull; }
        const float* mB = &sMt[v * 218];

#pragma unroll
        for (int n = 0; n < 27; n++) {
            const u64* mp = (const u64*)(mB + n * 8);
            u64 m01 = mp[0], m23 = mp[1], m45 = mp[2], m67 = mp[3];
            u64 T0 = dup2(t0[n]);
            u64 T1 = dup2(t1[n]);
            fma2(a0[0], m01, T0); fma2(a1[0], m01, T1);
            fma2(a0[1], m23, T0); fma2(a1[1], m23, T1);
            fma2(a0[2], m45, T0); fma2(a1[2], m45, T1);
            fma2(a0[3], m67, T0); fma2(a1[3], m67, T1);
        }

        // acc pair {g0=i*4+j*2, g0+1} = {k=0, k=1} -> direct float2 store
#pragma unroll
        for (int i = 0; i < 2; i++)
#pragma unroll
            for (int j = 0; j < 2; j++) {
                int q = i * 2 + j;
                long ob0 = (((long)cp * 96 + 2 * d + i) * 96 + 2 * hB + j) * 96 + 2 * v;
                long ob1 = (((long)(cp + 16) * 96 + 2 * d + i) * 96 + 2 * hB + j) * 96 + 2 * v;
                *(float2*)&out[ob0] = *(float2*)&a0[q];
                *(float2*)&out[ob1] = *(float2*)&a1[q];
            }
    }
}

// ---------------------------------------------------------------------------
extern "C" void kernel_launch(void* const* d_in, const int* in_sizes, int n_in,
                              void* d_out, int out_size)
{
    const float* x    = (const float*)d_in[0];
    const float* feat = (const float*)d_in[1];
    const float* w1   = (const float*)d_in[2];
    const float* b1   = (const float*)d_in[3];
    const float* w2   = (const float*)d_in[4];
    const float* b2   = (const float*)d_in[5];
    float* out = (float*)d_out;

    const int smem1 = (6912 + 7488) * 4;     // 57600 B
    const int smem2 = (10464 + 6240) * 4;    // 66816 B
    cudaFuncSetAttribute(k_conv1, cudaFuncAttributeMaxDynamicSharedMemorySize, smem1);
    cudaFuncSetAttribute(k_mask_apply, cudaFuncAttributeMaxDynamicSharedMemorySize, smem2);

    k_prep<<<270, 256>>>(w1, w2);
    k_conv1<<<dim3(12, 48), 256, smem1>>>(feat, b1);
    k_mask_apply<<<dim3(48, 48), 256, smem2>>>(x, b2, out);
}

// round 4
// speedup vs baseline: 1.8615x; 1.0690x over previous
#include <cuda_runtime.h>

#define VOX (48*48*48)
typedef unsigned long long u64;

// Device globals: intermediate h, pre-transposed weights.
__device__ float g_h[VOX * 64];        // [voxel][64]
__device__ float g_w1s[55296];         // [(ci*27+tap)*64 + o]
__device__ float g_w2t[13824];         // [k*216 + mc]

__device__ __forceinline__ void fma2(u64& acc, u64 a, u64 b) {
    asm("fma.rn.f32x2 %0, %1, %2, %0;" : "+l"(acc) : "l"(a), "l"(b));
}
__device__ __forceinline__ u64 dup2(float v) {
    u64 r; asm("mov.b64 %0, {%1, %1};" : "=l"(r) : "f"(v)); return r;
}

// ---------------------------------------------------------------------------
// Prep: transpose w1 -> g_w1s, w2 -> g_w2t
// ---------------------------------------------------------------------------
extern "C" __global__ void k_prep(const float* __restrict__ w1,
                                  const float* __restrict__ w2)
{
    int id = blockIdx.x * 256 + threadIdx.x;
    if (id < 13824) {
        int k = id / 216, mc = id % 216;
        g_w2t[id] = w2[mc * 64 + k];
    } else if (id < 13824 + 55296) {
        int q = id - 13824;
        int o = q & 63, r = q >> 6;
        int tap = r % 27, ci = r / 27;
        g_w1s[q] = w1[o * 864 + ci * 27 + tap];
    }
}

// ---------------------------------------------------------------------------
// Kernel 1: h = silu(conv3x3x3(features)), replicate pad, f32x2.
// grid (12,48): block = 4 h-rows at depth d. 256 thr = op4(16) x wg(4) x hr(4).
// Double-buffered 2-ci chunks:
//   buf = [ sW 2ci*27*64 = 3456 | sF 2ci*3kd*6hh*52 = 1872 ]  (5328 floats)
// Features stored scalar; duplicated to f32x2 at use via ALU mov.
// ---------------------------------------------------------------------------
extern "C" __global__ void __launch_bounds__(256, 2) k_conv1(
    const float* __restrict__ feat, const float* __restrict__ b1)
{
    extern __shared__ float sm1[];   // 2 buffers of 5328 floats

    const int tid = threadIdx.x;
    const int op4 = tid & 15;
    const int wg  = (tid >> 4) & 3;
    const int hr  = tid >> 6;
    const int w0  = wg * 12;
    const int h0  = blockIdx.x * 4;
    const int d   = blockIdx.y;
    const int h   = h0 + hr;

    u64 acc[2][12];
    {
        u64 bias0 = *(const u64*)&b1[2 * op4];
        u64 bias1 = *(const u64*)&b1[2 * op4 + 32];
#pragma unroll
        for (int j = 0; j < 12; j++) { acc[0][j] = bias0; acc[1][j] = bias1; }
    }

    // ---- staging helper (chunk c -> buffer buf) ----
    auto stage = [&](float* buf, int c) {
        // weights: contiguous float4 copy
        const float4* wsrc = (const float4*)(g_w1s + c * 3456);
        float4* wdst = (float4*)buf;
        for (int t = tid; t < 864; t += 256) wdst[t] = wsrc[t];
        // features scalar: row rr = (ci*3+kd)*6+hh, entry i -> w = i-1 clamped
        float* fdst = buf + 3456;
        for (int t = tid; t < 1872; t += 256) {
            int i  = t % 52, rr = t / 52;
            int hh = rr % 6, kd = (rr / 6) % 3, ci = rr / 18;
            float v = 0.0f;
            if (i < 50) {
                int zw = min(max(i - 1, 0), 47);
                int zz = min(max(d - 1 + kd, 0), 47);
                int yy = min(max(h0 - 1 + hh, 0), 47);
                v = feat[(2 * c + ci) * VOX + (zz * 48 + yy) * 48 + zw];
            }
            fdst[t] = v;
        }
    };

    stage(sm1, 0);
    __syncthreads();

#pragma unroll 1
    for (int c = 0; c < 16; c++) {
        float* cur = sm1 + (c & 1) * 5328;
        if (c + 1 < 16) stage(sm1 + ((c + 1) & 1) * 5328, c + 1);

        const float* sW = cur;
        const float* sF = cur + 3456;
#pragma unroll 1
        for (int ci = 0; ci < 2; ci++) {
#pragma unroll
            for (int kd = 0; kd < 3; kd++) {
#pragma unroll
                for (int kh = 0; kh < 3; kh++) {
                    const float* fp = &sF[((ci * 3 + kd) * 6 + hr + kh) * 52 + w0];
                    float fs[14];
                    *(float4*)&fs[0]  = *(const float4*)fp;
                    *(float4*)&fs[4]  = *(const float4*)(fp + 4);
                    *(float4*)&fs[8]  = *(const float4*)(fp + 8);
                    *(float2*)&fs[12] = *(const float2*)(fp + 12);
                    u64 Dv[14];
#pragma unroll
                    for (int t = 0; t < 14; t++) Dv[t] = dup2(fs[t]);
                    const float* Wb = &sW[(ci * 27 + kd * 9 + kh * 3) * 64 + 2 * op4];
#pragma unroll
                    for (int kw = 0; kw < 3; kw++) {
                        u64 wv0 = *(const u64*)(Wb + kw * 64);
                        u64 wv1 = *(const u64*)(Wb + kw * 64 + 32);
#pragma unroll
                        for (int j = 0; j < 12; j++) {
                            fma2(acc[0][j], wv0, Dv[j + kw]);
                            fma2(acc[1][j], wv1, Dv[j + kw]);
                        }
                    }
                }
            }
        }
        __syncthreads();
    }

    // SiLU + store pairs
    long vb = (long)((d * 48 + h) * 48 + w0) * 64;
#pragma unroll
    for (int j = 0; j < 12; j++) {
#pragma unroll
        for (int half = 0; half < 2; half++) {
            float2 v = *(float2*)&acc[half][j];
            v.x = v.x / (1.0f + __expf(-v.x));
            v.y = v.y / (1.0f + __expf(-v.y));
            *(float2*)&g_h[vb + (long)j * 64 + 2 * op4 + half * 32] = v;
        }
    }
}

// ---------------------------------------------------------------------------
// Kernel 2 (per (d,h) row of 48 voxels), 3 CTA/SM target:
//   A: masks = w2 @ h + b2 (f32x2 GEMM, w2t streamed from global)
//      -> sMt[v*218 + n*8 + g] (transposed)
//   B: softmax per (v,g) over n, in place
//   C: apply, register-lean (immediate accumulate per tap)
// smem: sMt 10464 + sHd 6240 = 66816 B
// ---------------------------------------------------------------------------
extern "C" __global__ void __launch_bounds__(256, 3) k_mask_apply(
    const float* __restrict__ x, const float* __restrict__ b2,
    float* __restrict__ out)
{
    extern __shared__ float sm2[];
    float* sMt = sm2;            // 10464
    float* sHd = sm2 + 10464;    // 6240 (v*130 + 2k, duplicated h)

    const int tid = threadIdx.x;
    const int hB = blockIdx.x, d = blockIdx.y;

    // stage dup h
    {
        long rowb = (long)((d * 48 + hB) * 48) * 64;
        for (int t = tid; t < 3072; t += 256) {
            int k = t & 63, v = t >> 6;
            float hv = g_h[rowb + t];
            *(float2*)&sHd[v * 130 + 2 * k] = make_float2(hv, hv);
        }
    }
    __syncthreads();

    // ---- A: 1x1 conv GEMM, 6v x 8mc tiles, f32x2 over mc pairs ----
    if (tid < 216) {
        const int v0  = (tid & 7) * 6;
        const int mc0 = (tid >> 3) * 8;
        u64 acc[6][4];
        {
            u64 bb[4];
#pragma unroll
            for (int jp = 0; jp < 4; jp++) bb[jp] = *(const u64*)&b2[mc0 + 2 * jp];
#pragma unroll
            for (int i = 0; i < 6; i++)
#pragma unroll
                for (int jp = 0; jp < 4; jp++) acc[i][jp] = bb[jp];
        }
#pragma unroll 4
        for (int k = 0; k < 64; k++) {
            u64 hd[6];
#pragma unroll
            for (int i = 0; i < 6; i++)
                hd[i] = *(const u64*)&sHd[(v0 + i) * 130 + 2 * k];
            const float* wr = g_w2t + k * 216 + mc0;
            float4 wA = *(const float4*)wr;
            float4 wB = *(const float4*)(wr + 4);
            u64 wv[4] = { *(u64*)&wA.x, *(u64*)&wA.z, *(u64*)&wB.x, *(u64*)&wB.z };
#pragma unroll
            for (int i = 0; i < 6; i++)
#pragma unroll
                for (int jp = 0; jp < 4; jp++)
                    fma2(acc[i][jp], hd[i], wv[jp]);
        }
        // scatter-store transposed: mc = g*27+n -> sMt[v*218 + n*8 + g]
#pragma unroll
        for (int i = 0; i < 6; i++) {
            float* row = &sMt[(v0 + i) * 218];
#pragma unroll
            for (int jp = 0; jp < 4; jp++) {
                float2 val = *(float2*)&acc[i][jp];
                int mcA = mc0 + 2 * jp, mcB = mcA + 1;
                row[(mcA % 27) * 8 + mcA / 27] = val.x;
                row[(mcB % 27) * 8 + mcB / 27] = val.y;
            }
        }
    }
    __syncthreads();

    // ---- B: softmax over n for each (v,g) ----
    for (int s = tid; s < 384; s += 256) {
        int v = s >> 3, g = s & 7;
        float* p = &sMt[v * 218 + g];
        float mx = p[0];
#pragma unroll
        for (int n = 1; n < 27; n++) mx = fmaxf(mx, p[n * 8]);
        float e[27], ssum = 0.0f;
#pragma unroll
        for (int n = 0; n < 27; n++) { e[n] = __expf(p[n * 8] - mx); ssum += e[n]; }
        float inv = 1.0f / ssum;
#pragma unroll
        for (int n = 0; n < 27; n++) p[n * 8] = e[n] * inv;
    }
    __syncthreads();

    // ---- C: apply, immediate accumulate (low regs). slot = (v, cp). ----
    int zd[3], zh[3];
#pragma unroll
    for (int t = 0; t < 3; t++) {
        zd[t] = min(max(d + t - 1, 0), 47);
        zh[t] = min(max(hB + t - 1, 0), 47);
    }

#pragma unroll 1
    for (int p = tid; p < 768; p += 256) {
        int v = p % 48, cp = p / 48;
        int zw[3];
        zw[0] = max(v - 1, 0); zw[1] = v; zw[2] = min(v + 1, 47);
        const float* x0 = x + (long)cp * VOX;
        const float* x1 = x + (long)(cp + 16) * VOX;
        const float* mB = &sMt[v * 218];

        u64 a0[4], a1[4];   // pairs {g0,g1},{g2,g3},{g4,g5},{g6,g7}
#pragma unroll
        for (int q = 0; q < 4; q++) { a0[q] = 0ull; a1[q] = 0ull; }

#pragma unroll
        for (int dz = 0; dz < 3; dz++) {
#pragma unroll
            for (int dy = 0; dy < 3; dy++) {
                long rbase = ((long)zd[dz] * 48 + zh[dy]) * 48;
                float t0[3], t1[3];
#pragma unroll
                for (int dx = 0; dx < 3; dx++) {
                    t0[dx] = x0[rbase + zw[dx]];
                    t1[dx] = x1[rbase + zw[dx]];
                }
#pragma unroll
                for (int dx = 0; dx < 3; dx++) {
                    int n = (dz * 3 + dy) * 3 + dx;
                    const u64* mp = (const u64*)(mB + n * 8);
                    u64 T0 = dup2(t0[dx]);
                    u64 T1 = dup2(t1[dx]);
                    fma2(a0[0], mp[0], T0); fma2(a1[0], mp[0], T1);
                    fma2(a0[1], mp[1], T0); fma2(a1[1], mp[1], T1);
                    fma2(a0[2], mp[2], T0); fma2(a1[2], mp[2], T1);
                    fma2(a0[3], mp[3], T0); fma2(a1[3], mp[3], T1);
                }
            }
        }

        // acc pair {g0=i*4+j*2, g0+1} = {k=0, k=1} -> direct float2 store
#pragma unroll
        for (int i = 0; i < 2; i++)
#pragma unroll
            for (int j = 0; j < 2; j++) {
                int q = i * 2 + j;
                long ob0 = (((long)cp * 96 + 2 * d + i) * 96 + 2 * hB + j) * 96 + 2 * v;
                long ob1 = (((long)(cp + 16) * 96 + 2 * d + i) * 96 + 2 * hB + j) * 96 + 2 * v;
                *(float2*)&out[ob0] = *(float2*)&a0[q];
                *(float2*)&out[ob1] = *(float2*)&a1[q];
            }
    }
}

// ---------------------------------------------------------------------------
extern "C" void kernel_launch(void* const* d_in, const int* in_sizes, int n_in,
                              void* d_out, int out_size)
{
    const float* x    = (const float*)d_in[0];
    const float* feat = (const float*)d_in[1];
    const float* w1   = (const float*)d_in[2];
    const float* b1   = (const float*)d_in[3];
    const float* w2   = (const float*)d_in[4];
    const float* b2   = (const float*)d_in[5];
    float* out = (float*)d_out;

    const int smem1 = 2 * 5328 * 4;          // 42624 B
    const int smem2 = (10464 + 6240) * 4;    // 66816 B
    cudaFuncSetAttribute(k_conv1, cudaFuncAttributeMaxDynamicSharedMemorySize, smem1);
    cudaFuncSetAttribute(k_mask_apply, cudaFuncAttributeMaxDynamicSharedMemorySize, smem2);

    k_prep<<<270, 256>>>(w1, w2);
    k_conv1<<<dim3(12, 48), 256, smem1>>>(feat, b1);
    k_mask_apply<<<dim3(48, 48), 256, smem2>>>(x, b2, out);
}

// round 6
// speedup vs baseline: 2.4097x; 1.2945x over previous
#include <cuda_runtime.h>
#include <cuda_bf16.h>
#include <cstdint>

#define VOX (48*48*48)
typedef unsigned long long u64;
typedef unsigned int u32;

// Device globals
__device__ float g_h[VOX * 64];                   // [voxel][64] conv1 output
__device__ __nv_bfloat16 g_w1a[3 * 9 * 64 * 72];  // [dz][tap9][oc64][72]: row 144B = [hi ci0-31 | lo ci0-31 | pad]
__device__ float g_w2t[13824];                    // [k*216 + mc]

__device__ __forceinline__ void fma2(u64& acc, u64 a, u64 b) {
    asm("fma.rn.f32x2 %0, %1, %2, %0;" : "+l"(acc) : "l"(a), "l"(b));
}
__device__ __forceinline__ u64 dup2(float v) {
    u64 r; asm("mov.b64 %0, {%1, %1};" : "=l"(r) : "f"(v)); return r;
}

__device__ __forceinline__ void ldsm4(u32& r0, u32& r1, u32& r2, u32& r3, u32 a) {
    asm volatile("ldmatrix.sync.aligned.m8n8.x4.shared.b16 {%0,%1,%2,%3}, [%4];"
                 : "=r"(r0), "=r"(r1), "=r"(r2), "=r"(r3) : "r"(a));
}
__device__ __forceinline__ void mmabf(float* d, const u32* a, const u32* b) {
    asm volatile(
        "mma.sync.aligned.m16n8k16.row.col.f32.bf16.bf16.f32 "
        "{%0,%1,%2,%3}, {%4,%5,%6,%7}, {%8,%9}, {%0,%1,%2,%3};"
        : "+f"(d[0]), "+f"(d[1]), "+f"(d[2]), "+f"(d[3])
        : "r"(a[0]), "r"(a[1]), "r"(a[2]), "r"(a[3]), "r"(b[0]), "r"(b[1]));
}

// ---------------------------------------------------------------------------
// Prep: split w1 into bf16 hi/lo in MMA-A layout; transpose w2.
// ---------------------------------------------------------------------------
extern "C" __global__ void k_prep(const float* __restrict__ w1,
                                  const float* __restrict__ w2)
{
    int id = blockIdx.x * 256 + threadIdx.x;
    if (id < 13824) {
        int k = id / 216, mc = id % 216;
        g_w2t[id] = w2[mc * 64 + k];
    } else if (id < 13824 + 55296) {
        int q = id - 13824;
        int ci = q & 31;
        int r  = q >> 5;
        int oc = r & 63;
        int r2 = r >> 6;          // dz*9 + tap
        int tap = r2 % 9, dz = r2 / 9;
        float v = w1[oc * 864 + ci * 27 + dz * 9 + tap];
        __nv_bfloat16 hi = __float2bfloat16(v);
        __nv_bfloat16 lo = __float2bfloat16(v - __bfloat162float(hi));
        int base = ((dz * 9 + tap) * 64 + oc) * 72;
        g_w1a[base + ci]      = hi;
        g_w1a[base + 32 + ci] = lo;
    }
}

// ---------------------------------------------------------------------------
// Kernel 1: h = silu(conv3x3x3(features)) via mma.sync bf16 hi/lo split.
// grid (12, 48): block = (4 h-rows, depth d), 256 threads = 8 warps.
// Warp grid: mw = warp&1 (oc 0-31 / 32-63), nw = warp>>1 (h row h0+nw, 48 w).
// smem: sF 900 rows x 144B  ([dz3][hh6][wp50], row = [F_hi ci0-31|F_lo|pad])
//       sA 576 rows x 144B  (current dz: [tap9][oc64], row = [W_hi|W_lo|pad])
// B tiles ([n][k] smem = col-major B) -> NON-trans ldmatrix.
// K passes per tap: (A_hi,B_hi), (A_lo,B_hi), (A_hi,B_lo); fp32 accumulate.
// ---------------------------------------------------------------------------
extern "C" __global__ void __launch_bounds__(256, 1) k_conv1(
    const float* __restrict__ feat, const float* __restrict__ b1)
{
    extern __shared__ char sm[];
    char* sF = sm;                    // 129600 B
    char* sA = sm + 900 * 144;        // 82944 B
    const u32 sFb = (u32)__cvta_generic_to_shared(sF);
    const u32 sAb = (u32)__cvta_generic_to_shared(sA);

    const int tid  = threadIdx.x;
    const int lane = tid & 31;
    const int warp = tid >> 5;
    const int mw = warp & 1;          // oc half
    const int nw = warp >> 1;         // h row (0..3)
    const int grp = lane >> 3, r8 = lane & 7;
    const int h0 = blockIdx.x * 4;
    const int d  = blockIdx.y;

    // ---- stage features: split fp32 -> bf16 hi/lo, rows [dz][hh][wp] ----
    for (int t = tid; t < 14400; t += 256) {
        int wp = t % 50;
        int q  = t / 50;
        int hh = q % 6;
        int q2 = q / 6;
        int dzi = q2 % 3;
        int ci2 = q2 / 3;             // 0..15 (pair of channels)
        int z = min(max(d - 1 + dzi, 0), 47);
        int y = min(max(h0 - 1 + hh, 0), 47);
        int w = min(max(wp - 1, 0), 47);
        long gi = (long)(2 * ci2) * VOX + (z * 48 + y) * 48 + w;
        float f0 = feat[gi];
        float f1 = feat[gi + VOX];
        __nv_bfloat16 h0b = __float2bfloat16(f0);
        __nv_bfloat16 h1b = __float2bfloat16(f1);
        __nv_bfloat16 l0b = __float2bfloat16(f0 - __bfloat162float(h0b));
        __nv_bfloat16 l1b = __float2bfloat16(f1 - __bfloat162float(h1b));
        int row = (dzi * 6 + hh) * 50 + wp;
        u32 hp = ((u32)__bfloat16_as_ushort(h1b) << 16) | (u32)__bfloat16_as_ushort(h0b);
        u32 lp = ((u32)__bfloat16_as_ushort(l1b) << 16) | (u32)__bfloat16_as_ushort(l0b);
        *(u32*)(sF + row * 144 + ci2 * 4)      = hp;
        *(u32*)(sF + row * 144 + 64 + ci2 * 4) = lp;
    }

    float D[2][6][4];
#pragma unroll
    for (int mi = 0; mi < 2; mi++)
#pragma unroll
        for (int j = 0; j < 6; j++)
#pragma unroll
            for (int c = 0; c < 4; c++) D[mi][j][c] = 0.0f;

#pragma unroll 1
    for (int dz = 0; dz < 3; dz++) {
        __syncthreads();
        // stage A slab for this dz (contiguous uint4 copy)
        {
            const uint4* src = (const uint4*)(g_w1a + (size_t)dz * 9 * 64 * 72);
            uint4* dst = (uint4*)sA;
            for (int t = tid; t < 5184; t += 256) dst[t] = src[t];
        }
        __syncthreads();

#pragma unroll 1
        for (int dy = 0; dy < 3; dy++) {
#pragma unroll 1
            for (int dx = 0; dx < 3; dx++) {
                const u32 tapBase = sAb + (dy * 3 + dx) * 64 * 144;
                const int rowBase = (dz * 6 + nw + dy) * 50 + dx;
#pragma unroll
                for (int kc = 0; kc < 2; kc++) {
                    // A fragments (2 m16 tiles), hi and lo
                    u32 a_hi[2][4], a_lo[2][4];
#pragma unroll
                    for (int mi = 0; mi < 2; mi++) {
                        u32 ab = tapBase
                               + (mw * 32 + mi * 16 + (grp & 1) * 8 + r8) * 144
                               + (grp >> 1) * 16 + kc * 32;
                        ldsm4(a_hi[mi][0], a_hi[mi][1], a_hi[mi][2], a_hi[mi][3], ab);
                        ldsm4(a_lo[mi][0], a_lo[mi][1], a_lo[mi][2], a_lo[mi][3], ab + 64);
                    }
                    // B_hi fragments (6 n8 tiles via 3 x4 NON-trans ldmatrix):
                    // m0 = n0-7/k0-7 (b0 tile0), m1 = n0-7/k8-15 (b1 tile0),
                    // m2 = n8-15/k0-7 (b0 tile1), m3 = n8-15/k8-15 (b1 tile1)
                    u32 bh[6][2];
#pragma unroll
                    for (int jj = 0; jj < 3; jj++) {
                        int rowI = rowBase + jj * 16 + (grp >> 1) * 8 + r8;
                        u32 bb = sFb + rowI * 144 + (grp & 1) * 16 + kc * 32;
                        ldsm4(bh[2 * jj][0], bh[2 * jj][1],
                              bh[2 * jj + 1][0], bh[2 * jj + 1][1], bb);
                    }
#pragma unroll
                    for (int mi = 0; mi < 2; mi++)
#pragma unroll
                        for (int j = 0; j < 6; j++) {
                            mmabf(D[mi][j], a_hi[mi], bh[j]);
                            mmabf(D[mi][j], a_lo[mi], bh[j]);
                        }
                    // B_lo fragments
                    u32 bl[6][2];
#pragma unroll
                    for (int jj = 0; jj < 3; jj++) {
                        int rowI = rowBase + jj * 16 + (grp >> 1) * 8 + r8;
                        u32 bb = sFb + rowI * 144 + 64 + (grp & 1) * 16 + kc * 32;
                        ldsm4(bl[2 * jj][0], bl[2 * jj][1],
                              bl[2 * jj + 1][0], bl[2 * jj + 1][1], bb);
                    }
#pragma unroll
                    for (int mi = 0; mi < 2; mi++)
#pragma unroll
                        for (int j = 0; j < 6; j++)
                            mmabf(D[mi][j], a_hi[mi], bl[j]);
                }
            }
        }
    }

    // ---- epilogue: bias + SiLU + store to g_h[vox][oc] ----
    const int tr = lane >> 2, tc = lane & 3;
    const int hrow = h0 + nw;
#pragma unroll
    for (int mi = 0; mi < 2; mi++) {
        int oc0 = mw * 32 + mi * 16 + tr;
        int oc1 = oc0 + 8;
        float bias0 = b1[oc0], bias1 = b1[oc1];
#pragma unroll
        for (int j = 0; j < 6; j++) {
            int w0 = j * 8 + 2 * tc;
            long base = ((long)(d * 48 + hrow) * 48 + w0) * 64;
            float v0 = D[mi][j][0] + bias0;
            float v1 = D[mi][j][1] + bias0;
            float v2 = D[mi][j][2] + bias1;
            float v3 = D[mi][j][3] + bias1;
            g_h[base + oc0]      = v0 / (1.0f + __expf(-v0));
            g_h[base + 64 + oc0] = v1 / (1.0f + __expf(-v1));
            g_h[base + oc1]      = v2 / (1.0f + __expf(-v2));
            g_h[base + 64 + oc1] = v3 / (1.0f + __expf(-v3));
        }
    }
}

// ---------------------------------------------------------------------------
// Kernel 2 (unchanged from R4): per (d,h) row of 48 voxels.
// ---------------------------------------------------------------------------
extern "C" __global__ void __launch_bounds__(256, 3) k_mask_apply(
    const float* __restrict__ x, const float* __restrict__ b2,
    float* __restrict__ out)
{
    extern __shared__ float sm2[];
    float* sMt = sm2;            // 10464
    float* sHd = sm2 + 10464;    // 6240 (v*130 + 2k, duplicated h)

    const int tid = threadIdx.x;
    const int hB = blockIdx.x, d = blockIdx.y;

    {
        long rowb = (long)((d * 48 + hB) * 48) * 64;
        for (int t = tid; t < 3072; t += 256) {
            int k = t & 63, v = t >> 6;
            float hv = g_h[rowb + t];
            *(float2*)&sHd[v * 130 + 2 * k] = make_float2(hv, hv);
        }
    }
    __syncthreads();

    if (tid < 216) {
        const int v0  = (tid & 7) * 6;
        const int mc0 = (tid >> 3) * 8;
        u64 acc[6][4];
        {
            u64 bb[4];
#pragma unroll
            for (int jp = 0; jp < 4; jp++) bb[jp] = *(const u64*)&b2[mc0 + 2 * jp];
#pragma unroll
            for (int i = 0; i < 6; i++)
#pragma unroll
                for (int jp = 0; jp < 4; jp++) acc[i][jp] = bb[jp];
        }
#pragma unroll 4
        for (int k = 0; k < 64; k++) {
            u64 hd[6];
#pragma unroll
            for (int i = 0; i < 6; i++)
                hd[i] = *(const u64*)&sHd[(v0 + i) * 130 + 2 * k];
            const float* wr = g_w2t + k * 216 + mc0;
            float4 wA = *(const float4*)wr;
            float4 wB = *(const float4*)(wr + 4);
            u64 wv[4] = { *(u64*)&wA.x, *(u64*)&wA.z, *(u64*)&wB.x, *(u64*)&wB.z };
#pragma unroll
            for (int i = 0; i < 6; i++)
#pragma unroll
                for (int jp = 0; jp < 4; jp++)
                    fma2(acc[i][jp], hd[i], wv[jp]);
        }
#pragma unroll
        for (int i = 0; i < 6; i++) {
            float* row = &sMt[(v0 + i) * 218];
#pragma unroll
            for (int jp = 0; jp < 4; jp++) {
                float2 val = *(float2*)&acc[i][jp];
                int mcA = mc0 + 2 * jp, mcB = mcA + 1;
                row[(mcA % 27) * 8 + mcA / 27] = val.x;
                row[(mcB % 27) * 8 + mcB / 27] = val.y;
            }
        }
    }
    __syncthreads();

    for (int s = tid; s < 384; s += 256) {
        int v = s >> 3, g = s & 7;
        float* p = &sMt[v * 218 + g];
        float mx = p[0];
#pragma unroll
        for (int n = 1; n < 27; n++) mx = fmaxf(mx, p[n * 8]);
        float e[27], ssum = 0.0f;
#pragma unroll
        for (int n = 0; n < 27; n++) { e[n] = __expf(p[n * 8] - mx); ssum += e[n]; }
        float inv = 1.0f / ssum;
#pragma unroll
        for (int n = 0; n < 27; n++) p[n * 8] = e[n] * inv;
    }
    __syncthreads();

    int zd[3], zh[3];
#pragma unroll
    for (int t = 0; t < 3; t++) {
        zd[t] = min(max(d + t - 1, 0), 47);
        zh[t] = min(max(hB + t - 1, 0), 47);
    }

#pragma unroll 1
    for (int p = tid; p < 768; p += 256) {
        int v = p % 48, cp = p / 48;
        int zw[3];
        zw[0] = max(v - 1, 0); zw[1] = v; zw[2] = min(v + 1, 47);
        const float* x0 = x + (long)cp * VOX;
        const float* x1 = x + (long)(cp + 16) * VOX;
        const float* mB = &sMt[v * 218];

        u64 a0[4], a1[4];
#pragma unroll
        for (int q = 0; q < 4; q++) { a0[q] = 0ull; a1[q] = 0ull; }

#pragma unroll
        for (int dz = 0; dz < 3; dz++) {
#pragma unroll
            for (int dy = 0; dy < 3; dy++) {
                long rbase = ((long)zd[dz] * 48 + zh[dy]) * 48;
                float t0[3], t1[3];
#pragma unroll
                for (int dx = 0; dx < 3; dx++) {
                    t0[dx] = x0[rbase + zw[dx]];
                    t1[dx] = x1[rbase + zw[dx]];
                }
#pragma unroll
                for (int dx = 0; dx < 3; dx++) {
                    int n = (dz * 3 + dy) * 3 + dx;
                    const u64* mp = (const u64*)(mB + n * 8);
                    u64 T0 = dup2(t0[dx]);
                    u64 T1 = dup2(t1[dx]);
                    fma2(a0[0], mp[0], T0); fma2(a1[0], mp[0], T1);
                    fma2(a0[1], mp[1], T0); fma2(a1[1], mp[1], T1);
                    fma2(a0[2], mp[2], T0); fma2(a1[2], mp[2], T1);
                    fma2(a0[3], mp[3], T0); fma2(a1[3], mp[3], T1);
                }
            }
        }

#pragma unroll
        for (int i = 0; i < 2; i++)
#pragma unroll
            for (int j = 0; j < 2; j++) {
                int q = i * 2 + j;
                long ob0 = (((long)cp * 96 + 2 * d + i) * 96 + 2 * hB + j) * 96 + 2 * v;
                long ob1 = (((long)(cp + 16) * 96 + 2 * d + i) * 96 + 2 * hB + j) * 96 + 2 * v;
                *(float2*)&out[ob0] = *(float2*)&a0[q];
                *(float2*)&out[ob1] = *(float2*)&a1[q];
            }
    }
}

// ---------------------------------------------------------------------------
extern "C" void kernel_launch(void* const* d_in, const int* in_sizes, int n_in,
                              void* d_out, int out_size)
{
    const float* x    = (const float*)d_in[0];
    const float* feat = (const float*)d_in[1];
    const float* w1   = (const float*)d_in[2];
    const float* b1   = (const float*)d_in[3];
    const float* w2   = (const float*)d_in[4];
    const float* b2   = (const float*)d_in[5];
    float* out = (float*)d_out;

    const int smem1 = 900 * 144 + 576 * 144;  // 212544 B
    const int smem2 = (10464 + 6240) * 4;     // 66816 B
    cudaFuncSetAttribute(k_conv1, cudaFuncAttributeMaxDynamicSharedMemorySize, smem1);
    cudaFuncSetAttribute(k_mask_apply, cudaFuncAttributeMaxDynamicSharedMemorySize, smem2);

    k_prep<<<271, 256>>>(w1, w2);
    k_conv1<<<dim3(12, 48), 256, smem1>>>(feat, b1);
    k_mask_apply<<<dim3(48, 48), 256, smem2>>>(x, b2, out);
}

// round 7
// speedup vs baseline: 2.4426x; 1.0136x over previous
#include <cuda_runtime.h>
#include <cuda_bf16.h>
#include <cstdint>

#define VOX (48*48*48)
typedef unsigned long long u64;
typedef unsigned int u32;

// Device globals
__device__ float g_h[VOX * 64];                   // [voxel][64] conv1 output
__device__ __nv_bfloat16 g_w1a[3 * 9 * 64 * 72];  // [dz][tap9][oc64][72]: row 144B = [hi ci0-31 | lo ci0-31 | pad]
__device__ float g_w2t[13824];                    // [k*216 + mc]

__device__ __forceinline__ void fma2(u64& acc, u64 a, u64 b) {
    asm("fma.rn.f32x2 %0, %1, %2, %0;" : "+l"(acc) : "l"(a), "l"(b));
}
__device__ __forceinline__ u64 dup2(float v) {
    u64 r; asm("mov.b64 %0, {%1, %1};" : "=l"(r) : "f"(v)); return r;
}
// pack {lo=cvt(a), hi=cvt(b)} bf16x2
__device__ __forceinline__ u32 cvt2bf(float a, float b) {
    u32 r; asm("cvt.rn.bf16x2.f32 %0, %1, %2;" : "=r"(r) : "f"(b), "f"(a)); return r;
}

__device__ __forceinline__ void ldsm4(u32& r0, u32& r1, u32& r2, u32& r3, u32 a) {
    asm volatile("ldmatrix.sync.aligned.m8n8.x4.shared.b16 {%0,%1,%2,%3}, [%4];"
                 : "=r"(r0), "=r"(r1), "=r"(r2), "=r"(r3) : "r"(a));
}
__device__ __forceinline__ void mmabf(float* d, const u32* a, const u32* b) {
    asm volatile(
        "mma.sync.aligned.m16n8k16.row.col.f32.bf16.bf16.f32 "
        "{%0,%1,%2,%3}, {%4,%5,%6,%7}, {%8,%9}, {%0,%1,%2,%3};"
        : "+f"(d[0]), "+f"(d[1]), "+f"(d[2]), "+f"(d[3])
        : "r"(a[0]), "r"(a[1]), "r"(a[2]), "r"(a[3]), "r"(b[0]), "r"(b[1]));
}

// ---------------------------------------------------------------------------
// Prep: split w1 into bf16 hi/lo in MMA-A layout; transpose w2.
// ---------------------------------------------------------------------------
extern "C" __global__ void k_prep(const float* __restrict__ w1,
                                  const float* __restrict__ w2)
{
    int id = blockIdx.x * 256 + threadIdx.x;
    if (id < 13824) {
        int k = id / 216, mc = id % 216;
        g_w2t[id] = w2[mc * 64 + k];
    } else if (id < 13824 + 55296) {
        int q = id - 13824;
        int ci = q & 31;
        int r  = q >> 5;
        int oc = r & 63;
        int r2 = r >> 6;          // dz*9 + tap
        int tap = r2 % 9, dz = r2 / 9;
        float v = w1[oc * 864 + ci * 27 + dz * 9 + tap];
        __nv_bfloat16 hi = __float2bfloat16(v);
        __nv_bfloat16 lo = __float2bfloat16(v - __bfloat162float(hi));
        int base = ((dz * 9 + tap) * 64 + oc) * 72;
        g_w1a[base + ci]      = hi;
        g_w1a[base + 32 + ci] = lo;
    }
}

// ---------------------------------------------------------------------------
// Kernel 1: h = silu(conv3x3x3(features)) via mma.sync bf16 hi/lo split.
// (structure unchanged from R6; staging conversion uses cvt.rn.bf16x2)
// ---------------------------------------------------------------------------
extern "C" __global__ void __launch_bounds__(256, 1) k_conv1(
    const float* __restrict__ feat, const float* __restrict__ b1)
{
    extern __shared__ char sm[];
    char* sF = sm;                    // 129600 B
    char* sA = sm + 900 * 144;        // 82944 B
    const u32 sFb = (u32)__cvta_generic_to_shared(sF);
    const u32 sAb = (u32)__cvta_generic_to_shared(sA);

    const int tid  = threadIdx.x;
    const int lane = tid & 31;
    const int warp = tid >> 5;
    const int mw = warp & 1;          // oc half
    const int nw = warp >> 1;         // h row (0..3)
    const int grp = lane >> 3, r8 = lane & 7;
    const int h0 = blockIdx.x * 4;
    const int d  = blockIdx.y;

    // ---- stage features: split fp32 -> bf16 hi/lo, rows [dz][hh][wp] ----
    for (int t = tid; t < 14400; t += 256) {
        int wp = t % 50;
        int q  = t / 50;
        int hh = q % 6;
        int q2 = q / 6;
        int dzi = q2 % 3;
        int ci2 = q2 / 3;             // 0..15 (pair of channels)
        int z = min(max(d - 1 + dzi, 0), 47);
        int y = min(max(h0 - 1 + hh, 0), 47);
        int w = min(max(wp - 1, 0), 47);
        long gi = (long)(2 * ci2) * VOX + (z * 48 + y) * 48 + w;
        float f0 = feat[gi];
        float f1 = feat[gi + VOX];
        u32 hp = cvt2bf(f0, f1);
        float r0 = f0 - __uint_as_float(hp << 16);
        float r1 = f1 - __uint_as_float(hp & 0xffff0000u);
        u32 lp = cvt2bf(r0, r1);
        int row = (dzi * 6 + hh) * 50 + wp;
        *(u32*)(sF + row * 144 + ci2 * 4)      = hp;
        *(u32*)(sF + row * 144 + 64 + ci2 * 4) = lp;
    }

    float D[2][6][4];
#pragma unroll
    for (int mi = 0; mi < 2; mi++)
#pragma unroll
        for (int j = 0; j < 6; j++)
#pragma unroll
            for (int c = 0; c < 4; c++) D[mi][j][c] = 0.0f;

#pragma unroll 1
    for (int dz = 0; dz < 3; dz++) {
        __syncthreads();
        {
            const uint4* src = (const uint4*)(g_w1a + (size_t)dz * 9 * 64 * 72);
            uint4* dst = (uint4*)sA;
            for (int t = tid; t < 5184; t += 256) dst[t] = src[t];
        }
        __syncthreads();

#pragma unroll 1
        for (int dy = 0; dy < 3; dy++) {
#pragma unroll 1
            for (int dx = 0; dx < 3; dx++) {
                const u32 tapBase = sAb + (dy * 3 + dx) * 64 * 144;
                const int rowBase = (dz * 6 + nw + dy) * 50 + dx;
#pragma unroll
                for (int kc = 0; kc < 2; kc++) {
                    u32 a_hi[2][4], a_lo[2][4];
#pragma unroll
                    for (int mi = 0; mi < 2; mi++) {
                        u32 ab = tapBase
                               + (mw * 32 + mi * 16 + (grp & 1) * 8 + r8) * 144
                               + (grp >> 1) * 16 + kc * 32;
                        ldsm4(a_hi[mi][0], a_hi[mi][1], a_hi[mi][2], a_hi[mi][3], ab);
                        ldsm4(a_lo[mi][0], a_lo[mi][1], a_lo[mi][2], a_lo[mi][3], ab + 64);
                    }
                    u32 bh[6][2];
#pragma unroll
                    for (int jj = 0; jj < 3; jj++) {
                        int rowI = rowBase + jj * 16 + (grp >> 1) * 8 + r8;
                        u32 bb = sFb + rowI * 144 + (grp & 1) * 16 + kc * 32;
                        ldsm4(bh[2 * jj][0], bh[2 * jj][1],
                              bh[2 * jj + 1][0], bh[2 * jj + 1][1], bb);
                    }
#pragma unroll
                    for (int mi = 0; mi < 2; mi++)
#pragma unroll
                        for (int j = 0; j < 6; j++) {
                            mmabf(D[mi][j], a_hi[mi], bh[j]);
                            mmabf(D[mi][j], a_lo[mi], bh[j]);
                        }
                    u32 bl[6][2];
#pragma unroll
                    for (int jj = 0; jj < 3; jj++) {
                        int rowI = rowBase + jj * 16 + (grp >> 1) * 8 + r8;
                        u32 bb = sFb + rowI * 144 + 64 + (grp & 1) * 16 + kc * 32;
                        ldsm4(bl[2 * jj][0], bl[2 * jj][1],
                              bl[2 * jj + 1][0], bl[2 * jj + 1][1], bb);
                    }
#pragma unroll
                    for (int mi = 0; mi < 2; mi++)
#pragma unroll
                        for (int j = 0; j < 6; j++)
                            mmabf(D[mi][j], a_hi[mi], bl[j]);
                }
            }
        }
    }

    // ---- epilogue: bias + SiLU + store to g_h[vox][oc] ----
    const int tr = lane >> 2, tc = lane & 3;
    const int hrow = h0 + nw;
#pragma unroll
    for (int mi = 0; mi < 2; mi++) {
        int oc0 = mw * 32 + mi * 16 + tr;
        int oc1 = oc0 + 8;
        float bias0 = b1[oc0], bias1 = b1[oc1];
#pragma unroll
        for (int j = 0; j < 6; j++) {
            int w0 = j * 8 + 2 * tc;
            long base = ((long)(d * 48 + hrow) * 48 + w0) * 64;
            float v0 = D[mi][j][0] + bias0;
            float v1 = D[mi][j][1] + bias0;
            float v2 = D[mi][j][2] + bias1;
            float v3 = D[mi][j][3] + bias1;
            g_h[base + oc0]      = v0 / (1.0f + __expf(-v0));
            g_h[base + 64 + oc0] = v1 / (1.0f + __expf(-v1));
            g_h[base + oc1]      = v2 / (1.0f + __expf(-v2));
            g_h[base + 64 + oc1] = v3 / (1.0f + __expf(-v3));
        }
    }
}

// ---------------------------------------------------------------------------
// Kernel 2: per (d,h) row of 48 voxels.
//   A: GEMM -> sMt[v*220 + n*8 + g] (stride 220: LDS.128 conflict-free)
//   B: softmax per (v,g)
//   C: apply, 4 channels per thread (384 slots), masks via 2x LDS.128
// smem: sMt 48*220 = 10560 ; sHd 48*130 = 6240  -> 67200 B
// ---------------------------------------------------------------------------
extern "C" __global__ void __launch_bounds__(256, 3) k_mask_apply(
    const float* __restrict__ x, const float* __restrict__ b2,
    float* __restrict__ out)
{
    extern __shared__ float sm2[];
    float* sMt = sm2;            // 10560
    float* sHd = sm2 + 10560;    // 6240 (v*130 + 2k, duplicated h)

    const int tid = threadIdx.x;
    const int hB = blockIdx.x, d = blockIdx.y;

    {
        long rowb = (long)((d * 48 + hB) * 48) * 64;
        for (int t = tid; t < 3072; t += 256) {
            int k = t & 63, v = t >> 6;
            float hv = g_h[rowb + t];
            *(float2*)&sHd[v * 130 + 2 * k] = make_float2(hv, hv);
        }
    }
    __syncthreads();

    // ---- A: 1x1 conv GEMM, 6v x 8mc tiles, f32x2 over mc pairs ----
    if (tid < 216) {
        const int v0  = (tid & 7) * 6;
        const int mc0 = (tid >> 3) * 8;
        u64 acc[6][4];
        {
            u64 bb[4];
#pragma unroll
            for (int jp = 0; jp < 4; jp++) bb[jp] = *(const u64*)&b2[mc0 + 2 * jp];
#pragma unroll
            for (int i = 0; i < 6; i++)
#pragma unroll
                for (int jp = 0; jp < 4; jp++) acc[i][jp] = bb[jp];
        }
#pragma unroll 4
        for (int k = 0; k < 64; k++) {
            u64 hd[6];
#pragma unroll
            for (int i = 0; i < 6; i++)
                hd[i] = *(const u64*)&sHd[(v0 + i) * 130 + 2 * k];
            const float* wr = g_w2t + k * 216 + mc0;
            float4 wA = *(const float4*)wr;
            float4 wB = *(const float4*)(wr + 4);
            u64 wv[4] = { *(u64*)&wA.x, *(u64*)&wA.z, *(u64*)&wB.x, *(u64*)&wB.z };
#pragma unroll
            for (int i = 0; i < 6; i++)
#pragma unroll
                for (int jp = 0; jp < 4; jp++)
                    fma2(acc[i][jp], hd[i], wv[jp]);
        }
#pragma unroll
        for (int i = 0; i < 6; i++) {
            float* row = &sMt[(v0 + i) * 220];
#pragma unroll
            for (int jp = 0; jp < 4; jp++) {
                float2 val = *(float2*)&acc[i][jp];
                int mcA = mc0 + 2 * jp, mcB = mcA + 1;
                row[(mcA % 27) * 8 + mcA / 27] = val.x;
                row[(mcB % 27) * 8 + mcB / 27] = val.y;
            }
        }
    }
    __syncthreads();

    // ---- B: softmax over n for each (v,g) ----
    for (int s = tid; s < 384; s += 256) {
        int v = s >> 3, g = s & 7;
        float* p = &sMt[v * 220 + g];
        float mx = p[0];
#pragma unroll
        for (int n = 1; n < 27; n++) mx = fmaxf(mx, p[n * 8]);
        float e[27], ssum = 0.0f;
#pragma unroll
        for (int n = 0; n < 27; n++) { e[n] = __expf(p[n * 8] - mx); ssum += e[n]; }
        float inv = 1.0f / ssum;
#pragma unroll
        for (int n = 0; n < 27; n++) p[n * 8] = e[n] * inv;
    }
    __syncthreads();

    // ---- C: apply. slot = (v, cq) -> channels cq, cq+8, cq+16, cq+24 ----
    int zd[3], zh[3];
#pragma unroll
    for (int t = 0; t < 3; t++) {
        zd[t] = min(max(d + t - 1, 0), 47);
        zh[t] = min(max(hB + t - 1, 0), 47);
    }

#pragma unroll 1
    for (int p = tid; p < 384; p += 256) {
        int v = p % 48, cq = p / 48;        // cq in 0..7
        int zw[3];
        zw[0] = max(v - 1, 0); zw[1] = v; zw[2] = min(v + 1, 47);
        const float* mB = &sMt[v * 220];

        u64 acc[4][4];                      // [channel][g-pair]
#pragma unroll
        for (int ch = 0; ch < 4; ch++)
#pragma unroll
            for (int q = 0; q < 4; q++) acc[ch][q] = 0ull;

#pragma unroll
        for (int dz = 0; dz < 3; dz++) {
#pragma unroll
            for (int dy = 0; dy < 3; dy++) {
                long rbase = ((long)zd[dz] * 48 + zh[dy]) * 48;
                float tv[4][3];
#pragma unroll
                for (int ch = 0; ch < 4; ch++) {
                    const float* xc = x + (long)(cq + 8 * ch) * VOX + rbase;
#pragma unroll
                    for (int dx = 0; dx < 3; dx++) tv[ch][dx] = xc[zw[dx]];
                }
#pragma unroll
                for (int dx = 0; dx < 3; dx++) {
                    int n = (dz * 3 + dy) * 3 + dx;
                    const ulonglong2* mp = (const ulonglong2*)(mB + n * 8);
                    ulonglong2 mLo = mp[0];   // {m01, m23}
                    ulonglong2 mHi = mp[1];   // {m45, m67}
#pragma unroll
                    for (int ch = 0; ch < 4; ch++) {
                        u64 T = dup2(tv[ch][dx]);
                        fma2(acc[ch][0], mLo.x, T);
                        fma2(acc[ch][1], mLo.y, T);
                        fma2(acc[ch][2], mHi.x, T);
                        fma2(acc[ch][3], mHi.y, T);
                    }
                }
            }
        }

        // acc pair {g0=i*4+j*2, g0+1} = {k=0, k=1} -> direct float2 store
#pragma unroll
        for (int ch = 0; ch < 4; ch++) {
            int c = cq + 8 * ch;
#pragma unroll
            for (int i = 0; i < 2; i++)
#pragma unroll
                for (int j = 0; j < 2; j++) {
                    int q = i * 2 + j;
                    long ob = (((long)c * 96 + 2 * d + i) * 96 + 2 * hB + j) * 96 + 2 * v;
                    *(float2*)&out[ob] = *(float2*)&acc[ch][q];
                }
        }
    }
}

// ---------------------------------------------------------------------------
extern "C" void kernel_launch(void* const* d_in, const int* in_sizes, int n_in,
                              void* d_out, int out_size)
{
    const float* x    = (const float*)d_in[0];
    const float* feat = (const float*)d_in[1];
    const float* w1   = (const float*)d_in[2];
    const float* b1   = (const float*)d_in[3];
    const float* w2   = (const float*)d_in[4];
    const float* b2   = (const float*)d_in[5];
    float* out = (float*)d_out;

    const int smem1 = 900 * 144 + 576 * 144;  // 212544 B
    const int smem2 = (10560 + 6240) * 4;     // 67200 B
    cudaFuncSetAttribute(k_conv1, cudaFuncAttributeMaxDynamicSharedMemorySize, smem1);
    cudaFuncSetAttribute(k_mask_apply, cudaFuncAttributeMaxDynamicSharedMemorySize, smem2);

    k_prep<<<271, 256>>>(w1, w2);
    k_conv1<<<dim3(12, 48), 256, smem1>>>(feat, b1);
    k_mask_apply<<<dim3(48, 48), 256, smem2>>>(x, b2, out);
}

// round 8
// speedup vs baseline: 3.1465x; 1.2882x over previous
#include <cuda_runtime.h>
#include <cuda_bf16.h>
#include <cstdint>

#define VOX (48*48*48)
typedef unsigned long long u64;
typedef unsigned int u32;

// Device globals
__device__ float g_h[VOX * 64];                   // [voxel][64] conv1 output
__device__ __nv_bfloat16 g_w1a[3 * 9 * 64 * 72];  // conv1 A: [dz][tap9][oc64][hi32|lo32|pad]
__device__ u32 g_w2frag[13824];                   // conv2 B frags: [nt27][kt4][pass2][lane32][b0,b1]

__device__ __forceinline__ void fma2(u64& acc, u64 a, u64 b) {
    asm("fma.rn.f32x2 %0, %1, %2, %0;" : "+l"(acc) : "l"(a), "l"(b));
}
__device__ __forceinline__ u64 dup2(float v) {
    u64 r; asm("mov.b64 %0, {%1, %1};" : "=l"(r) : "f"(v)); return r;
}
// pack bf16x2 {lo=rn(a), hi=rn(b)}
__device__ __forceinline__ u32 cvt2bf(float a, float b) {
    u32 r; asm("cvt.rn.bf16x2.f32 %0, %1, %2;" : "=r"(r) : "f"(b), "f"(a)); return r;
}

__device__ __forceinline__ void ldsm4(u32& r0, u32& r1, u32& r2, u32& r3, u32 a) {
    asm volatile("ldmatrix.sync.aligned.m8n8.x4.shared.b16 {%0,%1,%2,%3}, [%4];"
                 : "=r"(r0), "=r"(r1), "=r"(r2), "=r"(r3) : "r"(a));
}
__device__ __forceinline__ void mmabf(float* d, const u32* a, const u32* b) {
    asm volatile(
        "mma.sync.aligned.m16n8k16.row.col.f32.bf16.bf16.f32 "
        "{%0,%1,%2,%3}, {%4,%5,%6,%7}, {%8,%9}, {%0,%1,%2,%3};"
        : "+f"(d[0]), "+f"(d[1]), "+f"(d[2]), "+f"(d[3])
        : "r"(a[0]), "r"(a[1]), "r"(a[2]), "r"(a[3]), "r"(b[0]), "r"(b[1]));
}

// ---------------------------------------------------------------------------
// Prep: w1 -> bf16 hi/lo MMA-A layout; w2 -> pre-baked bf16 hi/lo B fragments.
// B frag (m16n8k16, [n][k] col-major source): thread(tr=lane>>2, tc=lane&3):
//   b0 = {B[k0, n], B[k0+1, n]},  b1 = {B[k0+8, n], B[k0+9, n]},
//   n = nt*8+tr, k0 = kt*16+2tc.
// ---------------------------------------------------------------------------
extern "C" __global__ void k_prep(const float* __restrict__ w1,
                                  const float* __restrict__ w2)
{
    int id = blockIdx.x * 256 + threadIdx.x;
    if (id < 13824) {
        // one u32 of g_w2frag
        int breg  = id & 1;
        int entry = id >> 1;
        int lane  = entry & 31;
        int q     = entry >> 5;
        int pass  = q & 1;           // 0 = hi, 1 = lo
        int kt    = (q >> 1) & 3;
        int nt    = q >> 3;
        int tr = lane >> 2, tc = lane & 3;
        int mc = nt * 8 + tr;
        int k0 = kt * 16 + 2 * tc + breg * 8;
        float v0 = w2[mc * 64 + k0];
        float v1 = w2[mc * 64 + k0 + 1];
        __nv_bfloat16 h0 = __float2bfloat16(v0);
        __nv_bfloat16 h1 = __float2bfloat16(v1);
        u32 out;
        if (pass == 0) {
            out = ((u32)__bfloat16_as_ushort(h1) << 16) | (u32)__bfloat16_as_ushort(h0);
        } else {
            __nv_bfloat16 l0 = __float2bfloat16(v0 - __bfloat162float(h0));
            __nv_bfloat16 l1 = __float2bfloat16(v1 - __bfloat162float(h1));
            out = ((u32)__bfloat16_as_ushort(l1) << 16) | (u32)__bfloat16_as_ushort(l0);
        }
        g_w2frag[id] = out;
    } else if (id < 13824 + 55296) {
        int q = id - 13824;
        int ci = q & 31;
        int r  = q >> 5;
        int oc = r & 63;
        int r2 = r >> 6;
        int tap = r2 % 9, dz = r2 / 9;
        float v = w1[oc * 864 + ci * 27 + dz * 9 + tap];
        __nv_bfloat16 hi = __float2bfloat16(v);
        __nv_bfloat16 lo = __float2bfloat16(v - __bfloat162float(hi));
        int base = ((dz * 9 + tap) * 64 + oc) * 72;
        g_w1a[base + ci]      = hi;
        g_w1a[base + 32 + ci] = lo;
    }
}

// ---------------------------------------------------------------------------
// Kernel 1 (unchanged from R7): conv3x3x3 + SiLU via mma.sync bf16 hi/lo.
// ---------------------------------------------------------------------------
extern "C" __global__ void __launch_bounds__(256, 1) k_conv1(
    const float* __restrict__ feat, const float* __restrict__ b1)
{
    extern __shared__ char sm[];
    char* sF = sm;                    // 129600 B
    char* sA = sm + 900 * 144;        // 82944 B
    const u32 sFb = (u32)__cvta_generic_to_shared(sF);
    const u32 sAb = (u32)__cvta_generic_to_shared(sA);

    const int tid  = threadIdx.x;
    const int lane = tid & 31;
    const int warp = tid >> 5;
    const int mw = warp & 1;
    const int nw = warp >> 1;
    const int grp = lane >> 3, r8 = lane & 7;
    const int h0 = blockIdx.x * 4;
    const int d  = blockIdx.y;

    for (int t = tid; t < 14400; t += 256) {
        int wp = t % 50;
        int q  = t / 50;
        int hh = q % 6;
        int q2 = q / 6;
        int dzi = q2 % 3;
        int ci2 = q2 / 3;
        int z = min(max(d - 1 + dzi, 0), 47);
        int y = min(max(h0 - 1 + hh, 0), 47);
        int w = min(max(wp - 1, 0), 47);
        long gi = (long)(2 * ci2) * VOX + (z * 48 + y) * 48 + w;
        float f0 = feat[gi];
        float f1 = feat[gi + VOX];
        u32 hp = cvt2bf(f0, f1);
        float r0 = f0 - __uint_as_float(hp << 16);
        float r1 = f1 - __uint_as_float(hp & 0xffff0000u);
        u32 lp = cvt2bf(r0, r1);
        int row = (dzi * 6 + hh) * 50 + wp;
        *(u32*)(sF + row * 144 + ci2 * 4)      = hp;
        *(u32*)(sF + row * 144 + 64 + ci2 * 4) = lp;
    }

    float D[2][6][4];
#pragma unroll
    for (int mi = 0; mi < 2; mi++)
#pragma unroll
        for (int j = 0; j < 6; j++)
#pragma unroll
            for (int c = 0; c < 4; c++) D[mi][j][c] = 0.0f;

#pragma unroll 1
    for (int dz = 0; dz < 3; dz++) {
        __syncthreads();
        {
            const uint4* src = (const uint4*)(g_w1a + (size_t)dz * 9 * 64 * 72);
            uint4* dst = (uint4*)sA;
            for (int t = tid; t < 5184; t += 256) dst[t] = src[t];
        }
        __syncthreads();

#pragma unroll 1
        for (int dy = 0; dy < 3; dy++) {
#pragma unroll 1
            for (int dx = 0; dx < 3; dx++) {
                const u32 tapBase = sAb + (dy * 3 + dx) * 64 * 144;
                const int rowBase = (dz * 6 + nw + dy) * 50 + dx;
#pragma unroll
                for (int kc = 0; kc < 2; kc++) {
                    u32 a_hi[2][4], a_lo[2][4];
#pragma unroll
                    for (int mi = 0; mi < 2; mi++) {
                        u32 ab = tapBase
                               + (mw * 32 + mi * 16 + (grp & 1) * 8 + r8) * 144
                               + (grp >> 1) * 16 + kc * 32;
                        ldsm4(a_hi[mi][0], a_hi[mi][1], a_hi[mi][2], a_hi[mi][3], ab);
                        ldsm4(a_lo[mi][0], a_lo[mi][1], a_lo[mi][2], a_lo[mi][3], ab + 64);
                    }
                    u32 bh[6][2];
#pragma unroll
                    for (int jj = 0; jj < 3; jj++) {
                        int rowI = rowBase + jj * 16 + (grp >> 1) * 8 + r8;
                        u32 bb = sFb + rowI * 144 + (grp & 1) * 16 + kc * 32;
                        ldsm4(bh[2 * jj][0], bh[2 * jj][1],
                              bh[2 * jj + 1][0], bh[2 * jj + 1][1], bb);
                    }
#pragma unroll
                    for (int mi = 0; mi < 2; mi++)
#pragma unroll
                        for (int j = 0; j < 6; j++) {
                            mmabf(D[mi][j], a_hi[mi], bh[j]);
                            mmabf(D[mi][j], a_lo[mi], bh[j]);
                        }
                    u32 bl[6][2];
#pragma unroll
                    for (int jj = 0; jj < 3; jj++) {
                        int rowI = rowBase + jj * 16 + (grp >> 1) * 8 + r8;
                        u32 bb = sFb + rowI * 144 + 64 + (grp & 1) * 16 + kc * 32;
                        ldsm4(bl[2 * jj][0], bl[2 * jj][1],
                              bl[2 * jj + 1][0], bl[2 * jj + 1][1], bb);
                    }
#pragma unroll
                    for (int mi = 0; mi < 2; mi++)
#pragma unroll
                        for (int j = 0; j < 6; j++)
                            mmabf(D[mi][j], a_hi[mi], bl[j]);
                }
            }
        }
    }

    const int tr = lane >> 2, tc = lane & 3;
    const int hrow = h0 + nw;
#pragma unroll
    for (int mi = 0; mi < 2; mi++) {
        int oc0 = mw * 32 + mi * 16 + tr;
        int oc1 = oc0 + 8;
        float bias0 = b1[oc0], bias1 = b1[oc1];
#pragma unroll
        for (int j = 0; j < 6; j++) {
            int w0 = j * 8 + 2 * tc;
            long base = ((long)(d * 48 + hrow) * 48 + w0) * 64;
            float v0 = D[mi][j][0] + bias0;
            float v1 = D[mi][j][1] + bias0;
            float v2 = D[mi][j][2] + bias1;
            float v3 = D[mi][j][3] + bias1;
            g_h[base + oc0]      = v0 / (1.0f + __expf(-v0));
            g_h[base + 64 + oc0] = v1 / (1.0f + __expf(-v1));
            g_h[base + oc1]      = v2 / (1.0f + __expf(-v2));
            g_h[base + 64 + oc1] = v3 / (1.0f + __expf(-v3));
        }
    }
}

// ---------------------------------------------------------------------------
// Kernel 2: per (d,h) row of 48 voxels.
//   A: conv2 GEMM via mma.sync bf16 hi/lo (M=48v x N=216mc x K=64):
//      h split to bf16 in smem rows (272 B pitch, conflict-free ldsm),
//      w2 B fragments streamed from pre-baked g_w2frag. Bias at scatter.
//      -> sMt[v*220 + n*8 + g]
//   B: softmax per (v,g) over n
//   C: apply, 4 channels/thread (unchanged)
// smem: sMt 48*220 = 10560 fl ; sH 48*68 = 3264 u32 -> 55296 B total
// ---------------------------------------------------------------------------
extern "C" __global__ void __launch_bounds__(256, 3) k_mask_apply(
    const float* __restrict__ x, const float* __restrict__ b2,
    float* __restrict__ out)
{
    extern __shared__ float sm2[];
    float* sMt = sm2;                  // 10560 floats
    u32*   sHu = (u32*)(sm2 + 10560);  // 3264 u32: v*68 + [hi kp0-31 | lo kp0-31 | pad4]
    const u32 sHb = (u32)__cvta_generic_to_shared(sHu);

    const int tid = threadIdx.x;
    const int lane = tid & 31, warp = tid >> 5;
    const int grp = lane >> 3, r8 = lane & 7;
    const int tr = lane >> 2, tc = lane & 3;
    const int hB = blockIdx.x, d = blockIdx.y;

    // ---- stage h, split fp32 -> bf16 hi/lo ----
    {
        long rowb = (long)((d * 48 + hB) * 48) * 64;
        for (int t = tid; t < 1536; t += 256) {
            int v = t >> 5, kp = t & 31;
            float2 f = *(const float2*)&g_h[rowb + v * 64 + 2 * kp];
            u32 hp = cvt2bf(f.x, f.y);
            float r0 = f.x - __uint_as_float(hp << 16);
            float r1 = f.y - __uint_as_float(hp & 0xffff0000u);
            u32 lp = cvt2bf(r0, r1);
            sHu[v * 68 + kp]      = hp;
            sHu[v * 68 + 32 + kp] = lp;
        }
    }
    __syncthreads();

    // ---- A: GEMM via mma. warp w owns n-tiles {w, w+8, w+16, w+24<27}. ----
    const uint2* w2f = (const uint2*)g_w2frag;
#pragma unroll 1
    for (int nt = warp; nt < 27; nt += 8) {
        float Dv[3][4];
#pragma unroll
        for (int mt = 0; mt < 3; mt++)
#pragma unroll
            for (int c = 0; c < 4; c++) Dv[mt][c] = 0.0f;

#pragma unroll
        for (int kt = 0; kt < 4; kt++) {
            u32 ah[3][4], al[3][4];
#pragma unroll
            for (int mt = 0; mt < 3; mt++) {
                u32 ab = sHb + (mt * 16 + (grp & 1) * 8 + r8) * 272
                       + (grp >> 1) * 16 + kt * 32;
                ldsm4(ah[mt][0], ah[mt][1], ah[mt][2], ah[mt][3], ab);
                ldsm4(al[mt][0], al[mt][1], al[mt][2], al[mt][3], ab + 128);
            }
            uint2 bhv = w2f[((nt * 4 + kt) * 2 + 0) * 32 + lane];
            uint2 blv = w2f[((nt * 4 + kt) * 2 + 1) * 32 + lane];
            u32 bh[2] = { bhv.x, bhv.y };
            u32 bl[2] = { blv.x, blv.y };
#pragma unroll
            for (int mt = 0; mt < 3; mt++) {
                mmabf(Dv[mt], ah[mt], bh);
                mmabf(Dv[mt], al[mt], bh);
                mmabf(Dv[mt], ah[mt], bl);
            }
        }
        // scatter transposed with bias: mc -> sMt[v*220 + (mc%27)*8 + mc/27]
        int mcA = nt * 8 + 2 * tc;
        int mcB = mcA + 1;
        float bA = b2[mcA], bB = b2[mcB];
        int iA = (mcA % 27) * 8 + mcA / 27;
        int iB = (mcB % 27) * 8 + mcB / 27;
#pragma unroll
        for (int mt = 0; mt < 3; mt++) {
            int v0 = mt * 16 + tr;
            sMt[v0 * 220 + iA]       = Dv[mt][0] + bA;
            sMt[v0 * 220 + iB]       = Dv[mt][1] + bB;
            sMt[(v0 + 8) * 220 + iA] = Dv[mt][2] + bA;
            sMt[(v0 + 8) * 220 + iB] = Dv[mt][3] + bB;
        }
    }
    __syncthreads();

    // ---- B: softmax over n for each (v,g) ----
    for (int s = tid; s < 384; s += 256) {
        int v = s >> 3, g = s & 7;
        float* p = &sMt[v * 220 + g];
        float mx = p[0];
#pragma unroll
        for (int n = 1; n < 27; n++) mx = fmaxf(mx, p[n * 8]);
        float e[27], ssum = 0.0f;
#pragma unroll
        for (int n = 0; n < 27; n++) { e[n] = __expf(p[n * 8] - mx); ssum += e[n]; }
        float inv = 1.0f / ssum;
#pragma unroll
        for (int n = 0; n < 27; n++) p[n * 8] = e[n] * inv;
    }
    __syncthreads();

    // ---- C: apply. slot = (v, cq) -> channels cq, cq+8, cq+16, cq+24 ----
    int zd[3], zh[3];
#pragma unroll
    for (int t = 0; t < 3; t++) {
        zd[t] = min(max(d + t - 1, 0), 47);
        zh[t] = min(max(hB + t - 1, 0), 47);
    }

#pragma unroll 1
    for (int p = tid; p < 384; p += 256) {
        int v = p % 48, cq = p / 48;
        int zw[3];
        zw[0] = max(v - 1, 0); zw[1] = v; zw[2] = min(v + 1, 47);
        const float* mB = &sMt[v * 220];

        u64 acc[4][4];
#pragma unroll
        for (int ch = 0; ch < 4; ch++)
#pragma unroll
            for (int q = 0; q < 4; q++) acc[ch][q] = 0ull;

#pragma unroll
        for (int dz = 0; dz < 3; dz++) {
#pragma unroll
            for (int dy = 0; dy < 3; dy++) {
                long rbase = ((long)zd[dz] * 48 + zh[dy]) * 48;
                float tv[4][3];
#pragma unroll
                for (int ch = 0; ch < 4; ch++) {
                    const float* xc = x + (long)(cq + 8 * ch) * VOX + rbase;
#pragma unroll
                    for (int dx = 0; dx < 3; dx++) tv[ch][dx] = xc[zw[dx]];
                }
#pragma unroll
                for (int dx = 0; dx < 3; dx++) {
                    int n = (dz * 3 + dy) * 3 + dx;
                    const ulonglong2* mp = (const ulonglong2*)(mB + n * 8);
                    ulonglong2 mLo = mp[0];
                    ulonglong2 mHi = mp[1];
#pragma unroll
                    for (int ch = 0; ch < 4; ch++) {
                        u64 T = dup2(tv[ch][dx]);
                        fma2(acc[ch][0], mLo.x, T);
                        fma2(acc[ch][1], mLo.y, T);
                        fma2(acc[ch][2], mHi.x, T);
                        fma2(acc[ch][3], mHi.y, T);
                    }
                }
            }
        }

#pragma unroll
        for (int ch = 0; ch < 4; ch++) {
            int c = cq + 8 * ch;
#pragma unroll
            for (int i = 0; i < 2; i++)
#pragma unroll
                for (int j = 0; j < 2; j++) {
                    int q = i * 2 + j;
                    long ob = (((long)c * 96 + 2 * d + i) * 96 + 2 * hB + j) * 96 + 2 * v;
                    *(float2*)&out[ob] = *(float2*)&acc[ch][q];
                }
        }
    }
}

// ---------------------------------------------------------------------------
extern "C" void kernel_launch(void* const* d_in, const int* in_sizes, int n_in,
                              void* d_out, int out_size)
{
    const float* x    = (const float*)d_in[0];
    const float* feat = (const float*)d_in[1];
    const float* w1   = (const float*)d_in[2];
    const float* b1   = (const float*)d_in[3];
    const float* w2   = (const float*)d_in[4];
    const float* b2   = (const float*)d_in[5];
    float* out = (float*)d_out;

    const int smem1 = 900 * 144 + 576 * 144;       // 212544 B
    const int smem2 = 10560 * 4 + 3264 * 4;        // 55296 B
    cudaFuncSetAttribute(k_conv1, cudaFuncAttributeMaxDynamicSharedMemorySize, smem1);
    cudaFuncSetAttribute(k_mask_apply, cudaFuncAttributeMaxDynamicSharedMemorySize, smem2);

    k_prep<<<271, 256>>>(w1, w2);
    k_conv1<<<dim3(12, 48), 256, smem1>>>(feat, b1);
    k_mask_apply<<<dim3(48, 48), 256, smem2>>>(x, b2, out);
}

// round 9
// speedup vs baseline: 3.2068x; 1.0192x over previous
#include <cuda_runtime.h>
#include <cuda_bf16.h>
#include <cstdint>

#define VOX (48*48*48)
typedef unsigned long long u64;
typedef unsigned int u32;

// Device globals (weights only; h never leaves the block now)
__device__ __nv_bfloat16 g_w1a[3 * 9 * 64 * 72];  // conv1 A: [dz][tap9][oc64][hi32|lo32|pad]
__device__ u32 g_w2frag[13824];                   // conv2 B frags: [nt27][kt4][pass2][lane32][b0,b1]

__device__ __forceinline__ void fma2(u64& acc, u64 a, u64 b) {
    asm("fma.rn.f32x2 %0, %1, %2, %0;" : "+l"(acc) : "l"(a), "l"(b));
}
__device__ __forceinline__ u64 dup2(float v) {
    u64 r; asm("mov.b64 %0, {%1, %1};" : "=l"(r) : "f"(v)); return r;
}
__device__ __forceinline__ u32 cvt2bf(float a, float b) {
    u32 r; asm("cvt.rn.bf16x2.f32 %0, %1, %2;" : "=r"(r) : "f"(b), "f"(a)); return r;
}
__device__ __forceinline__ void ldsm4(u32& r0, u32& r1, u32& r2, u32& r3, u32 a) {
    asm volatile("ldmatrix.sync.aligned.m8n8.x4.shared.b16 {%0,%1,%2,%3}, [%4];"
                 : "=r"(r0), "=r"(r1), "=r"(r2), "=r"(r3) : "r"(a));
}
__device__ __forceinline__ void mmabf(float* d, const u32* a, const u32* b) {
    asm volatile(
        "mma.sync.aligned.m16n8k16.row.col.f32.bf16.bf16.f32 "
        "{%0,%1,%2,%3}, {%4,%5,%6,%7}, {%8,%9}, {%0,%1,%2,%3};"
        : "+f"(d[0]), "+f"(d[1]), "+f"(d[2]), "+f"(d[3])
        : "r"(a[0]), "r"(a[1]), "r"(a[2]), "r"(a[3]), "r"(b[0]), "r"(b[1]));
}

// ---------------------------------------------------------------------------
// Prep (unchanged from R8)
// ---------------------------------------------------------------------------
extern "C" __global__ void k_prep(const float* __restrict__ w1,
                                  const float* __restrict__ w2)
{
    int id = blockIdx.x * 256 + threadIdx.x;
    if (id < 13824) {
        int breg  = id & 1;
        int entry = id >> 1;
        int lane  = entry & 31;
        int q     = entry >> 5;
        int pass  = q & 1;
        int kt    = (q >> 1) & 3;
        int nt    = q >> 3;
        int tr = lane >> 2, tc = lane & 3;
        int mc = nt * 8 + tr;
        int k0 = kt * 16 + 2 * tc + breg * 8;
        float v0 = w2[mc * 64 + k0];
        float v1 = w2[mc * 64 + k0 + 1];
        __nv_bfloat16 h0 = __float2bfloat16(v0);
        __nv_bfloat16 h1 = __float2bfloat16(v1);
        u32 out;
        if (pass == 0) {
            out = ((u32)__bfloat16_as_ushort(h1) << 16) | (u32)__bfloat16_as_ushort(h0);
        } else {
            __nv_bfloat16 l0 = __float2bfloat16(v0 - __bfloat162float(h0));
            __nv_bfloat16 l1 = __float2bfloat16(v1 - __bfloat162float(h1));
            out = ((u32)__bfloat16_as_ushort(l1) << 16) | (u32)__bfloat16_as_ushort(l0);
        }
        g_w2frag[id] = out;
    } else if (id < 13824 + 55296) {
        int q = id - 13824;
        int ci = q & 31;
        int r  = q >> 5;
        int oc = r & 63;
        int r2 = r >> 6;
        int tap = r2 % 9, dz = r2 / 9;
        float v = w1[oc * 864 + ci * 27 + dz * 9 + tap];
        __nv_bfloat16 hi = __float2bfloat16(v);
        __nv_bfloat16 lo = __float2bfloat16(v - __bfloat162float(hi));
        int base = ((dz * 9 + tap) * 64 + oc) * 72;
        g_w1a[base + ci]      = hi;
        g_w1a[base + 32 + ci] = lo;
    }
}

// ---------------------------------------------------------------------------
// Fused kernel: conv1 (mma bf16 hi/lo) -> silu -> conv2 GEMM (mma) -> softmax
// -> apply, all per block (depth d, 4 h-rows). grid (12,48), 256 threads.
// smem phases (212544 B total):
//   phase1 conv1:  sF [0,129600) 900x144B ; sA [129600,212544) 576x144B
//   phase2 (after conv1): sS fp32 h scratch [52224,104448) pitch 68
//                         sHu bf16-split    [0,52224)  192 rows x 272B
//   phase3 per hpass (2 h-rows): sMt [104448,188928) 96x220 floats
// ---------------------------------------------------------------------------
extern "C" __global__ void __launch_bounds__(256, 1) k_fused(
    const float* __restrict__ feat, const float* __restrict__ b1,
    const float* __restrict__ x,    const float* __restrict__ b2,
    float* __restrict__ out)
{
    extern __shared__ char sm[];
    char* sF = sm;
    char* sA = sm + 900 * 144;
    const u32 sFb = (u32)__cvta_generic_to_shared(sF);
    const u32 sAb = (u32)__cvta_generic_to_shared(sA);

    const int tid  = threadIdx.x;
    const int lane = tid & 31;
    const int warp = tid >> 5;
    const int mw = warp & 1;
    const int nw = warp >> 1;
    const int grp = lane >> 3, r8 = lane & 7;
    const int tr = lane >> 2, tc = lane & 3;
    const int h0 = blockIdx.x * 4;
    const int d  = blockIdx.y;

    // ======================= Phase 1: conv1 =======================
    for (int t = tid; t < 14400; t += 256) {
        int wp = t % 50;
        int q  = t / 50;
        int hh = q % 6;
        int q2 = q / 6;
        int dzi = q2 % 3;
        int ci2 = q2 / 3;
        int z = min(max(d - 1 + dzi, 0), 47);
        int y = min(max(h0 - 1 + hh, 0), 47);
        int w = min(max(wp - 1, 0), 47);
        long gi = (long)(2 * ci2) * VOX + (z * 48 + y) * 48 + w;
        float f0 = feat[gi];
        float f1 = feat[gi + VOX];
        u32 hp = cvt2bf(f0, f1);
        float r0 = f0 - __uint_as_float(hp << 16);
        float r1 = f1 - __uint_as_float(hp & 0xffff0000u);
        u32 lp = cvt2bf(r0, r1);
        int row = (dzi * 6 + hh) * 50 + wp;
        *(u32*)(sF + row * 144 + ci2 * 4)      = hp;
        *(u32*)(sF + row * 144 + 64 + ci2 * 4) = lp;
    }

    float D[2][6][4];
#pragma unroll
    for (int mi = 0; mi < 2; mi++)
#pragma unroll
        for (int j = 0; j < 6; j++)
#pragma unroll
            for (int c = 0; c < 4; c++) D[mi][j][c] = 0.0f;

#pragma unroll 1
    for (int dz = 0; dz < 3; dz++) {
        __syncthreads();
        {
            const uint4* src = (const uint4*)(g_w1a + (size_t)dz * 9 * 64 * 72);
            uint4* dst = (uint4*)sA;
            for (int t = tid; t < 5184; t += 256) dst[t] = src[t];
        }
        __syncthreads();

#pragma unroll 1
        for (int dy = 0; dy < 3; dy++) {
#pragma unroll 1
            for (int dx = 0; dx < 3; dx++) {
                const u32 tapBase = sAb + (dy * 3 + dx) * 64 * 144;
                const int rowBase = (dz * 6 + nw + dy) * 50 + dx;
#pragma unroll
                for (int kc = 0; kc < 2; kc++) {
                    u32 a_hi[2][4], a_lo[2][4];
#pragma unroll
                    for (int mi = 0; mi < 2; mi++) {
                        u32 ab = tapBase
                               + (mw * 32 + mi * 16 + (grp & 1) * 8 + r8) * 144
                               + (grp >> 1) * 16 + kc * 32;
                        ldsm4(a_hi[mi][0], a_hi[mi][1], a_hi[mi][2], a_hi[mi][3], ab);
                        ldsm4(a_lo[mi][0], a_lo[mi][1], a_lo[mi][2], a_lo[mi][3], ab + 64);
                    }
                    u32 bh[6][2];
#pragma unroll
                    for (int jj = 0; jj < 3; jj++) {
                        int rowI = rowBase + jj * 16 + (grp >> 1) * 8 + r8;
                        u32 bb = sFb + rowI * 144 + (grp & 1) * 16 + kc * 32;
                        ldsm4(bh[2 * jj][0], bh[2 * jj][1],
                              bh[2 * jj + 1][0], bh[2 * jj + 1][1], bb);
                    }
#pragma unroll
                    for (int mi = 0; mi < 2; mi++)
#pragma unroll
                        for (int j = 0; j < 6; j++) {
                            mmabf(D[mi][j], a_hi[mi], bh[j]);
                            mmabf(D[mi][j], a_lo[mi], bh[j]);
                        }
                    u32 bl[6][2];
#pragma unroll
                    for (int jj = 0; jj < 3; jj++) {
                        int rowI = rowBase + jj * 16 + (grp >> 1) * 8 + r8;
                        u32 bb = sFb + rowI * 144 + 64 + (grp & 1) * 16 + kc * 32;
                        ldsm4(bl[2 * jj][0], bl[2 * jj][1],
                              bl[2 * jj + 1][0], bl[2 * jj + 1][1], bb);
                    }
#pragma unroll
                    for (int mi = 0; mi < 2; mi++)
#pragma unroll
                        for (int j = 0; j < 6; j++)
                            mmabf(D[mi][j], a_hi[mi], bl[j]);
                }
            }
        }
    }
    __syncthreads();   // sF/sA dead after this

    // ======================= Phase 2: silu -> scratch -> bf16 split ========
    float* sS  = (float*)(sm + 52224);   // h fp32, [vl*68 + oc], pitch 68
    u32*   sHu = (u32*)sm;               // [vl*68 + kp(hi) | 32+kp(lo)], 272B rows
    const u32 sHb = (u32)__cvta_generic_to_shared(sHu);
    {
#pragma unroll
        for (int mi = 0; mi < 2; mi++) {
            int oc0 = mw * 32 + mi * 16 + tr;
            int oc1 = oc0 + 8;
            float bias0 = b1[oc0], bias1 = b1[oc1];
#pragma unroll
            for (int j = 0; j < 6; j++) {
                int vl = nw * 48 + j * 8 + 2 * tc;
                float v0 = D[mi][j][0] + bias0;
                float v1 = D[mi][j][1] + bias0;
                float v2 = D[mi][j][2] + bias1;
                float v3 = D[mi][j][3] + bias1;
                sS[vl * 68 + oc0]       = v0 / (1.0f + __expf(-v0));
                sS[(vl + 1) * 68 + oc0] = v1 / (1.0f + __expf(-v1));
                sS[vl * 68 + oc1]       = v2 / (1.0f + __expf(-v2));
                sS[(vl + 1) * 68 + oc1] = v3 / (1.0f + __expf(-v3));
            }
        }
    }
    __syncthreads();

    for (int t = tid; t < 6144; t += 256) {        // 192 rows x 32 pairs
        int vl = t >> 5, kp = t & 31;
        float2 f = *(const float2*)&sS[vl * 68 + 2 * kp];
        u32 hp = cvt2bf(f.x, f.y);
        float r0 = f.x - __uint_as_float(hp << 16);
        float r1 = f.y - __uint_as_float(hp & 0xffff0000u);
        u32 lp = cvt2bf(r0, r1);
        sHu[vl * 68 + kp]      = hp;
        sHu[vl * 68 + 32 + kp] = lp;
    }
    __syncthreads();

    // ======================= Phase 3: masks + apply, per 2 h-rows ==========
    float* sMt = (float*)(sm + 104448);  // 96 x 220 floats
    const uint2* w2f = (const uint2*)g_w2frag;

    int zd[3];
#pragma unroll
    for (int t = 0; t < 3; t++) zd[t] = min(max(d + t - 1, 0), 47);

#pragma unroll 1
    for (int hpass = 0; hpass < 2; hpass++) {
        // --- conv2 GEMM: M=96 voxels (6 m16 tiles), N=216, K=64, bf16 hi/lo ---
#pragma unroll 1
        for (int nt = warp; nt < 27; nt += 8) {
            float Dv[6][4];
#pragma unroll
            for (int mt = 0; mt < 6; mt++)
#pragma unroll
                for (int c = 0; c < 4; c++) Dv[mt][c] = 0.0f;

#pragma unroll
            for (int kt = 0; kt < 4; kt++) {
                u32 ah[6][4], al[6][4];
#pragma unroll
                for (int mt = 0; mt < 6; mt++) {
                    u32 ab = sHb + (hpass * 96 + mt * 16 + (grp & 1) * 8 + r8) * 272
                           + (grp >> 1) * 16 + kt * 32;
                    ldsm4(ah[mt][0], ah[mt][1], ah[mt][2], ah[mt][3], ab);
                    ldsm4(al[mt][0], al[mt][1], al[mt][2], al[mt][3], ab + 128);
                }
                uint2 bhv = w2f[((nt * 4 + kt) * 2 + 0) * 32 + lane];
                uint2 blv = w2f[((nt * 4 + kt) * 2 + 1) * 32 + lane];
                u32 bh[2] = { bhv.x, bhv.y };
                u32 bl[2] = { blv.x, blv.y };
#pragma unroll
                for (int mt = 0; mt < 6; mt++) {
                    mmabf(Dv[mt], ah[mt], bh);
                    mmabf(Dv[mt], al[mt], bh);
                    mmabf(Dv[mt], ah[mt], bl);
                }
            }
            int mcA = nt * 8 + 2 * tc;
            int mcB = mcA + 1;
            float bA = b2[mcA], bB = b2[mcB];
            int iA = (mcA % 27) * 8 + mcA / 27;
            int iB = (mcB % 27) * 8 + mcB / 27;
#pragma unroll
            for (int mt = 0; mt < 6; mt++) {
                int v0 = mt * 16 + tr;
                sMt[v0 * 220 + iA]       = Dv[mt][0] + bA;
                sMt[v0 * 220 + iB]       = Dv[mt][1] + bB;
                sMt[(v0 + 8) * 220 + iA] = Dv[mt][2] + bA;
                sMt[(v0 + 8) * 220 + iB] = Dv[mt][3] + bB;
            }
        }
        __syncthreads();

        // --- softmax over n per (vl, g) ---
        for (int s = tid; s < 768; s += 256) {
            int vl = s >> 3, g = s & 7;
            float* p = &sMt[vl * 220 + g];
            float mx = p[0];
#pragma unroll
            for (int n = 1; n < 27; n++) mx = fmaxf(mx, p[n * 8]);
            float e[27], ssum = 0.0f;
#pragma unroll
            for (int n = 0; n < 27; n++) { e[n] = __expf(p[n * 8] - mx); ssum += e[n]; }
            float inv = 1.0f / ssum;
#pragma unroll
            for (int n = 0; n < 27; n++) p[n * 8] = e[n] * inv;
        }
        __syncthreads();

        // --- apply: slot = (vl 0..95, cq 0..7) -> channels cq+8*{0..3} ---
#pragma unroll 1
        for (int p = tid; p < 768; p += 256) {
            int vl = p % 96, cq = p / 96;
            int hr = hpass * 2 + (vl >= 48);
            int v  = vl - (vl >= 48 ? 48 : 0);
            int hB = h0 + hr;
            int zh[3], zw[3];
#pragma unroll
            for (int t = 0; t < 3; t++) zh[t] = min(max(hB + t - 1, 0), 47);
            zw[0] = max(v - 1, 0); zw[1] = v; zw[2] = min(v + 1, 47);
            const float* mB = &sMt[vl * 220];

            u64 acc[4][4];
#pragma unroll
            for (int ch = 0; ch < 4; ch++)
#pragma unroll
                for (int q = 0; q < 4; q++) acc[ch][q] = 0ull;

#pragma unroll
            for (int dz = 0; dz < 3; dz++) {
#pragma unroll
                for (int dy = 0; dy < 3; dy++) {
                    long rbase = ((long)zd[dz] * 48 + zh[dy]) * 48;
                    float tv[4][3];
#pragma unroll
                    for (int ch = 0; ch < 4; ch++) {
                        const float* xc = x + (long)(cq + 8 * ch) * VOX + rbase;
#pragma unroll
                        for (int dx = 0; dx < 3; dx++) tv[ch][dx] = xc[zw[dx]];
                    }
#pragma unroll
                    for (int dx = 0; dx < 3; dx++) {
                        int n = (dz * 3 + dy) * 3 + dx;
                        const ulonglong2* mp = (const ulonglong2*)(mB + n * 8);
                        ulonglong2 mLo = mp[0];
                        ulonglong2 mHi = mp[1];
#pragma unroll
                        for (int ch = 0; ch < 4; ch++) {
                            u64 T = dup2(tv[ch][dx]);
                            fma2(acc[ch][0], mLo.x, T);
                            fma2(acc[ch][1], mLo.y, T);
                            fma2(acc[ch][2], mHi.x, T);
                            fma2(acc[ch][3], mHi.y, T);
                        }
                    }
                }
            }

#pragma unroll
            for (int ch = 0; ch < 4; ch++) {
                int c = cq + 8 * ch;
#pragma unroll
                for (int i = 0; i < 2; i++)
#pragma unroll
                    for (int j = 0; j < 2; j++) {
                        int q = i * 2 + j;
                        long ob = (((long)c * 96 + 2 * d + i) * 96 + 2 * hB + j) * 96 + 2 * v;
                        *(float2*)&out[ob] = *(float2*)&acc[ch][q];
                    }
            }
        }
        __syncthreads();
    }
}

// ---------------------------------------------------------------------------
extern "C" void kernel_launch(void* const* d_in, const int* in_sizes, int n_in,
                              void* d_out, int out_size)
{
    const float* x    = (const float*)d_in[0];
    const float* feat = (const float*)d_in[1];
    const float* w1   = (const float*)d_in[2];
    const float* b1   = (const float*)d_in[3];
    const float* w2   = (const float*)d_in[4];
    const float* b2   = (const float*)d_in[5];
    float* out = (float*)d_out;

    const int smemF = 900 * 144 + 576 * 144;  // 212544 B
    cudaFuncSetAttribute(k_fused, cudaFuncAttributeMaxDynamicSharedMemorySize, smemF);

    k_prep<<<271, 256>>>(w1, w2);
    k_fused<<<dim3(12, 48), 256, smemF>>>(feat, b1, x, b2, out);
}

// round 10
// speedup vs baseline: 3.7121x; 1.1575x over previous
#include <cuda_runtime.h>
#include <cuda_bf16.h>
#include <cstdint>

#define VOX (48*48*48)
typedef unsigned long long u64;
typedef unsigned int u32;

// Device globals (weights only)
__device__ __nv_bfloat16 g_w1a[3 * 9 * 64 * 72];  // conv1 A: [dz][tap9][oc64][hi32|lo32|pad]
__device__ u32 g_w2frag[13824];                   // conv2 B frags: [nt27][kt4][pass2][lane32][b0,b1]

__device__ __forceinline__ void fma2(u64& acc, u64 a, u64 b) {
    asm("fma.rn.f32x2 %0, %1, %2, %0;" : "+l"(acc) : "l"(a), "l"(b));
}
__device__ __forceinline__ u64 dup2(float v) {
    u64 r; asm("mov.b64 %0, {%1, %1};" : "=l"(r) : "f"(v)); return r;
}
__device__ __forceinline__ u32 cvt2bf(float a, float b) {
    u32 r; asm("cvt.rn.bf16x2.f32 %0, %1, %2;" : "=r"(r) : "f"(b), "f"(a)); return r;
}
__device__ __forceinline__ void ldsm4(u32& r0, u32& r1, u32& r2, u32& r3, u32 a) {
    asm volatile("ldmatrix.sync.aligned.m8n8.x4.shared.b16 {%0,%1,%2,%3}, [%4];"
                 : "=r"(r0), "=r"(r1), "=r"(r2), "=r"(r3) : "r"(a));
}
__device__ __forceinline__ void mmabf(float* d, const u32* a, const u32* b) {
    asm volatile(
        "mma.sync.aligned.m16n8k16.row.col.f32.bf16.bf16.f32 "
        "{%0,%1,%2,%3}, {%4,%5,%6,%7}, {%8,%9}, {%0,%1,%2,%3};"
        : "+f"(d[0]), "+f"(d[1]), "+f"(d[2]), "+f"(d[3])
        : "r"(a[0]), "r"(a[1]), "r"(a[2]), "r"(a[3]), "r"(b[0]), "r"(b[1]));
}

// ---------------------------------------------------------------------------
// Prep (unchanged from R8)
// ---------------------------------------------------------------------------
extern "C" __global__ void k_prep(const float* __restrict__ w1,
                                  const float* __restrict__ w2)
{
    int id = blockIdx.x * 256 + threadIdx.x;
    if (id < 13824) {
        int breg  = id & 1;
        int entry = id >> 1;
        int lane  = entry & 31;
        int q     = entry >> 5;
        int pass  = q & 1;
        int kt    = (q >> 1) & 3;
        int nt    = q >> 3;
        int tr = lane >> 2, tc = lane & 3;
        int mc = nt * 8 + tr;
        int k0 = kt * 16 + 2 * tc + breg * 8;
        float v0 = w2[mc * 64 + k0];
        float v1 = w2[mc * 64 + k0 + 1];
        __nv_bfloat16 h0 = __float2bfloat16(v0);
        __nv_bfloat16 h1 = __float2bfloat16(v1);
        u32 out;
        if (pass == 0) {
            out = ((u32)__bfloat16_as_ushort(h1) << 16) | (u32)__bfloat16_as_ushort(h0);
        } else {
            __nv_bfloat16 l0 = __float2bfloat16(v0 - __bfloat162float(h0));
            __nv_bfloat16 l1 = __float2bfloat16(v1 - __bfloat162float(h1));
            out = ((u32)__bfloat16_as_ushort(l1) << 16) | (u32)__bfloat16_as_ushort(l0);
        }
        g_w2frag[id] = out;
    } else if (id < 13824 + 55296) {
        int q = id - 13824;
        int ci = q & 31;
        int r  = q >> 5;
        int oc = r & 63;
        int r2 = r >> 6;
        int tap = r2 % 9, dz = r2 / 9;
        float v = w1[oc * 864 + ci * 27 + dz * 9 + tap];
        __nv_bfloat16 hi = __float2bfloat16(v);
        __nv_bfloat16 lo = __float2bfloat16(v - __bfloat162float(hi));
        int base = ((dz * 9 + tap) * 64 + oc) * 72;
        g_w1a[base + ci]      = hi;
        g_w1a[base + 32 + ci] = lo;
    }
}

// ---------------------------------------------------------------------------
// Fused kernel, 512 threads (16 warps), grid (12,48).
// conv1 warp grid 4m x 4n: mw = warp&3 (one m16 oc tile), nw = warp>>2 (h row).
// Phases/smem identical to R9 otherwise.
// ---------------------------------------------------------------------------
extern "C" __global__ void __launch_bounds__(512, 1) k_fused(
    const float* __restrict__ feat, const float* __restrict__ b1,
    const float* __restrict__ x,    const float* __restrict__ b2,
    float* __restrict__ out)
{
    extern __shared__ char sm[];
    char* sF = sm;
    char* sA = sm + 900 * 144;
    const u32 sFb = (u32)__cvta_generic_to_shared(sF);
    const u32 sAb = (u32)__cvta_generic_to_shared(sA);

    const int tid  = threadIdx.x;
    const int lane = tid & 31;
    const int warp = tid >> 5;
    const int mw = warp & 3;          // m16 oc tile (0..3)
    const int nw = warp >> 2;         // h row (0..3)
    const int grp = lane >> 3, r8 = lane & 7;
    const int tr = lane >> 2, tc = lane & 3;
    const int h0 = blockIdx.x * 4;
    const int d  = blockIdx.y;

    // ======================= Phase 1: conv1 =======================
    for (int t = tid; t < 14400; t += 512) {
        int wp = t % 50;
        int q  = t / 50;
        int hh = q % 6;
        int q2 = q / 6;
        int dzi = q2 % 3;
        int ci2 = q2 / 3;
        int z = min(max(d - 1 + dzi, 0), 47);
        int y = min(max(h0 - 1 + hh, 0), 47);
        int w = min(max(wp - 1, 0), 47);
        long gi = (long)(2 * ci2) * VOX + (z * 48 + y) * 48 + w;
        float f0 = feat[gi];
        float f1 = feat[gi + VOX];
        u32 hp = cvt2bf(f0, f1);
        float r0 = f0 - __uint_as_float(hp << 16);
        float r1 = f1 - __uint_as_float(hp & 0xffff0000u);
        u32 lp = cvt2bf(r0, r1);
        int row = (dzi * 6 + hh) * 50 + wp;
        *(u32*)(sF + row * 144 + ci2 * 4)      = hp;
        *(u32*)(sF + row * 144 + 64 + ci2 * 4) = lp;
    }

    float D[6][4];
#pragma unroll
    for (int j = 0; j < 6; j++)
#pragma unroll
        for (int c = 0; c < 4; c++) D[j][c] = 0.0f;

#pragma unroll 1
    for (int dz = 0; dz < 3; dz++) {
        __syncthreads();
        {
            const uint4* src = (const uint4*)(g_w1a + (size_t)dz * 9 * 64 * 72);
            uint4* dst = (uint4*)sA;
            for (int t = tid; t < 5184; t += 512) dst[t] = src[t];
        }
        __syncthreads();

#pragma unroll 1
        for (int dy = 0; dy < 3; dy++) {
#pragma unroll 1
            for (int dx = 0; dx < 3; dx++) {
                const u32 tapBase = sAb + (dy * 3 + dx) * 64 * 144;
                const int rowBase = (dz * 6 + nw + dy) * 50 + dx;
#pragma unroll
                for (int kc = 0; kc < 2; kc++) {
                    u32 a_hi[4], a_lo[4];
                    {
                        u32 ab = tapBase
                               + (mw * 16 + (grp & 1) * 8 + r8) * 144
                               + (grp >> 1) * 16 + kc * 32;
                        ldsm4(a_hi[0], a_hi[1], a_hi[2], a_hi[3], ab);
                        ldsm4(a_lo[0], a_lo[1], a_lo[2], a_lo[3], ab + 64);
                    }
                    u32 bh[6][2];
#pragma unroll
                    for (int jj = 0; jj < 3; jj++) {
                        int rowI = rowBase + jj * 16 + (grp >> 1) * 8 + r8;
                        u32 bb = sFb + rowI * 144 + (grp & 1) * 16 + kc * 32;
                        ldsm4(bh[2 * jj][0], bh[2 * jj][1],
                              bh[2 * jj + 1][0], bh[2 * jj + 1][1], bb);
                    }
#pragma unroll
                    for (int j = 0; j < 6; j++) {
                        mmabf(D[j], a_hi, bh[j]);
                        mmabf(D[j], a_lo, bh[j]);
                    }
                    u32 bl[6][2];
#pragma unroll
                    for (int jj = 0; jj < 3; jj++) {
                        int rowI = rowBase + jj * 16 + (grp >> 1) * 8 + r8;
                        u32 bb = sFb + rowI * 144 + 64 + (grp & 1) * 16 + kc * 32;
                        ldsm4(bl[2 * jj][0], bl[2 * jj][1],
                              bl[2 * jj + 1][0], bl[2 * jj + 1][1], bb);
                    }
#pragma unroll
                    for (int j = 0; j < 6; j++)
                        mmabf(D[j], a_hi, bl[j]);
                }
            }
        }
    }
    __syncthreads();   // sF/sA dead after this

    // ======================= Phase 2: silu -> scratch -> bf16 split ========
    float* sS  = (float*)(sm + 52224);   // h fp32, [vl*68 + oc], pitch 68
    u32*   sHu = (u32*)sm;               // [vl*68 + kp(hi) | 32+kp(lo)], 272B rows
    const u32 sHb = (u32)__cvta_generic_to_shared(sHu);
    {
        int oc0 = mw * 16 + tr;
        int oc1 = oc0 + 8;
        float bias0 = b1[oc0], bias1 = b1[oc1];
#pragma unroll
        for (int j = 0; j < 6; j++) {
            int vl = nw * 48 + j * 8 + 2 * tc;
            float v0 = D[j][0] + bias0;
            float v1 = D[j][1] + bias0;
            float v2 = D[j][2] + bias1;
            float v3 = D[j][3] + bias1;
            sS[vl * 68 + oc0]       = v0 / (1.0f + __expf(-v0));
            sS[(vl + 1) * 68 + oc0] = v1 / (1.0f + __expf(-v1));
            sS[vl * 68 + oc1]       = v2 / (1.0f + __expf(-v2));
            sS[(vl + 1) * 68 + oc1] = v3 / (1.0f + __expf(-v3));
        }
    }
    __syncthreads();

    for (int t = tid; t < 6144; t += 512) {        // 192 rows x 32 pairs
        int vl = t >> 5, kp = t & 31;
        float2 f = *(const float2*)&sS[vl * 68 + 2 * kp];
        u32 hp = cvt2bf(f.x, f.y);
        float r0 = f.x - __uint_as_float(hp << 16);
        float r1 = f.y - __uint_as_float(hp & 0xffff0000u);
        u32 lp = cvt2bf(r0, r1);
        sHu[vl * 68 + kp]      = hp;
        sHu[vl * 68 + 32 + kp] = lp;
    }
    __syncthreads();

    // ======================= Phase 3: masks + apply, per 2 h-rows ==========
    float* sMt = (float*)(sm + 104448);  // 96 x 220 floats
    const uint2* w2f = (const uint2*)g_w2frag;

    int zd[3];
#pragma unroll
    for (int t = 0; t < 3; t++) zd[t] = min(max(d + t - 1, 0), 47);

#pragma unroll 1
    for (int hpass = 0; hpass < 2; hpass++) {
        // --- conv2 GEMM: M=96 voxels (6 m16 tiles), N=216, K=64 ---
#pragma unroll 1
        for (int nt = warp; nt < 27; nt += 16) {
            float Dv[6][4];
#pragma unroll
            for (int mt = 0; mt < 6; mt++)
#pragma unroll
                for (int c = 0; c < 4; c++) Dv[mt][c] = 0.0f;

#pragma unroll
            for (int kt = 0; kt < 4; kt++) {
                uint2 bhv = w2f[((nt * 4 + kt) * 2 + 0) * 32 + lane];
                uint2 blv = w2f[((nt * 4 + kt) * 2 + 1) * 32 + lane];
                u32 bh[2] = { bhv.x, bhv.y };
                u32 bl[2] = { blv.x, blv.y };
#pragma unroll
                for (int mt = 0; mt < 6; mt++) {
                    u32 ah[4], al[4];
                    u32 ab = sHb + (hpass * 96 + mt * 16 + (grp & 1) * 8 + r8) * 272
                           + (grp >> 1) * 16 + kt * 32;
                    ldsm4(ah[0], ah[1], ah[2], ah[3], ab);
                    ldsm4(al[0], al[1], al[2], al[3], ab + 128);
                    mmabf(Dv[mt], ah, bh);
                    mmabf(Dv[mt], al, bh);
                    mmabf(Dv[mt], ah, bl);
                }
            }
            int mcA = nt * 8 + 2 * tc;
            int mcB = mcA + 1;
            float bA = b2[mcA], bB = b2[mcB];
            int iA = (mcA % 27) * 8 + mcA / 27;
            int iB = (mcB % 27) * 8 + mcB / 27;
#pragma unroll
            for (int mt = 0; mt < 6; mt++) {
                int v0 = mt * 16 + tr;
                sMt[v0 * 220 + iA]       = Dv[mt][0] + bA;
                sMt[v0 * 220 + iB]       = Dv[mt][1] + bB;
                sMt[(v0 + 8) * 220 + iA] = Dv[mt][2] + bA;
                sMt[(v0 + 8) * 220 + iB] = Dv[mt][3] + bB;
            }
        }
        __syncthreads();

        // --- softmax over n per (vl, g) ---
        for (int s = tid; s < 768; s += 512) {
            int vl = s >> 3, g = s & 7;
            float* p = &sMt[vl * 220 + g];
            float mx = p[0];
#pragma unroll
            for (int n = 1; n < 27; n++) mx = fmaxf(mx, p[n * 8]);
            float e[27], ssum = 0.0f;
#pragma unroll
            for (int n = 0; n < 27; n++) { e[n] = __expf(p[n * 8] - mx); ssum += e[n]; }
            float inv = 1.0f / ssum;
#pragma unroll
            for (int n = 0; n < 27; n++) p[n * 8] = e[n] * inv;
        }
        __syncthreads();

        // --- apply: slot = (vl 0..95, cq 0..7) -> channels cq+8*{0..3} ---
#pragma unroll 1
        for (int p = tid; p < 768; p += 512) {
            int vl = p % 96, cq = p / 96;
            int hr = hpass * 2 + (vl >= 48);
            int v  = vl - (vl >= 48 ? 48 : 0);
            int hB = h0 + hr;
            int zh[3], zw[3];
#pragma unroll
            for (int t = 0; t < 3; t++) zh[t] = min(max(hB + t - 1, 0), 47);
            zw[0] = max(v - 1, 0); zw[1] = v; zw[2] = min(v + 1, 47);
            const float* mB = &sMt[vl * 220];

            u64 acc[4][4];
#pragma unroll
            for (int ch = 0; ch < 4; ch++)
#pragma unroll
                for (int q = 0; q < 4; q++) acc[ch][q] = 0ull;

#pragma unroll
            for (int dz = 0; dz < 3; dz++) {
#pragma unroll
                for (int dy = 0; dy < 3; dy++) {
                    long rbase = ((long)zd[dz] * 48 + zh[dy]) * 48;
                    float tv[4][3];
#pragma unroll
                    for (int ch = 0; ch < 4; ch++) {
                        const float* xc = x + (long)(cq + 8 * ch) * VOX + rbase;
#pragma unroll
                        for (int dx = 0; dx < 3; dx++) tv[ch][dx] = xc[zw[dx]];
                    }
#pragma unroll
                    for (int dx = 0; dx < 3; dx++) {
                        int n = (dz * 3 + dy) * 3 + dx;
                        const ulonglong2* mp = (const ulonglong2*)(mB + n * 8);
                        ulonglong2 mLo = mp[0];
                        ulonglong2 mHi = mp[1];
#pragma unroll
                        for (int ch = 0; ch < 4; ch++) {
                            u64 T = dup2(tv[ch][dx]);
                            fma2(acc[ch][0], mLo.x, T);
                            fma2(acc[ch][1], mLo.y, T);
                            fma2(acc[ch][2], mHi.x, T);
                            fma2(acc[ch][3], mHi.y, T);
                        }
                    }
                }
            }

#pragma unroll
            for (int ch = 0; ch < 4; ch++) {
                int c = cq + 8 * ch;
#pragma unroll
                for (int i = 0; i < 2; i++)
#pragma unroll
                    for (int j = 0; j < 2; j++) {
                        int q = i * 2 + j;
                        long ob = (((long)c * 96 + 2 * d + i) * 96 + 2 * hB + j) * 96 + 2 * v;
                        *(float2*)&out[ob] = *(float2*)&acc[ch][q];
                    }
            }
        }
        __syncthreads();
    }
}

// ---------------------------------------------------------------------------
extern "C" void kernel_launch(void* const* d_in, const int* in_sizes, int n_in,
                              void* d_out, int out_size)
{
    const float* x    = (const float*)d_in[0];
    const float* feat = (const float*)d_in[1];
    const float* w1   = (const float*)d_in[2];
    const float* b1   = (const float*)d_in[3];
    const float* w2   = (const float*)d_in[4];
    const float* b2   = (const float*)d_in[5];
    float* out = (float*)d_out;

    const int smemF = 900 * 144 + 576 * 144;  // 212544 B
    cudaFuncSetAttribute(k_fused, cudaFuncAttributeMaxDynamicSharedMemorySize, smemF);

    k_prep<<<271, 256>>>(w1, w2);
    k_fused<<<dim3(12, 48), 512, smemF>>>(feat, b1, x, b2, out);
}

// round 11
// speedup vs baseline: 3.9650x; 1.0681x over previous
#include <cuda_runtime.h>
#include <cuda_bf16.h>
#include <cstdint>

#define VOX (48*48*48)
typedef unsigned long long u64;
typedef unsigned int u32;

// Device globals (weights only)
__device__ __nv_bfloat16 g_w1a[3 * 9 * 64 * 72];  // conv1 A: [dz][tap9][oc64][hi32|lo32|pad]
__device__ u32 g_w2frag[13824];                   // conv2 B frags: [nt27][kt4][pass2][lane32][b0,b1]

__device__ __forceinline__ void fma2(u64& acc, u64 a, u64 b) {
    asm("fma.rn.f32x2 %0, %1, %2, %0;" : "+l"(acc) : "l"(a), "l"(b));
}
__device__ __forceinline__ u64 dup2(float v) {
    u64 r; asm("mov.b64 %0, {%1, %1};" : "=l"(r) : "f"(v)); return r;
}
__device__ __forceinline__ u32 cvt2bf(float a, float b) {
    u32 r; asm("cvt.rn.bf16x2.f32 %0, %1, %2;" : "=r"(r) : "f"(b), "f"(a)); return r;
}
__device__ __forceinline__ void ldsm4(u32& r0, u32& r1, u32& r2, u32& r3, u32 a) {
    asm volatile("ldmatrix.sync.aligned.m8n8.x4.shared.b16 {%0,%1,%2,%3}, [%4];"
                 : "=r"(r0), "=r"(r1), "=r"(r2), "=r"(r3) : "r"(a));
}
__device__ __forceinline__ void mmabf(float* d, const u32* a, const u32* b) {
    asm volatile(
        "mma.sync.aligned.m16n8k16.row.col.f32.bf16.bf16.f32 "
        "{%0,%1,%2,%3}, {%4,%5,%6,%7}, {%8,%9}, {%0,%1,%2,%3};"
        : "+f"(d[0]), "+f"(d[1]), "+f"(d[2]), "+f"(d[3])
        : "r"(a[0]), "r"(a[1]), "r"(a[2]), "r"(a[3]), "r"(b[0]), "r"(b[1]));
}

// ---------------------------------------------------------------------------
// Prep (unchanged)
// ---------------------------------------------------------------------------
extern "C" __global__ void k_prep(const float* __restrict__ w1,
                                  const float* __restrict__ w2)
{
    int id = blockIdx.x * 256 + threadIdx.x;
    if (id < 13824) {
        int breg  = id & 1;
        int entry = id >> 1;
        int lane  = entry & 31;
        int q     = entry >> 5;
        int pass  = q & 1;
        int kt    = (q >> 1) & 3;
        int nt    = q >> 3;
        int tr = lane >> 2, tc = lane & 3;
        int mc = nt * 8 + tr;
        int k0 = kt * 16 + 2 * tc + breg * 8;
        float v0 = w2[mc * 64 + k0];
        float v1 = w2[mc * 64 + k0 + 1];
        __nv_bfloat16 h0 = __float2bfloat16(v0);
        __nv_bfloat16 h1 = __float2bfloat16(v1);
        u32 out;
        if (pass == 0) {
            out = ((u32)__bfloat16_as_ushort(h1) << 16) | (u32)__bfloat16_as_ushort(h0);
        } else {
            __nv_bfloat16 l0 = __float2bfloat16(v0 - __bfloat162float(h0));
            __nv_bfloat16 l1 = __float2bfloat16(v1 - __bfloat162float(h1));
            out = ((u32)__bfloat16_as_ushort(l1) << 16) | (u32)__bfloat16_as_ushort(l0);
        }
        g_w2frag[id] = out;
    } else if (id < 13824 + 55296) {
        int q = id - 13824;
        int ci = q & 31;
        int r  = q >> 5;
        int oc = r & 63;
        int r2 = r >> 6;
        int tap = r2 % 9, dz = r2 / 9;
        float v = w1[oc * 864 + ci * 27 + dz * 9 + tap];
        __nv_bfloat16 hi = __float2bfloat16(v);
        __nv_bfloat16 lo = __float2bfloat16(v - __bfloat162float(hi));
        int base = ((dz * 9 + tap) * 64 + oc) * 72;
        g_w1a[base + ci]      = hi;
        g_w1a[base + 32 + ci] = lo;
    }
}

// ---------------------------------------------------------------------------
// Fused kernel, 256 threads (8 warps), 2 CTAs/SM, grid (24,48).
// Block = (depth d, 2 h-rows h0, h0+1).
// conv1 warp grid: mw = warp&3 (m16 oc tile), nw = warp>>2 (h row 0..1).
// smem (111744 B):
//   phase1: sF [0,28800) per-dz features 4hh x 50wp x 144B ; sA [28800,111744)
//   phase2: sHu [0,26112) 96 rows x 272B ; sS [26112,52224) 96 x 68 fp32
//   phase3: sHu [0,26112) ; sMt [26112,110592) 96 x 220 fp32
// ---------------------------------------------------------------------------
extern "C" __global__ void __launch_bounds__(256, 2) k_fused(
    const float* __restrict__ feat, const float* __restrict__ b1,
    const float* __restrict__ x,    const float* __restrict__ b2,
    float* __restrict__ out)
{
    extern __shared__ char sm[];
    char* sF = sm;
    char* sA = sm + 28800;
    const u32 sFb = (u32)__cvta_generic_to_shared(sF);
    const u32 sAb = (u32)__cvta_generic_to_shared(sA);

    const int tid  = threadIdx.x;
    const int lane = tid & 31;
    const int warp = tid >> 5;
    const int mw = warp & 3;          // m16 oc tile (0..3)
    const int nw = warp >> 2;         // h row (0..1)
    const int grp = lane >> 3, r8 = lane & 7;
    const int tr = lane >> 2, tc = lane & 3;
    const int h0 = blockIdx.x * 2;
    const int d  = blockIdx.y;

    // ======================= Phase 1: conv1 =======================
    float D[6][4];
#pragma unroll
    for (int j = 0; j < 6; j++)
#pragma unroll
        for (int c = 0; c < 4; c++) D[j][c] = 0.0f;

#pragma unroll 1
    for (int dz = 0; dz < 3; dz++) {
        __syncthreads();
        // stage A slab for this dz
        {
            const uint4* src = (const uint4*)(g_w1a + (size_t)dz * 9 * 64 * 72);
            uint4* dst = (uint4*)sA;
            for (int t = tid; t < 5184; t += 256) dst[t] = src[t];
        }
        // stage features for this dz: 16 ci2 x 4 hh x 50 wp
        {
            int z = min(max(d - 1 + dz, 0), 47);
            for (int t = tid; t < 3200; t += 256) {
                int wp = t % 50;
                int q  = t / 50;
                int hh = q & 3;
                int ci2 = q >> 2;
                int y = min(max(h0 - 1 + hh, 0), 47);
                int w = min(max(wp - 1, 0), 47);
                long gi = (long)(2 * ci2) * VOX + (z * 48 + y) * 48 + w;
                float f0 = feat[gi];
                float f1 = feat[gi + VOX];
                u32 hp = cvt2bf(f0, f1);
                float r0 = f0 - __uint_as_float(hp << 16);
                float r1 = f1 - __uint_as_float(hp & 0xffff0000u);
                u32 lp = cvt2bf(r0, r1);
                int row = hh * 50 + wp;
                *(u32*)(sF + row * 144 + ci2 * 4)      = hp;
                *(u32*)(sF + row * 144 + 64 + ci2 * 4) = lp;
            }
        }
        __syncthreads();

#pragma unroll 1
        for (int dy = 0; dy < 3; dy++) {
#pragma unroll 1
            for (int dx = 0; dx < 3; dx++) {
                const u32 tapBase = sAb + (dy * 3 + dx) * 64 * 144;
                const int rowBase = (nw + dy) * 50 + dx;
#pragma unroll
                for (int kc = 0; kc < 2; kc++) {
                    u32 a_hi[4], a_lo[4];
                    {
                        u32 ab = tapBase
                               + (mw * 16 + (grp & 1) * 8 + r8) * 144
                               + (grp >> 1) * 16 + kc * 32;
                        ldsm4(a_hi[0], a_hi[1], a_hi[2], a_hi[3], ab);
                        ldsm4(a_lo[0], a_lo[1], a_lo[2], a_lo[3], ab + 64);
                    }
                    u32 bh[6][2];
#pragma unroll
                    for (int jj = 0; jj < 3; jj++) {
                        int rowI = rowBase + jj * 16 + (grp >> 1) * 8 + r8;
                        u32 bb = sFb + rowI * 144 + (grp & 1) * 16 + kc * 32;
                        ldsm4(bh[2 * jj][0], bh[2 * jj][1],
                              bh[2 * jj + 1][0], bh[2 * jj + 1][1], bb);
                    }
#pragma unroll
                    for (int j = 0; j < 6; j++) {
                        mmabf(D[j], a_hi, bh[j]);
                        mmabf(D[j], a_lo, bh[j]);
                    }
                    u32 bl[6][2];
#pragma unroll
                    for (int jj = 0; jj < 3; jj++) {
                        int rowI = rowBase + jj * 16 + (grp >> 1) * 8 + r8;
                        u32 bb = sFb + rowI * 144 + 64 + (grp & 1) * 16 + kc * 32;
                        ldsm4(bl[2 * jj][0], bl[2 * jj][1],
                              bl[2 * jj + 1][0], bl[2 * jj + 1][1], bb);
                    }
#pragma unroll
                    for (int j = 0; j < 6; j++)
                        mmabf(D[j], a_hi, bl[j]);
                }
            }
        }
    }
    __syncthreads();   // sF/sA dead

    // ======================= Phase 2: silu -> scratch -> bf16 split ========
    u32*   sHu = (u32*)sm;               // 96 rows x 272B: vl*68 + kp | 32+kp
    float* sS  = (float*)(sm + 26112);   // 96 x 68 fp32
    const u32 sHb = (u32)__cvta_generic_to_shared(sHu);
    {
        int oc0 = mw * 16 + tr;
        int oc1 = oc0 + 8;
        float bias0 = b1[oc0], bias1 = b1[oc1];
#pragma unroll
        for (int j = 0; j < 6; j++) {
            int vl = nw * 48 + j * 8 + 2 * tc;
            float v0 = D[j][0] + bias0;
            float v1 = D[j][1] + bias0;
            float v2 = D[j][2] + bias1;
            float v3 = D[j][3] + bias1;
            sS[vl * 68 + oc0]       = v0 / (1.0f + __expf(-v0));
            sS[(vl + 1) * 68 + oc0] = v1 / (1.0f + __expf(-v1));
            sS[vl * 68 + oc1]       = v2 / (1.0f + __expf(-v2));
            sS[(vl + 1) * 68 + oc1] = v3 / (1.0f + __expf(-v3));
        }
    }
    __syncthreads();

    for (int t = tid; t < 3072; t += 256) {        // 96 rows x 32 pairs
        int vl = t >> 5, kp = t & 31;
        float2 f = *(const float2*)&sS[vl * 68 + 2 * kp];
        u32 hp = cvt2bf(f.x, f.y);
        float r0 = f.x - __uint_as_float(hp << 16);
        float r1 = f.y - __uint_as_float(hp & 0xffff0000u);
        u32 lp = cvt2bf(r0, r1);
        sHu[vl * 68 + kp]      = hp;
        sHu[vl * 68 + 32 + kp] = lp;
    }
    __syncthreads();

    // ======================= Phase 3: conv2 GEMM -> softmax -> apply =======
    float* sMt = (float*)(sm + 26112);   // 96 x 220 fp32
    const uint2* w2f = (const uint2*)g_w2frag;

    // --- GEMM: M=96 (6 m16 tiles) x N=216 (27 nt) x K=64, flat (nt, mt-pair)
#pragma unroll 1
    for (int u = warp; u < 81; u += 8) {
        int nt = u / 3, mp = u % 3;
        float Dv[2][4];
#pragma unroll
        for (int m = 0; m < 2; m++)
#pragma unroll
            for (int c = 0; c < 4; c++) Dv[m][c] = 0.0f;

#pragma unroll
        for (int kt = 0; kt < 4; kt++) {
            uint2 bhv = w2f[((nt * 4 + kt) * 2 + 0) * 32 + lane];
            uint2 blv = w2f[((nt * 4 + kt) * 2 + 1) * 32 + lane];
            u32 bh[2] = { bhv.x, bhv.y };
            u32 bl[2] = { blv.x, blv.y };
#pragma unroll
            for (int m = 0; m < 2; m++) {
                int mt = mp * 2 + m;
                u32 ah[4], al[4];
                u32 ab = sHb + (mt * 16 + (grp & 1) * 8 + r8) * 272
                       + (grp >> 1) * 16 + kt * 32;
                ldsm4(ah[0], ah[1], ah[2], ah[3], ab);
                ldsm4(al[0], al[1], al[2], al[3], ab + 128);
                mmabf(Dv[m], ah, bh);
                mmabf(Dv[m], al, bh);
                mmabf(Dv[m], ah, bl);
            }
        }
        int mcA = nt * 8 + 2 * tc;
        int mcB = mcA + 1;
        float bA = b2[mcA], bB = b2[mcB];
        int iA = (mcA % 27) * 8 + mcA / 27;
        int iB = (mcB % 27) * 8 + mcB / 27;
#pragma unroll
        for (int m = 0; m < 2; m++) {
            int v0 = (mp * 2 + m) * 16 + tr;
            sMt[v0 * 220 + iA]       = Dv[m][0] + bA;
            sMt[v0 * 220 + iB]       = Dv[m][1] + bB;
            sMt[(v0 + 8) * 220 + iA] = Dv[m][2] + bA;
            sMt[(v0 + 8) * 220 + iB] = Dv[m][3] + bB;
        }
    }
    __syncthreads();

    // --- softmax over n per (vl, g): 768 units / 256 threads = 3 each ---
    for (int s = tid; s < 768; s += 256) {
        int vl = s >> 3, g = s & 7;
        float* p = &sMt[vl * 220 + g];
        float mx = p[0];
#pragma unroll
        for (int n = 1; n < 27; n++) mx = fmaxf(mx, p[n * 8]);
        float e[27], ssum = 0.0f;
#pragma unroll
        for (int n = 0; n < 27; n++) { e[n] = __expf(p[n * 8] - mx); ssum += e[n]; }
        float inv = 1.0f / ssum;
#pragma unroll
        for (int n = 0; n < 27; n++) p[n * 8] = e[n] * inv;
    }
    __syncthreads();

    // --- apply: 768 slots (vl 0..95, cq 0..7) / 256 threads = 3 each ---
    int zd[3];
#pragma unroll
    for (int t = 0; t < 3; t++) zd[t] = min(max(d + t - 1, 0), 47);

#pragma unroll 1
    for (int p = tid; p < 768; p += 256) {
        int vl = p % 96, cq = p / 96;
        int hr = (vl >= 48);
        int v  = vl - (hr ? 48 : 0);
        int hB = h0 + hr;
        int zh[3], zw[3];
#pragma unroll
        for (int t = 0; t < 3; t++) zh[t] = min(max(hB + t - 1, 0), 47);
        zw[0] = max(v - 1, 0); zw[1] = v; zw[2] = min(v + 1, 47);
        const float* mB = &sMt[vl * 220];

        u64 acc[4][4];
#pragma unroll
        for (int ch = 0; ch < 4; ch++)
#pragma unroll
            for (int q = 0; q < 4; q++) acc[ch][q] = 0ull;

#pragma unroll
        for (int dz = 0; dz < 3; dz++) {
#pragma unroll
            for (int dy = 0; dy < 3; dy++) {
                long rbase = ((long)zd[dz] * 48 + zh[dy]) * 48;
                float tv[4][3];
#pragma unroll
                for (int ch = 0; ch < 4; ch++) {
                    const float* xc = x + (long)(cq + 8 * ch) * VOX + rbase;
#pragma unroll
                    for (int dx = 0; dx < 3; dx++) tv[ch][dx] = xc[zw[dx]];
                }
#pragma unroll
                for (int dx = 0; dx < 3; dx++) {
                    int n = (dz * 3 + dy) * 3 + dx;
                    const ulonglong2* mp2 = (const ulonglong2*)(mB + n * 8);
                    ulonglong2 mLo = mp2[0];
                    ulonglong2 mHi = mp2[1];
#pragma unroll
                    for (int ch = 0; ch < 4; ch++) {
                        u64 T = dup2(tv[ch][dx]);
                        fma2(acc[ch][0], mLo.x, T);
                        fma2(acc[ch][1], mLo.y, T);
                        fma2(acc[ch][2], mHi.x, T);
                        fma2(acc[ch][3], mHi.y, T);
                    }
                }
            }
        }

#pragma unroll
        for (int ch = 0; ch < 4; ch++) {
            int c = cq + 8 * ch;
#pragma unroll
            for (int i = 0; i < 2; i++)
#pragma unroll
                for (int j = 0; j < 2; j++) {
                    int q = i * 2 + j;
                    long ob = (((long)c * 96 + 2 * d + i) * 96 + 2 * hB + j) * 96 + 2 * v;
                    *(float2*)&out[ob] = *(float2*)&acc[ch][q];
                }
        }
    }
}

// ---------------------------------------------------------------------------
extern "C" void kernel_launch(void* const* d_in, const int* in_sizes, int n_in,
                              void* d_out, int out_size)
{
    const float* x    = (const float*)d_in[0];
    const float* feat = (const float*)d_in[1];
    const float* w1   = (const float*)d_in[2];
    const float* b1   = (const float*)d_in[3];
    const float* w2   = (const float*)d_in[4];
    const float* b2   = (const float*)d_in[5];
    float* out = (float*)d_out;

    const int smemF = 111744;   // 28800 + 82944 (phase1 max)
    cudaFuncSetAttribute(k_fused, cudaFuncAttributeMaxDynamicSharedMemorySize, smemF);

    k_prep<<<271, 256>>>(w1, w2);
    k_fused<<<dim3(24, 48), 256, smemF>>>(feat, b1, x, b2, out);
}

// round 12
// speedup vs baseline: 4.1687x; 1.0514x over previous
#include <cuda_runtime.h>
#include <cuda_bf16.h>
#include <cstdint>

#define VOX (48*48*48)
typedef unsigned long long u64;
typedef unsigned int u32;

// Device globals (weights only)
__device__ __nv_bfloat16 g_w1a[3 * 9 * 64 * 72];  // conv1 A: [dz][tap9][oc64][hi32|lo32|pad]
__device__ u32 g_w2frag[13824];                   // conv2 B frags: [nt27][kt4][pass2][lane32][b0,b1]

__device__ __forceinline__ void fma2(u64& acc, u64 a, u64 b) {
    asm("fma.rn.f32x2 %0, %1, %2, %0;" : "+l"(acc) : "l"(a), "l"(b));
}
__device__ __forceinline__ u64 dup2(float v) {
    u64 r; asm("mov.b64 %0, {%1, %1};" : "=l"(r) : "f"(v)); return r;
}
__device__ __forceinline__ u32 cvt2bf(float a, float b) {
    u32 r; asm("cvt.rn.bf16x2.f32 %0, %1, %2;" : "=r"(r) : "f"(b), "f"(a)); return r;
}
__device__ __forceinline__ void ldsm4(u32& r0, u32& r1, u32& r2, u32& r3, u32 a) {
    asm volatile("ldmatrix.sync.aligned.m8n8.x4.shared.b16 {%0,%1,%2,%3}, [%4];"
                 : "=r"(r0), "=r"(r1), "=r"(r2), "=r"(r3) : "r"(a));
}
__device__ __forceinline__ void ldsm2(u32& r0, u32& r1, u32 a) {
    asm volatile("ldmatrix.sync.aligned.m8n8.x2.shared.b16 {%0,%1}, [%2];"
                 : "=r"(r0), "=r"(r1) : "r"(a));
}
__device__ __forceinline__ void mmabf(float* d, const u32* a, const u32* b) {
    asm volatile(
        "mma.sync.aligned.m16n8k16.row.col.f32.bf16.bf16.f32 "
        "{%0,%1,%2,%3}, {%4,%5,%6,%7}, {%8,%9}, {%0,%1,%2,%3};"
        : "+f"(d[0]), "+f"(d[1]), "+f"(d[2]), "+f"(d[3])
        : "r"(a[0]), "r"(a[1]), "r"(a[2]), "r"(a[3]), "r"(b[0]), "r"(b[1]));
}

// ---------------------------------------------------------------------------
// Prep (unchanged)
// ---------------------------------------------------------------------------
extern "C" __global__ void k_prep(const float* __restrict__ w1,
                                  const float* __restrict__ w2)
{
    int id = blockIdx.x * 256 + threadIdx.x;
    if (id < 13824) {
        int breg  = id & 1;
        int entry = id >> 1;
        int lane  = entry & 31;
        int q     = entry >> 5;
        int pass  = q & 1;
        int kt    = (q >> 1) & 3;
        int nt    = q >> 3;
        int tr = lane >> 2, tc = lane & 3;
        int mc = nt * 8 + tr;
        int k0 = kt * 16 + 2 * tc + breg * 8;
        float v0 = w2[mc * 64 + k0];
        float v1 = w2[mc * 64 + k0 + 1];
        __nv_bfloat16 h0 = __float2bfloat16(v0);
        __nv_bfloat16 h1 = __float2bfloat16(v1);
        u32 out;
        if (pass == 0) {
            out = ((u32)__bfloat16_as_ushort(h1) << 16) | (u32)__bfloat16_as_ushort(h0);
        } else {
            __nv_bfloat16 l0 = __float2bfloat16(v0 - __bfloat162float(h0));
            __nv_bfloat16 l1 = __float2bfloat16(v1 - __bfloat162float(h1));
            out = ((u32)__bfloat16_as_ushort(l1) << 16) | (u32)__bfloat16_as_ushort(l0);
        }
        g_w2frag[id] = out;
    } else if (id < 13824 + 55296) {
        int q = id - 13824;
        int ci = q & 31;
        int r  = q >> 5;
        int oc = r & 63;
        int r2 = r >> 6;
        int tap = r2 % 9, dz = r2 / 9;
        float v = w1[oc * 864 + ci * 27 + dz * 9 + tap];
        __nv_bfloat16 hi = __float2bfloat16(v);
        __nv_bfloat16 lo = __float2bfloat16(v - __bfloat162float(hi));
        int base = ((dz * 9 + tap) * 64 + oc) * 72;
        g_w1a[base + ci]      = hi;
        g_w1a[base + 32 + ci] = lo;
    }
}

// ---------------------------------------------------------------------------
// Fused kernel, 256 threads, 2 CTAs/SM, grid (24,48). Block = (d, 2 h-rows).
// conv1 warp tile M_t=2 x N_t=3: mw = warp&1 (m-tiles 2mw,2mw+1),
//   nh = (warp>>1)&1 (n8-tiles 3nh..3nh+2), nw = warp>>2 (h row).
// ---------------------------------------------------------------------------
extern "C" __global__ void __launch_bounds__(256, 2) k_fused(
    const float* __restrict__ feat, const float* __restrict__ b1,
    const float* __restrict__ x,    const float* __restrict__ b2,
    float* __restrict__ out)
{
    extern __shared__ char sm[];
    char* sF = sm;
    char* sA = sm + 28800;
    const u32 sFb = (u32)__cvta_generic_to_shared(sF);
    const u32 sAb = (u32)__cvta_generic_to_shared(sA);

    const int tid  = threadIdx.x;
    const int lane = tid & 31;
    const int warp = tid >> 5;
    const int mw = warp & 1;          // m-tile pair (0..1)
    const int nh = (warp >> 1) & 1;   // n8-tile triple (0..1)
    const int nw = warp >> 2;         // h row (0..1)
    const int grp = lane >> 3, r8 = lane & 7;
    const int tr = lane >> 2, tc = lane & 3;
    const int h0 = blockIdx.x * 2;
    const int d  = blockIdx.y;

    // ======================= Phase 1: conv1 =======================
    float D[2][3][4];
#pragma unroll
    for (int i = 0; i < 2; i++)
#pragma unroll
        for (int j = 0; j < 3; j++)
#pragma unroll
            for (int c = 0; c < 4; c++) D[i][j][c] = 0.0f;

#pragma unroll 1
    for (int dz = 0; dz < 3; dz++) {
        __syncthreads();
        {
            const uint4* src = (const uint4*)(g_w1a + (size_t)dz * 9 * 64 * 72);
            uint4* dst = (uint4*)sA;
            for (int t = tid; t < 5184; t += 256) dst[t] = src[t];
        }
        {
            int z = min(max(d - 1 + dz, 0), 47);
            for (int t = tid; t < 3200; t += 256) {
                int wp = t % 50;
                int q  = t / 50;
                int hh = q & 3;
                int ci2 = q >> 2;
                int y = min(max(h0 - 1 + hh, 0), 47);
                int w = min(max(wp - 1, 0), 47);
                long gi = (long)(2 * ci2) * VOX + (z * 48 + y) * 48 + w;
                float f0 = feat[gi];
                float f1 = feat[gi + VOX];
                u32 hp = cvt2bf(f0, f1);
                float r0 = f0 - __uint_as_float(hp << 16);
                float r1 = f1 - __uint_as_float(hp & 0xffff0000u);
                u32 lp = cvt2bf(r0, r1);
                int row = hh * 50 + wp;
                *(u32*)(sF + row * 144 + ci2 * 4)      = hp;
                *(u32*)(sF + row * 144 + 64 + ci2 * 4) = lp;
            }
        }
        __syncthreads();

#pragma unroll 1
        for (int dy = 0; dy < 3; dy++) {
#pragma unroll 1
            for (int dx = 0; dx < 3; dx++) {
                const u32 tapBase = sAb + (dy * 3 + dx) * 64 * 144;
                const int rowBase = (nw + dy) * 50 + dx + nh * 24;
#pragma unroll
                for (int kc = 0; kc < 2; kc++) {
                    // A: 2 m-tiles, hi + lo
                    u32 a_hi[2][4], a_lo[2][4];
#pragma unroll
                    for (int i = 0; i < 2; i++) {
                        u32 ab = tapBase
                               + ((2 * mw + i) * 16 + (grp & 1) * 8 + r8) * 144
                               + (grp >> 1) * 16 + kc * 32;
                        ldsm4(a_hi[i][0], a_hi[i][1], a_hi[i][2], a_hi[i][3], ab);
                        ldsm4(a_lo[i][0], a_lo[i][1], a_lo[i][2], a_lo[i][3], ab + 64);
                    }
                    // B hi: tiles {3nh,3nh+1} via x4, tile {3nh+2} via x2
                    u32 bh[3][2];
                    {
                        u32 bb = sFb + (rowBase + (grp >> 1) * 8 + r8) * 144
                               + (grp & 1) * 16 + kc * 32;
                        ldsm4(bh[0][0], bh[0][1], bh[1][0], bh[1][1], bb);
                        u32 b2a = sFb + (rowBase + 16 + r8) * 144
                                + (grp & 1) * 16 + kc * 32;
                        ldsm2(bh[2][0], bh[2][1], b2a);
                    }
#pragma unroll
                    for (int i = 0; i < 2; i++)
#pragma unroll
                        for (int j = 0; j < 3; j++) {
                            mmabf(D[i][j], a_hi[i], bh[j]);
                            mmabf(D[i][j], a_lo[i], bh[j]);
                        }
                    // B lo
                    u32 bl[3][2];
                    {
                        u32 bb = sFb + (rowBase + (grp >> 1) * 8 + r8) * 144
                               + 64 + (grp & 1) * 16 + kc * 32;
                        ldsm4(bl[0][0], bl[0][1], bl[1][0], bl[1][1], bb);
                        u32 b2a = sFb + (rowBase + 16 + r8) * 144
                                + 64 + (grp & 1) * 16 + kc * 32;
                        ldsm2(bl[2][0], bl[2][1], b2a);
                    }
#pragma unroll
                    for (int i = 0; i < 2; i++)
#pragma unroll
                        for (int j = 0; j < 3; j++)
                            mmabf(D[i][j], a_hi[i], bl[j]);
                }
            }
        }
    }
    __syncthreads();   // sF/sA dead

    // ======================= Phase 2: silu -> scratch -> bf16 split ========
    u32*   sHu = (u32*)sm;               // 96 rows x 272B: vl*68 + kp | 32+kp
    float* sS  = (float*)(sm + 26112);   // 96 x 68 fp32
    const u32 sHb = (u32)__cvta_generic_to_shared(sHu);
    {
#pragma unroll
        for (int i = 0; i < 2; i++) {
            int oc0 = (2 * mw + i) * 16 + tr;
            int oc1 = oc0 + 8;
            float bias0 = b1[oc0], bias1 = b1[oc1];
#pragma unroll
            for (int j = 0; j < 3; j++) {
                int vl = nw * 48 + (3 * nh + j) * 8 + 2 * tc;
                float v0 = D[i][j][0] + bias0;
                float v1 = D[i][j][1] + bias0;
                float v2 = D[i][j][2] + bias1;
                float v3 = D[i][j][3] + bias1;
                sS[vl * 68 + oc0]       = v0 / (1.0f + __expf(-v0));
                sS[(vl + 1) * 68 + oc0] = v1 / (1.0f + __expf(-v1));
                sS[vl * 68 + oc1]       = v2 / (1.0f + __expf(-v2));
                sS[(vl + 1) * 68 + oc1] = v3 / (1.0f + __expf(-v3));
            }
        }
    }
    __syncthreads();

    for (int t = tid; t < 3072; t += 256) {        // 96 rows x 32 pairs
        int vl = t >> 5, kp = t & 31;
        float2 f = *(const float2*)&sS[vl * 68 + 2 * kp];
        u32 hp = cvt2bf(f.x, f.y);
        float r0 = f.x - __uint_as_float(hp << 16);
        float r1 = f.y - __uint_as_float(hp & 0xffff0000u);
        u32 lp = cvt2bf(r0, r1);
        sHu[vl * 68 + kp]      = hp;
        sHu[vl * 68 + 32 + kp] = lp;
    }
    __syncthreads();

    // ======================= Phase 3: conv2 GEMM -> softmax -> apply =======
    float* sMt = (float*)(sm + 26112);   // 96 x 220 fp32
    const uint2* w2f = (const uint2*)g_w2frag;

    // --- GEMM: units of 2 nt sharing A loads; mt processed in halves of 3.
#pragma unroll 1
    for (int u = warp; u < 14; u += 8) {
        int nt0 = 2 * u;
        bool two = (nt0 + 1 < 27);
        float Dv[2][6][4];
#pragma unroll
        for (int t = 0; t < 2; t++)
#pragma unroll
            for (int mt = 0; mt < 6; mt++)
#pragma unroll
                for (int c = 0; c < 4; c++) Dv[t][mt][c] = 0.0f;

#pragma unroll
        for (int kt = 0; kt < 4; kt++) {
#pragma unroll
            for (int mh = 0; mh < 2; mh++) {
                u32 ah[3][4], al[3][4];
#pragma unroll
                for (int mi = 0; mi < 3; mi++) {
                    int mt = mh * 3 + mi;
                    u32 ab = sHb + (mt * 16 + (grp & 1) * 8 + r8) * 272
                           + (grp >> 1) * 16 + kt * 32;
                    ldsm4(ah[mi][0], ah[mi][1], ah[mi][2], ah[mi][3], ab);
                    ldsm4(al[mi][0], al[mi][1], al[mi][2], al[mi][3], ab + 128);
                }
#pragma unroll
                for (int t = 0; t < 2; t++) {
                    if (t == 1 && !two) break;
                    int nt = nt0 + t;
                    uint2 bhv = w2f[((nt * 4 + kt) * 2 + 0) * 32 + lane];
                    uint2 blv = w2f[((nt * 4 + kt) * 2 + 1) * 32 + lane];
                    u32 bh[2] = { bhv.x, bhv.y };
                    u32 bl[2] = { blv.x, blv.y };
#pragma unroll
                    for (int mi = 0; mi < 3; mi++) {
                        int mt = mh * 3 + mi;
                        mmabf(Dv[t][mt], ah[mi], bh);
                        mmabf(Dv[t][mt], al[mi], bh);
                        mmabf(Dv[t][mt], ah[mi], bl);
                    }
                }
            }
        }
#pragma unroll
        for (int t = 0; t < 2; t++) {
            if (t == 1 && !two) break;
            int nt = nt0 + t;
            int mcA = nt * 8 + 2 * tc;
            int mcB = mcA + 1;
            float bA = b2[mcA], bB = b2[mcB];
            int iA = (mcA % 27) * 8 + mcA / 27;
            int iB = (mcB % 27) * 8 + mcB / 27;
#pragma unroll
            for (int mt = 0; mt < 6; mt++) {
                int v0 = mt * 16 + tr;
                sMt[v0 * 220 + iA]       = Dv[t][mt][0] + bA;
                sMt[v0 * 220 + iB]       = Dv[t][mt][1] + bB;
                sMt[(v0 + 8) * 220 + iA] = Dv[t][mt][2] + bA;
                sMt[(v0 + 8) * 220 + iB] = Dv[t][mt][3] + bB;
            }
        }
    }
    __syncthreads();

    // --- softmax over n per (vl, g) ---
    for (int s = tid; s < 768; s += 256) {
        int vl = s >> 3, g = s & 7;
        float* p = &sMt[vl * 220 + g];
        float mx = p[0];
#pragma unroll
        for (int n = 1; n < 27; n++) mx = fmaxf(mx, p[n * 8]);
        float e[27], ssum = 0.0f;
#pragma unroll
        for (int n = 0; n < 27; n++) { e[n] = __expf(p[n * 8] - mx); ssum += e[n]; }
        float inv = 1.0f / ssum;
#pragma unroll
        for (int n = 0; n < 27; n++) p[n * 8] = e[n] * inv;
    }
    __syncthreads();

    // --- apply ---
    int zd[3];
#pragma unroll
    for (int t = 0; t < 3; t++) zd[t] = min(max(d + t - 1, 0), 47);

#pragma unroll 1
    for (int p = tid; p < 768; p += 256) {
        int vl = p % 96, cq = p / 96;
        int hr = (vl >= 48);
        int v  = vl - (hr ? 48 : 0);
        int hB = h0 + hr;
        int zh[3], zw[3];
#pragma unroll
        for (int t = 0; t < 3; t++) zh[t] = min(max(hB + t - 1, 0), 47);
        zw[0] = max(v - 1, 0); zw[1] = v; zw[2] = min(v + 1, 47);
        const float* mB = &sMt[vl * 220];

        u64 acc[4][4];
#pragma unroll
        for (int ch = 0; ch < 4; ch++)
#pragma unroll
            for (int q = 0; q < 4; q++) acc[ch][q] = 0ull;

#pragma unroll
        for (int dz = 0; dz < 3; dz++) {
#pragma unroll
            for (int dy = 0; dy < 3; dy++) {
                long rbase = ((long)zd[dz] * 48 + zh[dy]) * 48;
                float tv[4][3];
#pragma unroll
                for (int ch = 0; ch < 4; ch++) {
                    const float* xc = x + (long)(cq + 8 * ch) * VOX + rbase;
#pragma unroll
                    for (int dx = 0; dx < 3; dx++) tv[ch][dx] = xc[zw[dx]];
                }
#pragma unroll
                for (int dx = 0; dx < 3; dx++) {
                    int n = (dz * 3 + dy) * 3 + dx;
                    const ulonglong2* mp2 = (const ulonglong2*)(mB + n * 8);
                    ulonglong2 mLo = mp2[0];
                    ulonglong2 mHi = mp2[1];
#pragma unroll
                    for (int ch = 0; ch < 4; ch++) {
                        u64 T = dup2(tv[ch][dx]);
                        fma2(acc[ch][0], mLo.x, T);
                        fma2(acc[ch][1], mLo.y, T);
                        fma2(acc[ch][2], mHi.x, T);
                        fma2(acc[ch][3], mHi.y, T);
                    }
                }
            }
        }

#pragma unroll
        for (int ch = 0; ch < 4; ch++) {
            int c = cq + 8 * ch;
#pragma unroll
            for (int i = 0; i < 2; i++)
#pragma unroll
                for (int j = 0; j < 2; j++) {
                    int q = i * 2 + j;
                    long ob = (((long)c * 96 + 2 * d + i) * 96 + 2 * hB + j) * 96 + 2 * v;
                    *(float2*)&out[ob] = *(float2*)&acc[ch][q];
                }
        }
    }
}

// ---------------------------------------------------------------------------
extern "C" void kernel_launch(void* const* d_in, const int* in_sizes, int n_in,
                              void* d_out, int out_size)
{
    const float* x    = (const float*)d_in[0];
    const float* feat = (const float*)d_in[1];
    const float* w1   = (const float*)d_in[2];
    const float* b1   = (const float*)d_in[3];
    const float* w2   = (const float*)d_in[4];
    const float* b2   = (const float*)d_in[5];
    float* out = (float*)d_out;

    const int smemF = 111744;
    cudaFuncSetAttribute(k_fused, cudaFuncAttributeMaxDynamicSharedMemorySize, smemF);

    k_prep<<<271, 256>>>(w1, w2);
    k_fused<<<dim3(24, 48), 256, smemF>>>(feat, b1, x, b2, out);
}

// round 13
// speedup vs baseline: 4.4245x; 1.0614x over previous
#include <cuda_runtime.h>
#include <cuda_bf16.h>
#include <cstdint>

#define VOX (48*48*48)
typedef unsigned long long u64;
typedef unsigned int u32;

// Device globals (weights only)
__device__ __nv_bfloat16 g_w1a[3 * 9 * 64 * 72];  // conv1 A: [dz][tap9][oc64][hi32|lo32|pad]
__device__ u32 g_w2frag[13824];                   // conv2 B frags (k-permuted)

__device__ __forceinline__ void fma2(u64& acc, u64 a, u64 b) {
    asm("fma.rn.f32x2 %0, %1, %2, %0;" : "+l"(acc) : "l"(a), "l"(b));
}
__device__ __forceinline__ u64 dup2(float v) {
    u64 r; asm("mov.b64 %0, {%1, %1};" : "=l"(r) : "f"(v)); return r;
}
__device__ __forceinline__ u32 cvt2bf(float a, float b) {
    u32 r; asm("cvt.rn.bf16x2.f32 %0, %1, %2;" : "=r"(r) : "f"(b), "f"(a)); return r;
}
__device__ __forceinline__ void ldsm4(u32& r0, u32& r1, u32& r2, u32& r3, u32 a) {
    asm volatile("ldmatrix.sync.aligned.m8n8.x4.shared.b16 {%0,%1,%2,%3}, [%4];"
                 : "=r"(r0), "=r"(r1), "=r"(r2), "=r"(r3) : "r"(a));
}
__device__ __forceinline__ void mmabf(float* d, const u32* a, const u32* b) {
    asm volatile(
        "mma.sync.aligned.m16n8k16.row.col.f32.bf16.bf16.f32 "
        "{%0,%1,%2,%3}, {%4,%5,%6,%7}, {%8,%9}, {%0,%1,%2,%3};"
        : "+f"(d[0]), "+f"(d[1]), "+f"(d[2]), "+f"(d[3])
        : "r"(a[0]), "r"(a[1]), "r"(a[2]), "r"(a[3]), "r"(b[0]), "r"(b[1]));
}
__device__ __forceinline__ void cpasync16(u32 dst, const void* src) {
    asm volatile("cp.async.cg.shared.global [%0], [%1], 16;"
                 :: "r"(dst), "l"(src));
}

// ---------------------------------------------------------------------------
// Prep: w1 MMA-A layout (unchanged); w2 B fragments with PERMUTED k:
//   oc(k') = (k'>>4)*16 + ((k'>>1)&7) + ((k'&1)<<3)
// ---------------------------------------------------------------------------
extern "C" __global__ void k_prep(const float* __restrict__ w1,
                                  const float* __restrict__ w2)
{
    int id = blockIdx.x * 256 + threadIdx.x;
    if (id < 13824) {
        int breg  = id & 1;
        int entry = id >> 1;
        int lane  = entry & 31;
        int q     = entry >> 5;
        int pass  = q & 1;
        int kt    = (q >> 1) & 3;
        int nt    = q >> 3;
        int tr = lane >> 2, tc = lane & 3;
        int mc = nt * 8 + tr;
        int k0 = kt * 16 + 2 * tc + breg * 8;       // permuted positions k0, k0+1
        int ocA = ((k0 >> 4) << 4) + ((k0 >> 1) & 7) + ((k0 & 1) << 3);
        int k1 = k0 + 1;
        int ocB = ((k1 >> 4) << 4) + ((k1 >> 1) & 7) + ((k1 & 1) << 3);
        float v0 = w2[mc * 64 + ocA];
        float v1 = w2[mc * 64 + ocB];
        __nv_bfloat16 h0 = __float2bfloat16(v0);
        __nv_bfloat16 h1 = __float2bfloat16(v1);
        u32 out;
        if (pass == 0) {
            out = ((u32)__bfloat16_as_ushort(h1) << 16) | (u32)__bfloat16_as_ushort(h0);
        } else {
            __nv_bfloat16 l0 = __float2bfloat16(v0 - __bfloat162float(h0));
            __nv_bfloat16 l1 = __float2bfloat16(v1 - __bfloat162float(h1));
            out = ((u32)__bfloat16_as_ushort(l1) << 16) | (u32)__bfloat16_as_ushort(l0);
        }
        g_w2frag[id] = out;
    } else if (id < 13824 + 55296) {
        int q = id - 13824;
        int ci = q & 31;
        int r  = q >> 5;
        int oc = r & 63;
        int r2 = r >> 6;
        int tap = r2 % 9, dz = r2 / 9;
        float v = w1[oc * 864 + ci * 27 + dz * 9 + tap];
        __nv_bfloat16 hi = __float2bfloat16(v);
        __nv_bfloat16 lo = __float2bfloat16(v - __bfloat162float(hi));
        int base = ((dz * 9 + tap) * 64 + oc) * 72;
        g_w1a[base + ci]      = hi;
        g_w1a[base + 32 + ci] = lo;
    }
}

// ---------------------------------------------------------------------------
// Fused kernel, 256 threads, 2 CTAs/SM, grid (24,48). Block = (d, 2 h-rows).
// ---------------------------------------------------------------------------
extern "C" __global__ void __launch_bounds__(256, 2) k_fused(
    const float* __restrict__ feat, const float* __restrict__ b1,
    const float* __restrict__ x,    const float* __restrict__ b2,
    float* __restrict__ out)
{
    extern __shared__ char sm[];
    char* sF = sm;
    char* sA = sm + 28800;
    const u32 sFb = (u32)__cvta_generic_to_shared(sF);
    const u32 sAb = (u32)__cvta_generic_to_shared(sA);

    const int tid  = threadIdx.x;
    const int lane = tid & 31;
    const int warp = tid >> 5;
    const int mw = warp & 1;
    const int nh = (warp >> 1) & 1;
    const int nw = warp >> 2;
    const int grp = lane >> 3, r8 = lane & 7;
    const int tr = lane >> 2, tc = lane & 3;
    const int h0 = blockIdx.x * 2;
    const int d  = blockIdx.y;

    // ======================= Phase 1: conv1 =======================
    float D[2][3][4];
#pragma unroll
    for (int i = 0; i < 2; i++)
#pragma unroll
        for (int j = 0; j < 3; j++)
#pragma unroll
            for (int c = 0; c < 4; c++) D[i][j][c] = 0.0f;

#pragma unroll 1
    for (int dz = 0; dz < 3; dz++) {
        __syncthreads();
        // stage A via cp.async (overlaps with feature conversion below)
        {
            const char* src = (const char*)(g_w1a + (size_t)dz * 9 * 64 * 72);
            for (int t = tid; t < 5184; t += 256)
                cpasync16(sAb + t * 16, src + t * 16);
            asm volatile("cp.async.commit_group;" ::: "memory");
        }
        // stage features for this dz (compute-heavy; overlaps cp.async)
        {
            int z = min(max(d - 1 + dz, 0), 47);
            for (int t = tid; t < 3200; t += 256) {
                int wp = t % 50;
                int q  = t / 50;
                int hh = q & 3;
                int ci2 = q >> 2;
                int y = min(max(h0 - 1 + hh, 0), 47);
                int w = min(max(wp - 1, 0), 47);
                long gi = (long)(2 * ci2) * VOX + (z * 48 + y) * 48 + w;
                float f0 = feat[gi];
                float f1 = feat[gi + VOX];
                u32 hp = cvt2bf(f0, f1);
                float r0 = f0 - __uint_as_float(hp << 16);
                float r1 = f1 - __uint_as_float(hp & 0xffff0000u);
                u32 lp = cvt2bf(r0, r1);
                int row = hh * 50 + wp;
                *(u32*)(sF + row * 144 + ci2 * 4)      = hp;
                *(u32*)(sF + row * 144 + 64 + ci2 * 4) = lp;
            }
        }
        asm volatile("cp.async.wait_group 0;" ::: "memory");
        __syncthreads();

#pragma unroll 1
        for (int dy = 0; dy < 3; dy++) {
#pragma unroll 1
            for (int dx = 0; dx < 3; dx++) {
                const u32 tapBase = sAb + (dy * 3 + dx) * 64 * 144;
                const int rowBase = (nw + dy) * 50 + dx + nh * 24;
#pragma unroll
                for (int kc = 0; kc < 2; kc++) {
                    // A: 2 m-tiles, hi + lo
                    u32 a_hi[2][4], a_lo[2][4];
#pragma unroll
                    for (int i = 0; i < 2; i++) {
                        u32 ab = tapBase
                               + ((2 * mw + i) * 16 + (grp & 1) * 8 + r8) * 144
                               + (grp >> 1) * 16 + kc * 32;
                        ldsm4(a_hi[i][0], a_hi[i][1], a_hi[i][2], a_hi[i][3], ab);
                        ldsm4(a_lo[i][0], a_lo[i][1], a_lo[i][2], a_lo[i][3], ab + 64);
                    }
                    // B: tiles {3nh,3nh+1} hi and lo via x4 each;
                    //    tile {3nh+2} hi+lo together in ONE x4 (grp = k-half, hi/lo)
                    u32 bh[3][2], bl[3][2];
                    {
                        u32 bb = sFb + (rowBase + (grp >> 1) * 8 + r8) * 144
                               + (grp & 1) * 16 + kc * 32;
                        ldsm4(bh[0][0], bh[0][1], bh[1][0], bh[1][1], bb);
                        ldsm4(bl[0][0], bl[0][1], bl[1][0], bl[1][1], bb + 64);
                        u32 b2a = sFb + (rowBase + 16 + r8) * 144
                                + (grp & 1) * 16 + (grp >> 1) * 64 + kc * 32;
                        ldsm4(bh[2][0], bh[2][1], bl[2][0], bl[2][1], b2a);
                    }
#pragma unroll
                    for (int i = 0; i < 2; i++)
#pragma unroll
                        for (int j = 0; j < 3; j++) {
                            mmabf(D[i][j], a_hi[i], bh[j]);
                            mmabf(D[i][j], a_lo[i], bh[j]);
                            mmabf(D[i][j], a_hi[i], bl[j]);
                        }
                }
            }
        }
    }
    __syncthreads();   // sF/sA dead

    // ====== Phase 2: silu + direct bf16 hi/lo split into sHu (permuted k) ===
    // sHu row vl (272B): hi u32 at [jcol], lo at [32+jcol];
    // jcol = (oc>>4)*8 + (oc&7); packed pair = {oc, oc+8}.
    u32* sHu = (u32*)sm;
    const u32 sHb = (u32)__cvta_generic_to_shared(sHu);
    {
#pragma unroll
        for (int i = 0; i < 2; i++) {
            int oc0 = (2 * mw + i) * 16 + tr;          // oc in 0..55, tr<8
            int jcol = (2 * mw + i) * 8 + tr;
            float bias0 = b1[oc0], bias1 = b1[oc0 + 8];
#pragma unroll
            for (int j = 0; j < 3; j++) {
                int vl = nw * 48 + (3 * nh + j) * 8 + 2 * tc;
                float v0 = D[i][j][0] + bias0;         // vl,   oc0
                float v1 = D[i][j][1] + bias0;         // vl+1, oc0
                float v2 = D[i][j][2] + bias1;         // vl,   oc0+8
                float v3 = D[i][j][3] + bias1;         // vl+1, oc0+8
                v0 = v0 / (1.0f + __expf(-v0));
                v1 = v1 / (1.0f + __expf(-v1));
                v2 = v2 / (1.0f + __expf(-v2));
                v3 = v3 / (1.0f + __expf(-v3));
                u32 hp0 = cvt2bf(v0, v2);
                u32 hp1 = cvt2bf(v1, v3);
                u32 lp0 = cvt2bf(v0 - __uint_as_float(hp0 << 16),
                                 v2 - __uint_as_float(hp0 & 0xffff0000u));
                u32 lp1 = cvt2bf(v1 - __uint_as_float(hp1 << 16),
                                 v3 - __uint_as_float(hp1 & 0xffff0000u));
                sHu[vl * 68 + jcol]            = hp0;
                sHu[vl * 68 + 32 + jcol]       = lp0;
                sHu[(vl + 1) * 68 + jcol]      = hp1;
                sHu[(vl + 1) * 68 + 32 + jcol] = lp1;
            }
        }
    }
    __syncthreads();

    // ======================= Phase 3: conv2 GEMM -> softmax -> apply =======
    float* sMt = (float*)(sm + 26112);   // 96 x 220 fp32
    const uint2* w2f = (const uint2*)g_w2frag;

    // --- GEMM: warp owns nt = {warp, warp+8, warp+16, warp+24<27};
    //     A fragments hoisted above the nt loop (per mh half of m-tiles).
    {
        const int nnt = (warp < 3) ? 4 : 3;
#pragma unroll 1
        for (int mh = 0; mh < 2; mh++) {
            float Dv[4][3][4];
#pragma unroll
            for (int t = 0; t < 4; t++)
#pragma unroll
                for (int mi = 0; mi < 3; mi++)
#pragma unroll
                    for (int c = 0; c < 4; c++) Dv[t][mi][c] = 0.0f;

#pragma unroll
            for (int kt = 0; kt < 4; kt++) {
                u32 ah[3][4], al[3][4];
#pragma unroll
                for (int mi = 0; mi < 3; mi++) {
                    int mt = mh * 3 + mi;
                    u32 ab = sHb + (mt * 16 + (grp & 1) * 8 + r8) * 272
                           + (grp >> 1) * 16 + kt * 32;
                    ldsm4(ah[mi][0], ah[mi][1], ah[mi][2], ah[mi][3], ab);
                    ldsm4(al[mi][0], al[mi][1], al[mi][2], al[mi][3], ab + 128);
                }
#pragma unroll
                for (int t = 0; t < 4; t++) {
                    if (t >= nnt) break;
                    int nt = warp + 8 * t;
                    uint2 bhv = w2f[((nt * 4 + kt) * 2 + 0) * 32 + lane];
                    uint2 blv = w2f[((nt * 4 + kt) * 2 + 1) * 32 + lane];
                    u32 bh[2] = { bhv.x, bhv.y };
                    u32 bl[2] = { blv.x, blv.y };
#pragma unroll
                    for (int mi = 0; mi < 3; mi++) {
                        mmabf(Dv[t][mi], ah[mi], bh);
                        mmabf(Dv[t][mi], al[mi], bh);
                        mmabf(Dv[t][mi], ah[mi], bl);
                    }
                }
            }
#pragma unroll
            for (int t = 0; t < 4; t++) {
                if (t >= nnt) break;
                int nt = warp + 8 * t;
                int mcA = nt * 8 + 2 * tc;
                int mcB = mcA + 1;
                float bA = b2[mcA], bB = b2[mcB];
                int iA = (mcA % 27) * 8 + mcA / 27;
                int iB = (mcB % 27) * 8 + mcB / 27;
#pragma unroll
                for (int mi = 0; mi < 3; mi++) {
                    int v0 = (mh * 3 + mi) * 16 + tr;
                    sMt[v0 * 220 + iA]       = Dv[t][mi][0] + bA;
                    sMt[v0 * 220 + iB]       = Dv[t][mi][1] + bB;
                    sMt[(v0 + 8) * 220 + iA] = Dv[t][mi][2] + bA;
                    sMt[(v0 + 8) * 220 + iB] = Dv[t][mi][3] + bB;
                }
            }
        }
    }
    __syncthreads();

    // --- softmax over n per (vl, g) ---
    for (int s = tid; s < 768; s += 256) {
        int vl = s >> 3, g = s & 7;
        float* p = &sMt[vl * 220 + g];
        float mx = p[0];
#pragma unroll
        for (int n = 1; n < 27; n++) mx = fmaxf(mx, p[n * 8]);
        float e[27], ssum = 0.0f;
#pragma unroll
        for (int n = 0; n < 27; n++) { e[n] = __expf(p[n * 8] - mx); ssum += e[n]; }
        float inv = 1.0f / ssum;
#pragma unroll
        for (int n = 0; n < 27; n++) p[n * 8] = e[n] * inv;
    }
    __syncthreads();

    // --- apply ---
    int zd[3];
#pragma unroll
    for (int t = 0; t < 3; t++) zd[t] = min(max(d + t - 1, 0), 47);

#pragma unroll 1
    for (int p = tid; p < 768; p += 256) {
        int vl = p % 96, cq = p / 96;
        int hr = (vl >= 48);
        int v  = vl - (hr ? 48 : 0);
        int hB = h0 + hr;
        int zh[3], zw[3];
#pragma unroll
        for (int t = 0; t < 3; t++) zh[t] = min(max(hB + t - 1, 0), 47);
        zw[0] = max(v - 1, 0); zw[1] = v; zw[2] = min(v + 1, 47);
        const float* mB = &sMt[vl * 220];

        u64 acc[4][4];
#pragma unroll
        for (int ch = 0; ch < 4; ch++)
#pragma unroll
            for (int q = 0; q < 4; q++) acc[ch][q] = 0ull;

#pragma unroll
        for (int dz = 0; dz < 3; dz++) {
#pragma unroll
            for (int dy = 0; dy < 3; dy++) {
                long rbase = ((long)zd[dz] * 48 + zh[dy]) * 48;
                float tv[4][3];
#pragma unroll
                for (int ch = 0; ch < 4; ch++) {
                    const float* xc = x + (long)(cq + 8 * ch) * VOX + rbase;
#pragma unroll
                    for (int dx = 0; dx < 3; dx++) tv[ch][dx] = xc[zw[dx]];
                }
#pragma unroll
                for (int dx = 0; dx < 3; dx++) {
                    int n = (dz * 3 + dy) * 3 + dx;
                    const ulonglong2* mp2 = (const ulonglong2*)(mB + n * 8);
                    ulonglong2 mLo = mp2[0];
                    ulonglong2 mHi = mp2[1];
#pragma unroll
                    for (int ch = 0; ch < 4; ch++) {
                        u64 T = dup2(tv[ch][dx]);
                        fma2(acc[ch][0], mLo.x, T);
                        fma2(acc[ch][1], mLo.y, T);
                        fma2(acc[ch][2], mHi.x, T);
                        fma2(acc[ch][3], mHi.y, T);
                    }
                }
            }
        }

#pragma unroll
        for (int ch = 0; ch < 4; ch++) {
            int c = cq + 8 * ch;
#pragma unroll
            for (int i = 0; i < 2; i++)
#pragma unroll
                for (int j = 0; j < 2; j++) {
                    int q = i * 2 + j;
                    long ob = (((long)c * 96 + 2 * d + i) * 96 + 2 * hB + j) * 96 + 2 * v;
                    *(float2*)&out[ob] = *(float2*)&acc[ch][q];
                }
        }
    }
}

// ---------------------------------------------------------------------------
extern "C" void kernel_launch(void* const* d_in, const int* in_sizes, int n_in,
                              void* d_out, int out_size)
{
    const float* x    = (const float*)d_in[0];
    const float* feat = (const float*)d_in[1];
    const float* w1   = (const float*)d_in[2];
    const float* b1   = (const float*)d_in[3];
    const float* w2   = (const float*)d_in[4];
    const float* b2   = (const float*)d_in[5];
    float* out = (float*)d_out;

    const int smemF = 111744;
    cudaFuncSetAttribute(k_fused, cudaFuncAttributeMaxDynamicSharedMemorySize, smemF);

    k_prep<<<271, 256>>>(w1, w2);
    k_fused<<<dim3(24, 48), 256, smemF>>>(feat, b1, x, b2, out);
}

// round 14
// speedup vs baseline: 4.5725x; 1.0334x over previous
#include <cuda_runtime.h>
#include <cuda_bf16.h>
#include <cstdint>

#define VOX (48*48*48)
typedef unsigned long long u64;
typedef unsigned int u32;

// Device globals
__device__ __nv_bfloat16 g_w1a[3 * 9 * 64 * 72];  // conv1 A: [dz][tap9][oc64][hi32|lo32|pad]
__device__ u32 g_w2frag[13824];                   // conv2 B frags (k-permuted)
__device__ char g_feats[48 * 48 * 50 * 144];      // pre-split features, sF row format (15.9 MB)

__device__ __forceinline__ void fma2(u64& acc, u64 a, u64 b) {
    asm("fma.rn.f32x2 %0, %1, %2, %0;" : "+l"(acc) : "l"(a), "l"(b));
}
__device__ __forceinline__ u64 dup2(float v) {
    u64 r; asm("mov.b64 %0, {%1, %1};" : "=l"(r) : "f"(v)); return r;
}
__device__ __forceinline__ u32 cvt2bf(float a, float b) {
    u32 r; asm("cvt.rn.bf16x2.f32 %0, %1, %2;" : "=r"(r) : "f"(b), "f"(a)); return r;
}
__device__ __forceinline__ void ldsm4(u32& r0, u32& r1, u32& r2, u32& r3, u32 a) {
    asm volatile("ldmatrix.sync.aligned.m8n8.x4.shared.b16 {%0,%1,%2,%3}, [%4];"
                 : "=r"(r0), "=r"(r1), "=r"(r2), "=r"(r3) : "r"(a));
}
__device__ __forceinline__ void mmabf(float* d, const u32* a, const u32* b) {
    asm volatile(
        "mma.sync.aligned.m16n8k16.row.col.f32.bf16.bf16.f32 "
        "{%0,%1,%2,%3}, {%4,%5,%6,%7}, {%8,%9}, {%0,%1,%2,%3};"
        : "+f"(d[0]), "+f"(d[1]), "+f"(d[2]), "+f"(d[3])
        : "r"(a[0]), "r"(a[1]), "r"(a[2]), "r"(a[3]), "r"(b[0]), "r"(b[1]));
}
__device__ __forceinline__ void cpasync16(u32 dst, const void* src) {
    asm volatile("cp.async.cg.shared.global [%0], [%1], 16;"
                 :: "r"(dst), "l"(src));
}

// ---------------------------------------------------------------------------
// Prep A: weights (unchanged from R13)
// ---------------------------------------------------------------------------
extern "C" __global__ void k_prep(const float* __restrict__ w1,
                                  const float* __restrict__ w2)
{
    int id = blockIdx.x * 256 + threadIdx.x;
    if (id < 13824) {
        int breg  = id & 1;
        int entry = id >> 1;
        int lane  = entry & 31;
        int q     = entry >> 5;
        int pass  = q & 1;
        int kt    = (q >> 1) & 3;
        int nt    = q >> 3;
        int tr = lane >> 2, tc = lane & 3;
        int mc = nt * 8 + tr;
        int k0 = kt * 16 + 2 * tc + breg * 8;
        int ocA = ((k0 >> 4) << 4) + ((k0 >> 1) & 7) + ((k0 & 1) << 3);
        int k1 = k0 + 1;
        int ocB = ((k1 >> 4) << 4) + ((k1 >> 1) & 7) + ((k1 & 1) << 3);
        float v0 = w2[mc * 64 + ocA];
        float v1 = w2[mc * 64 + ocB];
        __nv_bfloat16 h0 = __float2bfloat16(v0);
        __nv_bfloat16 h1 = __float2bfloat16(v1);
        u32 out;
        if (pass == 0) {
            out = ((u32)__bfloat16_as_ushort(h1) << 16) | (u32)__bfloat16_as_ushort(h0);
        } else {
            __nv_bfloat16 l0 = __float2bfloat16(v0 - __bfloat162float(h0));
            __nv_bfloat16 l1 = __float2bfloat16(v1 - __bfloat162float(h1));
            out = ((u32)__bfloat16_as_ushort(l1) << 16) | (u32)__bfloat16_as_ushort(l0);
        }
        g_w2frag[id] = out;
    } else if (id < 13824 + 55296) {
        int q = id - 13824;
        int ci = q & 31;
        int r  = q >> 5;
        int oc = r & 63;
        int r2 = r >> 6;
        int tap = r2 % 9, dz = r2 / 9;
        float v = w1[oc * 864 + ci * 27 + dz * 9 + tap];
        __nv_bfloat16 hi = __float2bfloat16(v);
        __nv_bfloat16 lo = __float2bfloat16(v - __bfloat162float(hi));
        int base = ((dz * 9 + tap) * 64 + oc) * 72;
        g_w1a[base + ci]      = hi;
        g_w1a[base + 32 + ci] = lo;
    }
}

// ---------------------------------------------------------------------------
// Prep B: features -> bf16 hi/lo, sF row format: row (z*48+y)*50+wp, 144 B.
// One thread per (row, ci2): 48*48*50*16 = 1,843,200 threads.
// ---------------------------------------------------------------------------
extern "C" __global__ void k_prep_feat(const float* __restrict__ feat)
{
    int id = blockIdx.x * 256 + threadIdx.x;
    if (id >= 48 * 48 * 50 * 16) return;
    int ci2 = id & 15;
    int q   = id >> 4;
    int wp  = q % 50;
    int row = q;                 // (z*48+y)*50 + wp
    int y   = (q / 50) % 48;
    int z   = q / (50 * 48);
    int w = min(max(wp - 1, 0), 47);
    long gi = (long)(2 * ci2) * VOX + (z * 48 + y) * 48 + w;
    float f0 = feat[gi];
    float f1 = feat[gi + VOX];
    u32 hp = cvt2bf(f0, f1);
    float r0 = f0 - __uint_as_float(hp << 16);
    float r1 = f1 - __uint_as_float(hp & 0xffff0000u);
    u32 lp = cvt2bf(r0, r1);
    char* dst = g_feats + (size_t)row * 144;
    *(u32*)(dst + ci2 * 4)      = hp;
    *(u32*)(dst + 64 + ci2 * 4) = lp;
}

// ---------------------------------------------------------------------------
// Fused kernel, 256 threads, 2 CTAs/SM, grid (24,48). Block = (d, 2 h-rows).
// Phase 1 = 9-stage (dz,dy) cp.async pipeline (double-buffered sF and sA).
// smem: sF 2x28800 [0,57600) ; sA 2x27648 [57600,112896)
//       phase2: sHu [0,26112) ; phase3: sMt [26112,110592)
// ---------------------------------------------------------------------------
extern "C" __global__ void __launch_bounds__(256, 2) k_fused(
    const float* __restrict__ b1, const float* __restrict__ x,
    const float* __restrict__ b2, float* __restrict__ out)
{
    extern __shared__ char sm[];
    const u32 sFb = (u32)__cvta_generic_to_shared(sm);
    const u32 sAb = sFb + 57600;

    const int tid  = threadIdx.x;
    const int lane = tid & 31;
    const int warp = tid >> 5;
    const int mw = warp & 1;
    const int nh = (warp >> 1) & 1;
    const int nw = warp >> 2;
    const int grp = lane >> 3, r8 = lane & 7;
    const int tr = lane >> 2, tc = lane & 3;
    const int h0 = blockIdx.x * 2;
    const int d  = blockIdx.y;

    // staging helpers (pure cp.async)
    auto issueA = [&](int s, int buf) {   // s = dz*3+dy ; slab = 3 taps
        const char* src = (const char*)g_w1a + (size_t)s * 27648;
        u32 dst = sAb + buf * 27648;
        for (int t = tid; t < 1728; t += 256)
            cpasync16(dst + t * 16, src + t * 16);
    };
    auto issueF = [&](int dz, int buf) {
        int z = min(max(d - 1 + dz, 0), 47);
        u32 dst = sFb + buf * 28800;
#pragma unroll
        for (int hh = 0; hh < 4; hh++) {
            int y = min(max(h0 - 1 + hh, 0), 47);
            const char* src = g_feats + (size_t)((z * 48 + y) * 50) * 144;
            for (int t = tid; t < 450; t += 256)
                cpasync16(dst + hh * 7200 + t * 16, src + t * 16);
        }
    };

    // ======================= Phase 1: conv1 (pipelined) =======================
    float D[2][3][4];
#pragma unroll
    for (int i = 0; i < 2; i++)
#pragma unroll
        for (int j = 0; j < 3; j++)
#pragma unroll
            for (int c = 0; c < 4; c++) D[i][j][c] = 0.0f;

    issueF(0, 0);
    issueA(0, 0);
    asm volatile("cp.async.commit_group;" ::: "memory");

#pragma unroll 1
    for (int s = 0; s < 9; s++) {
        const int dz = s / 3, dy = s % 3;
        const int abuf = s & 1;
        const int fbuf = dz & 1;

        __syncthreads();                       // all warps done with buffers being overwritten
        if (s < 8) {
            issueA(s + 1, abuf ^ 1);
            if (dy == 2) issueF(dz + 1, fbuf ^ 1);
            asm volatile("cp.async.commit_group;" ::: "memory");
            asm volatile("cp.async.wait_group 1;" ::: "memory");
        } else {
            asm volatile("cp.async.wait_group 0;" ::: "memory");
        }
        __syncthreads();                       // stage s data visible to all

        const u32 slabBase = sAb + abuf * 27648;
        const u32 fBase    = sFb + fbuf * 28800;
#pragma unroll 1
        for (int dx = 0; dx < 3; dx++) {
            const u32 tapBase = slabBase + dx * 64 * 144;
            const int rowBase = (nw + dy) * 50 + dx + nh * 24;
#pragma unroll
            for (int kc = 0; kc < 2; kc++) {
                u32 a_hi[2][4], a_lo[2][4];
#pragma unroll
                for (int i = 0; i < 2; i++) {
                    u32 ab = tapBase
                           + ((2 * mw + i) * 16 + (grp & 1) * 8 + r8) * 144
                           + (grp >> 1) * 16 + kc * 32;
                    ldsm4(a_hi[i][0], a_hi[i][1], a_hi[i][2], a_hi[i][3], ab);
                    ldsm4(a_lo[i][0], a_lo[i][1], a_lo[i][2], a_lo[i][3], ab + 64);
                }
                u32 bh[3][2], bl[3][2];
                {
                    u32 bb = fBase + (rowBase + (grp >> 1) * 8 + r8) * 144
                           + (grp & 1) * 16 + kc * 32;
                    ldsm4(bh[0][0], bh[0][1], bh[1][0], bh[1][1], bb);
                    ldsm4(bl[0][0], bl[0][1], bl[1][0], bl[1][1], bb + 64);
                    u32 b2a = fBase + (rowBase + 16 + r8) * 144
                            + (grp & 1) * 16 + (grp >> 1) * 64 + kc * 32;
                    ldsm4(bh[2][0], bh[2][1], bl[2][0], bl[2][1], b2a);
                }
#pragma unroll
                for (int i = 0; i < 2; i++)
#pragma unroll
                    for (int j = 0; j < 3; j++) {
                        mmabf(D[i][j], a_hi[i], bh[j]);
                        mmabf(D[i][j], a_lo[i], bh[j]);
                        mmabf(D[i][j], a_hi[i], bl[j]);
                    }
            }
        }
    }
    __syncthreads();   // phase1 buffers dead

    // ====== Phase 2: silu + direct bf16 hi/lo split into sHu (permuted k) ===
    u32* sHu = (u32*)sm;
    const u32 sHb = sFb;
    {
#pragma unroll
        for (int i = 0; i < 2; i++) {
            int oc0 = (2 * mw + i) * 16 + tr;
            int jcol = (2 * mw + i) * 8 + tr;
            float bias0 = b1[oc0], bias1 = b1[oc0 + 8];
#pragma unroll
            for (int j = 0; j < 3; j++) {
                int vl = nw * 48 + (3 * nh + j) * 8 + 2 * tc;
                float v0 = D[i][j][0] + bias0;
                float v1 = D[i][j][1] + bias0;
                float v2 = D[i][j][2] + bias1;
                float v3 = D[i][j][3] + bias1;
                v0 = v0 / (1.0f + __expf(-v0));
                v1 = v1 / (1.0f + __expf(-v1));
                v2 = v2 / (1.0f + __expf(-v2));
                v3 = v3 / (1.0f + __expf(-v3));
                u32 hp0 = cvt2bf(v0, v2);
                u32 hp1 = cvt2bf(v1, v3);
                u32 lp0 = cvt2bf(v0 - __uint_as_float(hp0 << 16),
                                 v2 - __uint_as_float(hp0 & 0xffff0000u));
                u32 lp1 = cvt2bf(v1 - __uint_as_float(hp1 << 16),
                                 v3 - __uint_as_float(hp1 & 0xffff0000u));
                sHu[vl * 68 + jcol]            = hp0;
                sHu[vl * 68 + 32 + jcol]       = lp0;
                sHu[(vl + 1) * 68 + jcol]      = hp1;
                sHu[(vl + 1) * 68 + 32 + jcol] = lp1;
            }
        }
    }
    __syncthreads();

    // ======================= Phase 3: conv2 GEMM -> softmax -> apply =======
    float* sMt = (float*)(sm + 26112);   // 96 x 220 fp32
    const uint2* w2f = (const uint2*)g_w2frag;

    {
        const int nnt = (warp < 3) ? 4 : 3;
#pragma unroll 1
        for (int mh = 0; mh < 2; mh++) {
            float Dv[4][3][4];
#pragma unroll
            for (int t = 0; t < 4; t++)
#pragma unroll
                for (int mi = 0; mi < 3; mi++)
#pragma unroll
                    for (int c = 0; c < 4; c++) Dv[t][mi][c] = 0.0f;

#pragma unroll
            for (int kt = 0; kt < 4; kt++) {
                u32 ah[3][4], al[3][4];
#pragma unroll
                for (int mi = 0; mi < 3; mi++) {
                    int mt = mh * 3 + mi;
                    u32 ab = sHb + (mt * 16 + (grp & 1) * 8 + r8) * 272
                           + (grp >> 1) * 16 + kt * 32;
                    ldsm4(ah[mi][0], ah[mi][1], ah[mi][2], ah[mi][3], ab);
                    ldsm4(al[mi][0], al[mi][1], al[mi][2], al[mi][3], ab + 128);
                }
#pragma unroll
                for (int t = 0; t < 4; t++) {
                    if (t >= nnt) break;
                    int nt = warp + 8 * t;
                    uint2 bhv = w2f[((nt * 4 + kt) * 2 + 0) * 32 + lane];
                    uint2 blv = w2f[((nt * 4 + kt) * 2 + 1) * 32 + lane];
                    u32 bh[2] = { bhv.x, bhv.y };
                    u32 bl[2] = { blv.x, blv.y };
#pragma unroll
                    for (int mi = 0; mi < 3; mi++) {
                        mmabf(Dv[t][mi], ah[mi], bh);
                        mmabf(Dv[t][mi], al[mi], bh);
                        mmabf(Dv[t][mi], ah[mi], bl);
                    }
                }
            }
#pragma unroll
            for (int t = 0; t < 4; t++) {
                if (t >= nnt) break;
                int nt = warp + 8 * t;
                int mcA = nt * 8 + 2 * tc;
                int mcB = mcA + 1;
                float bA = b2[mcA], bB = b2[mcB];
                int iA = (mcA % 27) * 8 + mcA / 27;
                int iB = (mcB % 27) * 8 + mcB / 27;
#pragma unroll
                for (int mi = 0; mi < 3; mi++) {
                    int v0 = (mh * 3 + mi) * 16 + tr;
                    sMt[v0 * 220 + iA]       = Dv[t][mi][0] + bA;
                    sMt[v0 * 220 + iB]       = Dv[t][mi][1] + bB;
                    sMt[(v0 + 8) * 220 + iA] = Dv[t][mi][2] + bA;
                    sMt[(v0 + 8) * 220 + iB] = Dv[t][mi][3] + bB;
                }
            }
        }
    }
    __syncthreads();

    // --- softmax over n per (vl, g-pair): 384 units, float2 vector ops ---
    for (int s = tid; s < 384; s += 256) {
        int vl = s >> 2, gp = s & 3;
        float* p = &sMt[vl * 220 + 2 * gp];
        float2 m0 = *(float2*)p;
        float mx0 = m0.x, mx1 = m0.y;
#pragma unroll
        for (int n = 1; n < 27; n++) {
            float2 mv = *(float2*)(p + n * 8);
            mx0 = fmaxf(mx0, mv.x);
            mx1 = fmaxf(mx1, mv.y);
        }
        float e0[27], e1[27];
        float s0 = 0.0f, s1 = 0.0f;
#pragma unroll
        for (int n = 0; n < 27; n++) {
            float2 mv = *(float2*)(p + n * 8);
            e0[n] = __expf(mv.x - mx0); s0 += e0[n];
            e1[n] = __expf(mv.y - mx1); s1 += e1[n];
        }
        float i0 = 1.0f / s0, i1 = 1.0f / s1;
#pragma unroll
        for (int n = 0; n < 27; n++)
            *(float2*)(p + n * 8) = make_float2(e0[n] * i0, e1[n] * i1);
    }
    __syncthreads();

    // --- apply ---
    int zd[3];
#pragma unroll
    for (int t = 0; t < 3; t++) zd[t] = min(max(d + t - 1, 0), 47);

#pragma unroll 1
    for (int p = tid; p < 768; p += 256) {
        int vl = p % 96, cq = p / 96;
        int hr = (vl >= 48);
        int v  = vl - (hr ? 48 : 0);
        int hB = h0 + hr;
        int zh[3], zw[3];
#pragma unroll
        for (int t = 0; t < 3; t++) zh[t] = min(max(hB + t - 1, 0), 47);
        zw[0] = max(v - 1, 0); zw[1] = v; zw[2] = min(v + 1, 47);
        const float* mB = &sMt[vl * 220];

        u64 acc[4][4];
#pragma unroll
        for (int ch = 0; ch < 4; ch++)
#pragma unroll
            for (int q = 0; q < 4; q++) acc[ch][q] = 0ull;

#pragma unroll
        for (int dz = 0; dz < 3; dz++) {
#pragma unroll
            for (int dy = 0; dy < 3; dy++) {
                long rbase = ((long)zd[dz] * 48 + zh[dy]) * 48;
                float tv[4][3];
#pragma unroll
                for (int ch = 0; ch < 4; ch++) {
                    const float* xc = x + (long)(cq + 8 * ch) * VOX + rbase;
#pragma unroll
                    for (int dx = 0; dx < 3; dx++) tv[ch][dx] = xc[zw[dx]];
                }
#pragma unroll
                for (int dx = 0; dx < 3; dx++) {
                    int n = (dz * 3 + dy) * 3 + dx;
                    const ulonglong2* mp2 = (const ulonglong2*)(mB + n * 8);
                    ulonglong2 mLo = mp2[0];
                    ulonglong2 mHi = mp2[1];
#pragma unroll
                    for (int ch = 0; ch < 4; ch++) {
                        u64 T = dup2(tv[ch][dx]);
                        fma2(acc[ch][0], mLo.x, T);
                        fma2(acc[ch][1], mLo.y, T);
                        fma2(acc[ch][2], mHi.x, T);
                        fma2(acc[ch][3], mHi.y, T);
                    }
                }
            }
        }

#pragma unroll
        for (int ch = 0; ch < 4; ch++) {
            int c = cq + 8 * ch;
#pragma unroll
            for (int i = 0; i < 2; i++)
#pragma unroll
                for (int j = 0; j < 2; j++) {
                    int q = i * 2 + j;
                    long ob = (((long)c * 96 + 2 * d + i) * 96 + 2 * hB + j) * 96 + 2 * v;
                    *(float2*)&out[ob] = *(float2*)&acc[ch][q];
                }
        }
    }
}

// ---------------------------------------------------------------------------
extern "C" void kernel_launch(void* const* d_in, const int* in_sizes, int n_in,
                              void* d_out, int out_size)
{
    const float* x    = (const float*)d_in[0];
    const float* feat = (const float*)d_in[1];
    const float* w1   = (const float*)d_in[2];
    const float* b1   = (const float*)d_in[3];
    const float* w2   = (const float*)d_in[4];
    const float* b2   = (const float*)d_in[5];
    float* out = (float*)d_out;

    const int smemF = 112896;
    cudaFuncSetAttribute(k_fused, cudaFuncAttributeMaxDynamicSharedMemorySize, smemF);

    k_prep<<<271, 256>>>(w1, w2);
    k_prep_feat<<<7200, 256>>>(feat);
    k_fused<<<dim3(24, 48), 256, smemF>>>(b1, x, b2, out);
}